// round 1
// baseline (speedup 1.0000x reference)
#include <cuda_runtime.h>

#define N_VOX 131072        // 2^17 active voxels
#define CCH 128             // channels
#define NK 27               // stencil taps
#define TM 64               // GEMM tile rows
#define TPK (N_VOX / TM)    // 2048 tiles per offset
#define STAGE_ROWS (8 * N_VOX)   // worst-case compacted pair rows (actual ~505k)
#define EPSF 1e-4f
#define SLOPE_IN 0.05f
#define SLOPE_OUT (1.0f / 3.0f)

// ---------------- scratch (device globals; no runtime allocation) ----------
__device__ float g_y[(size_t)N_VOX * CCH];        // conv output accumulator
__device__ float g_a[(size_t)N_VOX * CCH];        // activated features (layer input)
__device__ float g_res[(size_t)N_VOX * CCH];      // residual
__device__ float g_stage[(size_t)STAGE_ROWS * CCH]; // per-pair GEMM results
__device__ int   g_pairs_j[STAGE_ROWS];           // source row per staged slot
__device__ int   g_pos[N_VOX * NK];               // (i,k) -> staged slot, -1 invalid
__device__ int   g_cnt[NK];
__device__ int   g_off[NK];
__device__ int   g_cursor[NK];
__device__ float g_sum[CCH], g_sumsq[CCH];
__device__ float g_scale[CCH], g_shift[CCH];

// ---------------- rulebook construction ------------------------------------
__global__ void k_zero_cnt() {
    if (threadIdx.x < NK) g_cnt[threadIdx.x] = 0;
}

// idx = k * N + i  (k warp-uniform since N is a power of two >= 32)
__global__ void k_count(const int* __restrict__ nbr) {
    int idx = blockIdx.x * blockDim.x + threadIdx.x;
    int k = idx >> 17;
    int i = idx & (N_VOX - 1);
    if (k == 13) return;  // identity tap handled densely
    int j = nbr[i * NK + k];
    unsigned m = __ballot_sync(0xffffffffu, j >= 0);
    if ((threadIdx.x & 31) == 0 && m)
        atomicAdd(&g_cnt[k], __popc(m));
}

__global__ void k_scan() {
    if (threadIdx.x == 0) {
        int o = 0;
        for (int k = 0; k < NK; ++k) {
            g_off[k] = o;
            o += g_cnt[k];
            g_cursor[k] = 0;
        }
    }
}

__global__ void k_fill(const int* __restrict__ nbr) {
    int idx = blockIdx.x * blockDim.x + threadIdx.x;
    int k = idx >> 17;
    int i = idx & (N_VOX - 1);
    if (k == 13) {                 // warp-uniform branch
        g_pos[i * NK + 13] = -1;
        return;
    }
    int j = nbr[i * NK + k];
    bool valid = (j >= 0);
    unsigned m = __ballot_sync(0xffffffffu, valid);
    int base = 0;
    if ((threadIdx.x & 31) == 0 && m)
        base = atomicAdd(&g_cursor[k], __popc(m));
    base = __shfl_sync(0xffffffffu, base, 0);
    int pos = -1;
    if (valid) {
        pos = g_off[k] + base + __popc(m & ((1u << (threadIdx.x & 31)) - 1u));
        g_pairs_j[pos] = j;
    }
    g_pos[i * NK + k] = pos;
}

// ---------------- gather-GEMM  (fp32 FFMA, 64x128x128 per block) -----------
// self_mode=1: k=13 identity tap, dense, plain store to OUT=g_y (rows = voxel id)
// self_mode=0: compacted pairs for k!=13, store to OUT=g_stage (rows = slot)
__global__ void __launch_bounds__(256) conv_gemm(
    const float* __restrict__ X, const float* __restrict__ W27,
    float* __restrict__ OUT, int self_mode)
{
    __shared__ float As[TM * 132];   // gathered rows, pad 4 to kill LDS conflicts
    __shared__ float Bs[16 * CCH];   // W chunk
    __shared__ int   sj[TM];

    int tid = threadIdx.x;
    int m0, cnt, obase;
    const float* Wk;
    if (self_mode) {
        m0 = blockIdx.x * TM;
        cnt = N_VOX;
        obase = m0;
        Wk = W27 + 13 * CCH * CCH;
    } else {
        int kp = blockIdx.x / TPK;
        int k = kp + (kp >= 13 ? 1 : 0);
        int t = blockIdx.x % TPK;
        cnt = g_cnt[k];
        m0 = t * TM;
        if (m0 >= cnt) return;
        obase = g_off[k] + m0;
        Wk = W27 + k * CCH * CCH;
    }
    int rows = min(TM, cnt - m0);

    if (tid < TM) {
        int j = -1;
        if (tid < rows)
            j = self_mode ? (m0 + tid) : g_pairs_j[obase + tid];
        sj[tid] = j;
    }
    __syncthreads();

    // gather A: 64 rows x 128 cols
#pragma unroll
    for (int it = 0; it < 8; ++it) {
        int f = tid + it * 256;
        int row = f >> 5;
        int c4 = f & 31;
        int j = sj[row];
        float4 v = make_float4(0.f, 0.f, 0.f, 0.f);
        if (j >= 0)
            v = *(const float4*)(X + (size_t)j * CCH + c4 * 4);
        *(float4*)(As + row * 132 + c4 * 4) = v;
    }

    float acc[4][8];
#pragma unroll
    for (int r = 0; r < 4; ++r)
#pragma unroll
        for (int c = 0; c < 8; ++c) acc[r][c] = 0.f;

    int rg = tid >> 4;   // 0..15 -> rows rg*4..rg*4+3
    int cg = tid & 15;   // 0..15 -> cols cg*8..cg*8+7

    for (int kc = 0; kc < 8; ++kc) {
        __syncthreads();
#pragma unroll
        for (int it = 0; it < 2; ++it) {
            int f = tid + it * 256;
            int br = f >> 5;
            int bc4 = f & 31;
            *(float4*)(Bs + br * CCH + bc4 * 4) =
                *(const float4*)(Wk + (kc * 16 + br) * CCH + bc4 * 4);
        }
        __syncthreads();
#pragma unroll
        for (int kk = 0; kk < 16; ++kk) {
            const float* ap = As + (rg * 4) * 132 + kc * 16 + kk;
            float a0 = ap[0];
            float a1 = ap[132];
            float a2 = ap[264];
            float a3 = ap[396];
            float4 b0 = *(const float4*)(Bs + kk * CCH + cg * 8);
            float4 b1 = *(const float4*)(Bs + kk * CCH + cg * 8 + 4);
            float bb[8] = {b0.x, b0.y, b0.z, b0.w, b1.x, b1.y, b1.z, b1.w};
#pragma unroll
            for (int c = 0; c < 8; ++c) {
                acc[0][c] = fmaf(a0, bb[c], acc[0][c]);
                acc[1][c] = fmaf(a1, bb[c], acc[1][c]);
                acc[2][c] = fmaf(a2, bb[c], acc[2][c]);
                acc[3][c] = fmaf(a3, bb[c], acc[3][c]);
            }
        }
    }

#pragma unroll
    for (int rr = 0; rr < 4; ++rr) {
        int r = rg * 4 + rr;
        if (r < rows) {
            size_t orow = (size_t)(obase + r);
            float4 o0 = make_float4(acc[rr][0], acc[rr][1], acc[rr][2], acc[rr][3]);
            float4 o1 = make_float4(acc[rr][4], acc[rr][5], acc[rr][6], acc[rr][7]);
            *(float4*)(OUT + orow * CCH + cg * 8) = o0;
            *(float4*)(OUT + orow * CCH + cg * 8 + 4) = o1;
        }
    }
}

// ---------------- combine staged rows into g_y ------------------------------
__global__ void k_combine(float* __restrict__ Y) {
    int gt = blockIdx.x * blockDim.x + threadIdx.x;
    int w = gt >> 5;
    int lane = gt & 31;
    if (w >= N_VOX) return;
    int myp = -1;
    if (lane < NK) myp = g_pos[w * NK + lane];
    float4 acc = *(const float4*)(Y + (size_t)w * CCH + lane * 4);
#pragma unroll
    for (int k = 0; k < NK; ++k) {
        int s = __shfl_sync(0xffffffffu, myp, k);
        if (s >= 0) {
            float4 v = *(const float4*)(g_stage + (size_t)s * CCH + lane * 4);
            acc.x += v.x; acc.y += v.y; acc.z += v.z; acc.w += v.w;
        }
    }
    *(float4*)(Y + (size_t)w * CCH + lane * 4) = acc;
}

// ---------------- batchnorm (batch stats) -----------------------------------
__global__ void k_zero_stats() {
    g_sum[threadIdx.x] = 0.f;
    g_sumsq[threadIdx.x] = 0.f;
}

__global__ void k_stats(const float* __restrict__ Y) {
    int c = threadIdx.x;
    float s = 0.f, s2 = 0.f;
    for (int i = blockIdx.x; i < N_VOX; i += gridDim.x) {
        float v = Y[(size_t)i * CCH + c];
        s += v;
        s2 += v * v;
    }
    atomicAdd(&g_sum[c], s);
    atomicAdd(&g_sumsq[c], s2);
}

__global__ void k_finalize(const float* __restrict__ gma, const float* __restrict__ bta) {
    int c = threadIdx.x;
    float mu = g_sum[c] * (1.0f / N_VOX);
    float var = g_sumsq[c] * (1.0f / N_VOX) - mu * mu;
    float rs = rsqrtf(var + EPSF);
    float sc = gma[c] * rs;
    g_scale[c] = sc;
    g_shift[c] = bta[c] - mu * sc;
}

// ---------------- activations ------------------------------------------------
__global__ void k_act_inner(const float* __restrict__ Y, float* __restrict__ A,
                            float* __restrict__ R, int write_res) {
    int idx = blockIdx.x * blockDim.x + threadIdx.x;  // float4 index
    int c4 = (idx & 31) << 2;
    float4 y = *(const float4*)(Y + (size_t)idx * 4);
    float4 sc = *(const float4*)(g_scale + c4);
    float4 sh = *(const float4*)(g_shift + c4);
    float4 v;
    v.x = fmaf(y.x, sc.x, sh.x);
    v.y = fmaf(y.y, sc.y, sh.y);
    v.z = fmaf(y.z, sc.z, sh.z);
    v.w = fmaf(y.w, sc.w, sh.w);
    v.x = v.x >= 0.f ? v.x : SLOPE_IN * v.x;
    v.y = v.y >= 0.f ? v.y : SLOPE_IN * v.y;
    v.z = v.z >= 0.f ? v.z : SLOPE_IN * v.z;
    v.w = v.w >= 0.f ? v.w : SLOPE_IN * v.w;
    *(float4*)(A + (size_t)idx * 4) = v;
    if (write_res) *(float4*)(R + (size_t)idx * 4) = v;
}

__global__ void k_act_out(const float* __restrict__ Y, const float* __restrict__ R,
                          float* __restrict__ O) {
    int idx = blockIdx.x * blockDim.x + threadIdx.x;
    int c4 = (idx & 31) << 2;
    float4 y = *(const float4*)(Y + (size_t)idx * 4);
    float4 r = *(const float4*)(R + (size_t)idx * 4);
    float4 sc = *(const float4*)(g_scale + c4);
    float4 sh = *(const float4*)(g_shift + c4);
    float4 v;
    v.x = fmaf(y.x, sc.x, sh.x) + r.x;
    v.y = fmaf(y.y, sc.y, sh.y) + r.y;
    v.z = fmaf(y.z, sc.z, sh.z) + r.z;
    v.w = fmaf(y.w, sc.w, sh.w) + r.w;
    v.x = v.x >= 0.f ? v.x : SLOPE_OUT * v.x;
    v.y = v.y >= 0.f ? v.y : SLOPE_OUT * v.y;
    v.z = v.z >= 0.f ? v.z : SLOPE_OUT * v.z;
    v.w = v.w >= 0.f ? v.w : SLOPE_OUT * v.w;
    *(float4*)(O + (size_t)idx * 4) = v;
}

// ---------------- launch -------------------------------------------------------
extern "C" void kernel_launch(void* const* d_in, const int* in_sizes, int n_in,
                              void* d_out, int out_size) {
    const float* feat = (const float*)d_in[0];
    const int*   nbr  = (const int*)d_in[1];
    const float* w1   = (const float*)d_in[2];
    const float* w2   = (const float*)d_in[3];
    const float* w3   = (const float*)d_in[4];
    const float* g1   = (const float*)d_in[5];
    const float* b1   = (const float*)d_in[6];
    const float* g2   = (const float*)d_in[7];
    const float* b2   = (const float*)d_in[8];
    const float* g3   = (const float*)d_in[9];
    const float* b3   = (const float*)d_in[10];
    float* out = (float*)d_out;

    float *p_y, *p_a, *p_res, *p_stage;
    cudaGetSymbolAddress((void**)&p_y, g_y);
    cudaGetSymbolAddress((void**)&p_a, g_a);
    cudaGetSymbolAddress((void**)&p_res, g_res);
    cudaGetSymbolAddress((void**)&p_stage, g_stage);

    const int nelem4 = (N_VOX * CCH) / 4;      // 4.19M float4
    const int act_grid = nelem4 / 256;         // 16384
    const int comb_grid = (N_VOX * 32) / 256;  // 16384

    // rulebook (same for all three convs)
    k_zero_cnt<<<1, 32>>>();
    k_count<<<(NK * N_VOX) / 256, 256>>>(nbr);
    k_scan<<<1, 32>>>();
    k_fill<<<(NK * N_VOX) / 256, 256>>>(nbr);

    // ---- layer 1 ----
    conv_gemm<<<TPK, 256>>>(feat, w1, p_y, 1);
    conv_gemm<<<26 * TPK, 256>>>(feat, w1, p_stage, 0);
    k_combine<<<comb_grid, 256>>>(p_y);
    k_zero_stats<<<1, 128>>>();
    k_stats<<<1024, 128>>>(p_y);
    k_finalize<<<1, 128>>>(g1, b1);
    k_act_inner<<<act_grid, 256>>>(p_y, p_a, p_res, 1);

    // ---- layer 2 ----
    conv_gemm<<<TPK, 256>>>(p_a, w2, p_y, 1);
    conv_gemm<<<26 * TPK, 256>>>(p_a, w2, p_stage, 0);
    k_combine<<<comb_grid, 256>>>(p_y);
    k_zero_stats<<<1, 128>>>();
    k_stats<<<1024, 128>>>(p_y);
    k_finalize<<<1, 128>>>(g2, b2);
    k_act_inner<<<act_grid, 256>>>(p_y, p_a, p_a, 0);

    // ---- layer 3 ----
    conv_gemm<<<TPK, 256>>>(p_a, w3, p_y, 1);
    conv_gemm<<<26 * TPK, 256>>>(p_a, w3, p_stage, 0);
    k_combine<<<comb_grid, 256>>>(p_y);
    k_zero_stats<<<1, 128>>>();
    k_stats<<<1024, 128>>>(p_y);
    k_finalize<<<1, 128>>>(g3, b3);
    k_act_out<<<act_grid, 256>>>(p_y, p_res, out);
}

// round 2
// speedup vs baseline: 2.0666x; 2.0666x over previous
#include <cuda_runtime.h>
#include <cuda_fp16.h>

#define N_VOX 131072
#define CCH 128
#define NK 27
#define TMM 128                    // GEMM tile rows
#define TPK (N_VOX / TMM)          // 1024 tiles per offset
#define STAGE_ROWS (8 * N_VOX)
#define WSZ (NK * CCH * CCH)       // 442368
#define EPSF 1e-4f
#define SLOPE_IN 0.05f
#define SLOPE_OUT (1.0f / 3.0f)

// ---------------- scratch (device globals) ----------------------------------
__device__ float g_y[(size_t)N_VOX * CCH];
__device__ float g_res[(size_t)N_VOX * CCH];
__device__ float g_stage[(size_t)STAGE_ROWS * CCH];
__device__ __half g_xh[(size_t)N_VOX * CCH];
__device__ __half g_xl[(size_t)N_VOX * CCH];
__device__ __half g_wh[3 * WSZ];
__device__ __half g_wl[3 * WSZ];
__device__ int   g_pairs_j[STAGE_ROWS];
__device__ int   g_pos[N_VOX * NK];
__device__ int   g_cnt[NK];
__device__ int   g_off[NK];
__device__ int   g_cursor[NK];
__device__ float g_sum[CCH], g_sumsq[CCH];
__device__ float g_scale[CCH], g_shift[CCH];

// ---------------- rulebook ----------------------------------------------------
__global__ void k_zero_cnt() {
    if (threadIdx.x < NK) { g_cnt[threadIdx.x] = 0; g_cursor[threadIdx.x] = 0; }
}

// idx = k * N + i ; 256-thread blocks => k uniform per block (N/256 = 512)
__global__ void k_count(const int* __restrict__ nbr) {
    __shared__ int scnt;
    if (threadIdx.x == 0) scnt = 0;
    __syncthreads();
    int idx = blockIdx.x * 256 + threadIdx.x;
    int k = idx >> 17;
    int i = idx & (N_VOX - 1);
    int j = (k == 13) ? -1 : nbr[i * NK + k];
    unsigned m = __ballot_sync(0xffffffffu, j >= 0);
    if ((threadIdx.x & 31) == 0 && m) atomicAdd(&scnt, __popc(m));
    __syncthreads();
    if (threadIdx.x == 0 && scnt) atomicAdd(&g_cnt[k], scnt);
}

__global__ void k_scan() {
    int o = 0;
    for (int k = 0; k < NK; ++k) { g_off[k] = o; o += g_cnt[k]; }
}

__global__ void k_fill(const int* __restrict__ nbr) {
    __shared__ int woff[8];
    __shared__ int sbase;
    int idx = blockIdx.x * 256 + threadIdx.x;
    int k = idx >> 17;
    int i = idx & (N_VOX - 1);
    if (k == 13) {                    // uniform per block
        g_pos[i * NK + 13] = -1;
        return;
    }
    int j = nbr[i * NK + k];
    bool valid = (j >= 0);
    unsigned m = __ballot_sync(0xffffffffu, valid);
    int w = threadIdx.x >> 5, lane = threadIdx.x & 31;
    if (lane == 0) woff[w] = __popc(m);
    __syncthreads();
    if (threadIdx.x == 0) {
        int o = 0;
        for (int q = 0; q < 8; ++q) { int c = woff[q]; woff[q] = o; o += c; }
        sbase = o ? atomicAdd(&g_cursor[k], o) : 0;
    }
    __syncthreads();
    int pos = -1;
    if (valid) {
        pos = g_off[k] + sbase + woff[w] + __popc(m & ((1u << lane) - 1u));
        g_pairs_j[pos] = j;
    }
    g_pos[i * NK + k] = pos;
}

// ---------------- fp16 hi/lo splits --------------------------------------------
__global__ void k_wsplit(const float* __restrict__ w1, const float* __restrict__ w2,
                         const float* __restrict__ w3) {
    int i = blockIdx.x * blockDim.x + threadIdx.x;   // 0..WSZ-1 (exact grid)
    const float* src = (blockIdx.y == 0) ? w1 : (blockIdx.y == 1 ? w2 : w3);
    float v = src[i];
    __half h = __float2half(v);
    g_wh[blockIdx.y * WSZ + i] = h;
    g_wl[blockIdx.y * WSZ + i] = __float2half(v - __half2float(h));
}

__device__ __forceinline__ void split_store4(int idx, float4 v) {
    __half h0 = __float2half(v.x), h1 = __float2half(v.y);
    __half h2 = __float2half(v.z), h3 = __float2half(v.w);
    __half l0 = __float2half(v.x - __half2float(h0));
    __half l1 = __float2half(v.y - __half2float(h1));
    __half l2 = __float2half(v.z - __half2float(h2));
    __half l3 = __float2half(v.w - __half2float(h3));
    __half2* xh = (__half2*)g_xh;
    __half2* xl = (__half2*)g_xl;
    xh[idx * 2]     = __halves2half2(h0, h1);
    xh[idx * 2 + 1] = __halves2half2(h2, h3);
    xl[idx * 2]     = __halves2half2(l0, l1);
    xl[idx * 2 + 1] = __halves2half2(l2, l3);
}

__global__ void k_xsplit(const float* __restrict__ F) {
    int idx = blockIdx.x * blockDim.x + threadIdx.x;   // float4 index
    float4 v = *(const float4*)(F + (size_t)idx * 4);
    split_store4(idx, v);
}

// ---------------- mma.sync GEMM (fp16 3-term split, fp32 acc) -------------------
__device__ __forceinline__ void mma16816(float* d, const unsigned* a, const unsigned* b) {
    asm volatile(
        "mma.sync.aligned.m16n8k16.row.col.f32.f16.f16.f32 "
        "{%0,%1,%2,%3}, {%4,%5,%6,%7}, {%8,%9}, {%0,%1,%2,%3};"
        : "+f"(d[0]), "+f"(d[1]), "+f"(d[2]), "+f"(d[3])
        : "r"(a[0]), "r"(a[1]), "r"(a[2]), "r"(a[3]), "r"(b[0]), "r"(b[1]));
}

#define LDSM_X4(R, addr) asm volatile( \
    "ldmatrix.sync.aligned.m8n8.x4.shared.b16 {%0,%1,%2,%3}, [%4];" \
    : "=r"((R)[0]), "=r"((R)[1]), "=r"((R)[2]), "=r"((R)[3]) : "r"(addr))
#define LDSM_X4T(R, addr) asm volatile( \
    "ldmatrix.sync.aligned.m8n8.x4.trans.shared.b16 {%0,%1,%2,%3}, [%4];" \
    : "=r"((R)[0]), "=r"((R)[1]), "=r"((R)[2]), "=r"((R)[3]) : "r"(addr))

// Block tile 128(M) x 128(N), K=128 in 4 chunks of 32.
// 8 warps: wm = warp&3 (32 rows each), wn = warp>>2 (64 cols each).
__global__ void __launch_bounds__(256, 2) conv_mma(
    const __half* __restrict__ Xh, const __half* __restrict__ Xl,
    const __half* __restrict__ Wh, const __half* __restrict__ Wl,
    float* __restrict__ OUT, int self_mode)
{
    __shared__ __half Ah[128 * 40];
    __shared__ __half Al[128 * 40];
    __shared__ __half Bh[32 * 136];
    __shared__ __half Bl[32 * 136];
    __shared__ int sj[TMM];

    int tid = threadIdx.x;
    int m0, cnt, obase;
    const __half *Whk, *Wlk;
    if (self_mode) {
        m0 = blockIdx.x * TMM; cnt = N_VOX; obase = m0;
        Whk = Wh + 13 * CCH * CCH; Wlk = Wl + 13 * CCH * CCH;
    } else {
        int kp = blockIdx.x >> 10;
        int k = kp + (kp >= 13 ? 1 : 0);
        int t = blockIdx.x & (TPK - 1);
        cnt = g_cnt[k];
        m0 = t * TMM;
        if (m0 >= cnt) return;
        obase = g_off[k] + m0;
        Whk = Wh + k * CCH * CCH; Wlk = Wl + k * CCH * CCH;
    }
    int rows = min(TMM, cnt - m0);

    if (tid < TMM) {
        int j = -1;
        if (tid < rows) j = self_mode ? (m0 + tid) : g_pairs_j[obase + tid];
        sj[tid] = j;
    }

    int lane = tid & 31, warp = tid >> 5;
    int wm = warp & 3, wn = warp >> 2;

    unsigned ah_b = (unsigned)__cvta_generic_to_shared(Ah);
    unsigned al_b = (unsigned)__cvta_generic_to_shared(Al);
    unsigned bh_b = (unsigned)__cvta_generic_to_shared(Bh);
    unsigned bl_b = (unsigned)__cvta_generic_to_shared(Bl);

    int arow = wm * 32 + (lane & 15);
    int acol = (lane >> 4) * 8;
    int brow = lane & 15;
    int bcol = wn * 64 + (lane >> 4) * 8;

    float acc[2][8][4];
#pragma unroll
    for (int mi = 0; mi < 2; ++mi)
#pragma unroll
        for (int ni = 0; ni < 8; ++ni)
#pragma unroll
            for (int q = 0; q < 4; ++q) acc[mi][ni][q] = 0.f;

    __syncthreads();   // sj visible

    for (int kc = 0; kc < 4; ++kc) {
        // ---- load A chunk (gathered rows, zero-fill invalid) ----
#pragma unroll
        for (int it = 0; it < 4; ++it) {
            int u = tid + it * 256;
            int row = (u >> 2) & 127;
            int seg = u & 3;
            int j = sj[row];
            const __half* src = (u < 512) ? Xh : Xl;
            __half* dst = ((u < 512) ? Ah : Al) + row * 40 + seg * 8;
            uint4 v = make_uint4(0u, 0u, 0u, 0u);
            if (j >= 0) v = *(const uint4*)(src + (size_t)j * CCH + kc * 32 + seg * 8);
            *(uint4*)dst = v;
        }
        // ---- load B chunk (weights) ----
#pragma unroll
        for (int it = 0; it < 4; ++it) {
            int u = tid + it * 256;
            int row = (u >> 4) & 31;
            int seg = u & 15;
            const __half* src = ((u < 512) ? Whk : Wlk) + (size_t)(kc * 32 + row) * CCH + seg * 8;
            __half* dst = ((u < 512) ? Bh : Bl) + row * 136 + seg * 8;
            *(uint4*)dst = *(const uint4*)src;
        }
        __syncthreads();

#pragma unroll
        for (int kk = 0; kk < 2; ++kk) {
            unsigned ahf[2][4], alf[2][4];
#pragma unroll
            for (int mi = 0; mi < 2; ++mi) {
                unsigned off = (unsigned)(((arow + mi * 16) * 40 + kk * 16 + acol) * 2);
                LDSM_X4(ahf[mi], ah_b + off);
                LDSM_X4(alf[mi], al_b + off);
            }
#pragma unroll
            for (int n2 = 0; n2 < 4; ++n2) {
                unsigned off = (unsigned)(((kk * 16 + brow) * 136 + bcol + n2 * 16) * 2);
                unsigned bhf[4], blf[4];
                LDSM_X4T(bhf, bh_b + off);
                LDSM_X4T(blf, bl_b + off);
#pragma unroll
                for (int mi = 0; mi < 2; ++mi) {
                    mma16816(acc[mi][n2 * 2],     ahf[mi], bhf);
                    mma16816(acc[mi][n2 * 2],     ahf[mi], blf);
                    mma16816(acc[mi][n2 * 2],     alf[mi], bhf);
                    mma16816(acc[mi][n2 * 2 + 1], ahf[mi], bhf + 2);
                    mma16816(acc[mi][n2 * 2 + 1], ahf[mi], blf + 2);
                    mma16816(acc[mi][n2 * 2 + 1], alf[mi], bhf + 2);
                }
            }
        }
        __syncthreads();
    }

    // ---- epilogue ----
    int gr = lane >> 2, gc = (lane & 3) * 2;
#pragma unroll
    for (int mi = 0; mi < 2; ++mi)
#pragma unroll
        for (int ni = 0; ni < 8; ++ni) {
            int c = wn * 64 + ni * 8 + gc;
            int r0 = wm * 32 + mi * 16 + gr;
            if (r0 < rows)
                *(float2*)(OUT + (size_t)(obase + r0) * CCH + c) =
                    make_float2(acc[mi][ni][0], acc[mi][ni][1]);
            int r1 = r0 + 8;
            if (r1 < rows)
                *(float2*)(OUT + (size_t)(obase + r1) * CCH + c) =
                    make_float2(acc[mi][ni][2], acc[mi][ni][3]);
        }
}

// ---------------- combine staged rows into g_y ----------------------------------
__global__ void k_combine(float* __restrict__ Y) {
    int gt = blockIdx.x * blockDim.x + threadIdx.x;
    int w = gt >> 5;
    int lane = gt & 31;
    if (w >= N_VOX) return;
    int myp = -1;
    if (lane < NK) myp = g_pos[w * NK + lane];
    float4 acc = *(const float4*)(Y + (size_t)w * CCH + lane * 4);
#pragma unroll
    for (int k = 0; k < NK; ++k) {
        int s = __shfl_sync(0xffffffffu, myp, k);
        if (s >= 0) {
            float4 v = *(const float4*)(g_stage + (size_t)s * CCH + lane * 4);
            acc.x += v.x; acc.y += v.y; acc.z += v.z; acc.w += v.w;
        }
    }
    *(float4*)(Y + (size_t)w * CCH + lane * 4) = acc;
}

// ---------------- batchnorm -------------------------------------------------------
__global__ void k_zero_stats() {
    g_sum[threadIdx.x] = 0.f;
    g_sumsq[threadIdx.x] = 0.f;
}

__global__ void k_stats(const float* __restrict__ Y) {
    int c = threadIdx.x;
    float s = 0.f, s2 = 0.f;
    for (int i = blockIdx.x; i < N_VOX; i += gridDim.x) {
        float v = Y[(size_t)i * CCH + c];
        s += v; s2 += v * v;
    }
    atomicAdd(&g_sum[c], s);
    atomicAdd(&g_sumsq[c], s2);
}

__global__ void k_finalize(const float* __restrict__ gma, const float* __restrict__ bta) {
    int c = threadIdx.x;
    float mu = g_sum[c] * (1.0f / N_VOX);
    float var = g_sumsq[c] * (1.0f / N_VOX) - mu * mu;
    float rs = rsqrtf(var + EPSF);
    float sc = gma[c] * rs;
    g_scale[c] = sc;
    g_shift[c] = bta[c] - mu * sc;
}

// ---------------- activations ------------------------------------------------------
__global__ void k_act_inner(const float* __restrict__ Y, float* __restrict__ R, int write_res) {
    int idx = blockIdx.x * blockDim.x + threadIdx.x;  // float4 index
    int c4 = (idx & 31) << 2;
    float4 y = *(const float4*)(Y + (size_t)idx * 4);
    float4 sc = *(const float4*)(g_scale + c4);
    float4 sh = *(const float4*)(g_shift + c4);
    float4 v;
    v.x = fmaf(y.x, sc.x, sh.x);
    v.y = fmaf(y.y, sc.y, sh.y);
    v.z = fmaf(y.z, sc.z, sh.z);
    v.w = fmaf(y.w, sc.w, sh.w);
    v.x = v.x >= 0.f ? v.x : SLOPE_IN * v.x;
    v.y = v.y >= 0.f ? v.y : SLOPE_IN * v.y;
    v.z = v.z >= 0.f ? v.z : SLOPE_IN * v.z;
    v.w = v.w >= 0.f ? v.w : SLOPE_IN * v.w;
    split_store4(idx, v);
    if (write_res) *(float4*)(R + (size_t)idx * 4) = v;
}

__global__ void k_act_out(const float* __restrict__ Y, const float* __restrict__ R,
                          float* __restrict__ O) {
    int idx = blockIdx.x * blockDim.x + threadIdx.x;
    int c4 = (idx & 31) << 2;
    float4 y = *(const float4*)(Y + (size_t)idx * 4);
    float4 r = *(const float4*)(R + (size_t)idx * 4);
    float4 sc = *(const float4*)(g_scale + c4);
    float4 sh = *(const float4*)(g_shift + c4);
    float4 v;
    v.x = fmaf(y.x, sc.x, sh.x) + r.x;
    v.y = fmaf(y.y, sc.y, sh.y) + r.y;
    v.z = fmaf(y.z, sc.z, sh.z) + r.z;
    v.w = fmaf(y.w, sc.w, sh.w) + r.w;
    v.x = v.x >= 0.f ? v.x : SLOPE_OUT * v.x;
    v.y = v.y >= 0.f ? v.y : SLOPE_OUT * v.y;
    v.z = v.z >= 0.f ? v.z : SLOPE_OUT * v.z;
    v.w = v.w >= 0.f ? v.w : SLOPE_OUT * v.w;
    *(float4*)(O + (size_t)idx * 4) = v;
}

// ---------------- launch --------------------------------------------------------------
extern "C" void kernel_launch(void* const* d_in, const int* in_sizes, int n_in,
                              void* d_out, int out_size) {
    const float* feat = (const float*)d_in[0];
    const int*   nbr  = (const int*)d_in[1];
    const float* w1   = (const float*)d_in[2];
    const float* w2   = (const float*)d_in[3];
    const float* w3   = (const float*)d_in[4];
    const float* g1   = (const float*)d_in[5];
    const float* b1   = (const float*)d_in[6];
    const float* g2   = (const float*)d_in[7];
    const float* b2   = (const float*)d_in[8];
    const float* g3   = (const float*)d_in[9];
    const float* b3   = (const float*)d_in[10];
    float* out = (float*)d_out;

    float *p_y, *p_res, *p_stage;
    __half *p_xh, *p_xl, *p_wh, *p_wl;
    cudaGetSymbolAddress((void**)&p_y, g_y);
    cudaGetSymbolAddress((void**)&p_res, g_res);
    cudaGetSymbolAddress((void**)&p_stage, g_stage);
    cudaGetSymbolAddress((void**)&p_xh, g_xh);
    cudaGetSymbolAddress((void**)&p_xl, g_xl);
    cudaGetSymbolAddress((void**)&p_wh, g_wh);
    cudaGetSymbolAddress((void**)&p_wl, g_wl);

    const int nelem4 = (N_VOX * CCH) / 4;       // 4.19M float4
    const int act_grid = nelem4 / 256;          // 16384
    const int comb_grid = (N_VOX * 32) / 256;   // 16384

    // rulebook + operand splits
    k_zero_cnt<<<1, 32>>>();
    k_count<<<(NK * N_VOX) / 256, 256>>>(nbr);
    k_scan<<<1, 1>>>();
    k_fill<<<(NK * N_VOX) / 256, 256>>>(nbr);
    {
        dim3 wg(WSZ / 256, 3);
        k_wsplit<<<wg, 256>>>(w1, w2, w3);
    }
    k_xsplit<<<act_grid, 256>>>(feat);

    // ---- layer 1 ----
    conv_mma<<<TPK, 256>>>(p_xh, p_xl, p_wh, p_wl, p_y, 1);
    conv_mma<<<26 * TPK, 256>>>(p_xh, p_xl, p_wh, p_wl, p_stage, 0);
    k_combine<<<comb_grid, 256>>>(p_y);
    k_zero_stats<<<1, 128>>>();
    k_stats<<<1024, 128>>>(p_y);
    k_finalize<<<1, 128>>>(g1, b1);
    k_act_inner<<<act_grid, 256>>>(p_y, p_res, 1);

    // ---- layer 2 ----
    conv_mma<<<TPK, 256>>>(p_xh, p_xl, p_wh + WSZ, p_wl + WSZ, p_y, 1);
    conv_mma<<<26 * TPK, 256>>>(p_xh, p_xl, p_wh + WSZ, p_wl + WSZ, p_stage, 0);
    k_combine<<<comb_grid, 256>>>(p_y);
    k_zero_stats<<<1, 128>>>();
    k_stats<<<1024, 128>>>(p_y);
    k_finalize<<<1, 128>>>(g2, b2);
    k_act_inner<<<act_grid, 256>>>(p_y, p_res, 0);

    // ---- layer 3 ----
    conv_mma<<<TPK, 256>>>(p_xh, p_xl, p_wh + 2 * WSZ, p_wl + 2 * WSZ, p_y, 1);
    conv_mma<<<26 * TPK, 256>>>(p_xh, p_xl, p_wh + 2 * WSZ, p_wl + 2 * WSZ, p_stage, 0);
    k_combine<<<comb_grid, 256>>>(p_y);
    k_zero_stats<<<1, 128>>>();
    k_stats<<<1024, 128>>>(p_y);
    k_finalize<<<1, 128>>>(g3, b3);
    k_act_out<<<act_grid, 256>>>(p_y, p_res, out);
}

// round 4
// speedup vs baseline: 2.5107x; 1.2149x over previous
#include <cuda_runtime.h>
#include <cuda_fp16.h>
#include <cstdint>

#define N_VOX 131072
#define CCH 128
#define NK 27
#define TMROWS 128
#define TPK (N_VOX / TMROWS)       // 1024 tiles per offset
#define STAGE_ROWS (8 * N_VOX)
#define WSZ (NK * CCH * CCH)       // 442368
#define EPSF 1e-4f
#define SLOPE_IN 0.05f
#define SLOPE_OUT (1.0f / 3.0f)

// ---------------- scratch (device globals) ----------------------------------
__device__ float g_y[(size_t)N_VOX * CCH];
__device__ float g_res[(size_t)N_VOX * CCH];
__device__ float g_stage[(size_t)STAGE_ROWS * CCH];
__device__ __half g_xh[(size_t)N_VOX * CCH];
__device__ __half g_xl[(size_t)N_VOX * CCH];
__device__ __half g_wh[3 * WSZ];
__device__ __half g_wl[3 * WSZ];
__device__ int   g_pairs_j[STAGE_ROWS];
__device__ int   g_pos[N_VOX * NK];
__device__ int   g_cnt[NK];
__device__ int   g_off[NK];
__device__ int   g_cursor[NK];
__device__ float g_sum[CCH], g_sumsq[CCH];
__device__ float g_scale[CCH], g_shift[CCH];

// ---------------- rulebook ----------------------------------------------------
__global__ void k_zero_cnt() {
    if (threadIdx.x < NK) { g_cnt[threadIdx.x] = 0; g_cursor[threadIdx.x] = 0; }
}

__global__ void k_count(const int* __restrict__ nbr) {
    __shared__ int scnt;
    if (threadIdx.x == 0) scnt = 0;
    __syncthreads();
    int idx = blockIdx.x * 256 + threadIdx.x;
    int k = idx >> 17;
    int i = idx & (N_VOX - 1);
    int j = (k == 13) ? -1 : nbr[i * NK + k];
    unsigned m = __ballot_sync(0xffffffffu, j >= 0);
    if ((threadIdx.x & 31) == 0 && m) atomicAdd(&scnt, __popc(m));
    __syncthreads();
    if (threadIdx.x == 0 && scnt) atomicAdd(&g_cnt[k], scnt);
}

__global__ void k_scan() {
    int o = 0;
    for (int k = 0; k < NK; ++k) { g_off[k] = o; o += g_cnt[k]; }
}

__global__ void k_fill(const int* __restrict__ nbr) {
    __shared__ int woff[8];
    __shared__ int sbase;
    int idx = blockIdx.x * 256 + threadIdx.x;
    int k = idx >> 17;
    int i = idx & (N_VOX - 1);
    if (k == 13) { g_pos[i * NK + 13] = -1; return; }
    int j = nbr[i * NK + k];
    bool valid = (j >= 0);
    unsigned m = __ballot_sync(0xffffffffu, valid);
    int w = threadIdx.x >> 5, lane = threadIdx.x & 31;
    if (lane == 0) woff[w] = __popc(m);
    __syncthreads();
    if (threadIdx.x == 0) {
        int o = 0;
        for (int q = 0; q < 8; ++q) { int c = woff[q]; woff[q] = o; o += c; }
        sbase = o ? atomicAdd(&g_cursor[k], o) : 0;
    }
    __syncthreads();
    int pos = -1;
    if (valid) {
        pos = g_off[k] + sbase + woff[w] + __popc(m & ((1u << lane) - 1u));
        g_pairs_j[pos] = j;
    }
    g_pos[i * NK + k] = pos;
}

// ---------------- fp16 hi/lo splits --------------------------------------------
__global__ void k_wsplit(const float* __restrict__ w1, const float* __restrict__ w2,
                         const float* __restrict__ w3) {
    int i = blockIdx.x * blockDim.x + threadIdx.x;
    const float* src = (blockIdx.y == 0) ? w1 : (blockIdx.y == 1 ? w2 : w3);
    float v = src[i];
    __half h = __float2half(v);
    g_wh[blockIdx.y * WSZ + i] = h;
    g_wl[blockIdx.y * WSZ + i] = __float2half(v - __half2float(h));
}

__device__ __forceinline__ void split_store4(int idx, float4 v) {
    __half h0 = __float2half(v.x), h1 = __float2half(v.y);
    __half h2 = __float2half(v.z), h3 = __float2half(v.w);
    __half l0 = __float2half(v.x - __half2float(h0));
    __half l1 = __float2half(v.y - __half2float(h1));
    __half l2 = __float2half(v.z - __half2float(h2));
    __half l3 = __float2half(v.w - __half2float(h3));
    __half2* xh = (__half2*)g_xh;
    __half2* xl = (__half2*)g_xl;
    xh[idx * 2]     = __halves2half2(h0, h1);
    xh[idx * 2 + 1] = __halves2half2(h2, h3);
    xl[idx * 2]     = __halves2half2(l0, l1);
    xl[idx * 2 + 1] = __halves2half2(l2, l3);
}

__global__ void k_xsplit(const float* __restrict__ F) {
    int idx = blockIdx.x * blockDim.x + threadIdx.x;
    float4 v = *(const float4*)(F + (size_t)idx * 4);
    split_store4(idx, v);
}

// ---------------- mma.sync helpers ----------------------------------------------
__device__ __forceinline__ void mma16816(float* d, const unsigned* a, const unsigned* b) {
    asm volatile(
        "mma.sync.aligned.m16n8k16.row.col.f32.f16.f16.f32 "
        "{%0,%1,%2,%3}, {%4,%5,%6,%7}, {%8,%9}, {%0,%1,%2,%3};"
        : "+f"(d[0]), "+f"(d[1]), "+f"(d[2]), "+f"(d[3])
        : "r"(a[0]), "r"(a[1]), "r"(a[2]), "r"(a[3]), "r"(b[0]), "r"(b[1]));
}

#define LDSM_X4(R, addr) asm volatile( \
    "ldmatrix.sync.aligned.m8n8.x4.shared.b16 {%0,%1,%2,%3}, [%4];" \
    : "=r"((R)[0]), "=r"((R)[1]), "=r"((R)[2]), "=r"((R)[3]) : "r"(addr))
#define LDSM_X4T(R, addr) asm volatile( \
    "ldmatrix.sync.aligned.m8n8.x4.trans.shared.b16 {%0,%1,%2,%3}, [%4];" \
    : "=r"((R)[0]), "=r"((R)[1]), "=r"((R)[2]), "=r"((R)[3]) : "r"(addr))

__device__ __forceinline__ void cp16(unsigned dst, const void* src, int srcsize) {
    asm volatile("cp.async.cg.shared.global [%0], [%1], 16, %2;"
                 :: "r"(dst), "l"(src), "r"(srcsize) : "memory");
}
#define CP_COMMIT() asm volatile("cp.async.commit_group;" ::: "memory")
#define CP_WAIT1() asm volatile("cp.async.wait_group 1;" ::: "memory")
#define CP_WAIT0() asm volatile("cp.async.wait_group 0;" ::: "memory")

// ---------------- SMEM layout (dynamic, bytes) -----------------------------------
// A: 128 rows x 136 halves (pad 8) hi + lo ; B: 2 stages x (hi,lo) 32 x 136
#define SM_AH 0
#define SM_AL 34816
#define SM_BB 69632            // + stage*17408 + hl*8704
#define SM_SJ 104448
#define SMEM_BYTES 104960

// One launch covers all 27 offsets: blockIdx.x = k*1024 + tile.
// k==13 -> dense self tap, output g_y rows; else compacted pairs -> g_stage.
__global__ void __launch_bounds__(256, 2) conv_mma(
    const __half* __restrict__ Xh, const __half* __restrict__ Xl,
    const __half* __restrict__ Wh, const __half* __restrict__ Wl,
    float* __restrict__ Ystage, float* __restrict__ Yself)
{
    extern __shared__ char dsm[];
    unsigned sb = (unsigned)__cvta_generic_to_shared(dsm);
    int tid = threadIdx.x;
    int k = blockIdx.x >> 10;
    int t = blockIdx.x & (TPK - 1);
    int m0 = t * TMROWS;

    int cnt, obase;
    float* OUT;
    if (k == 13) {
        cnt = N_VOX; obase = m0; OUT = Yself;
    } else {
        cnt = g_cnt[k];
        if (m0 >= cnt) return;
        obase = g_off[k] + m0;
        OUT = Ystage;
    }
    int rows = min(TMROWS, cnt - m0);
    const __half* Whk = Wh + k * CCH * CCH;
    const __half* Wlk = Wl + k * CCH * CCH;

    int* sj = (int*)(dsm + SM_SJ);
    if (tid < TMROWS) {
        int j = -1;
        if (tid < rows) j = (k == 13) ? (m0 + tid) : g_pairs_j[obase + tid];
        sj[tid] = j;
    }
    __syncthreads();

    // ---- issue B chunk 0 (group) ----
    {
#pragma unroll
        for (int it = 0; it < 4; ++it) {
            int u = it * 256 + tid;
            int hl = u >> 9;
            int rem = u & 511;
            int row = rem >> 4;
            int seg = rem & 15;
            const __half* src = (hl ? Wlk : Whk) + (size_t)row * CCH + seg * 8;
            unsigned dst = sb + SM_BB + hl * 8704 + row * 272 + seg * 16;
            cp16(dst, src, 16);
        }
        CP_COMMIT();
    }
    // ---- issue full A (hi+lo), zero-fill invalid rows (group) ----
    {
#pragma unroll
        for (int it = 0; it < 16; ++it) {
            int u = it * 256 + tid;
            int hl = u >> 11;
            int rem = u & 2047;
            int row = rem >> 4;
            int seg = rem & 15;
            int j = sj[row];
            const __half* src = (hl ? Xl : Xh) + (size_t)max(j, 0) * CCH + seg * 8;
            unsigned dst = sb + (hl ? SM_AL : SM_AH) + row * 272 + seg * 16;
            cp16(dst, src, j >= 0 ? 16 : 0);
        }
        CP_COMMIT();
    }

    int lane = tid & 31, warp = tid >> 5;
    int wm = warp & 3, wn = warp >> 2;
    int arow = wm * 32 + (lane & 15);
    int acol = (lane >> 4) * 8;
    int brow = lane & 15;
    int bcol = wn * 64 + (lane >> 4) * 8;

    float acc[2][8][4];
#pragma unroll
    for (int mi = 0; mi < 2; ++mi)
#pragma unroll
        for (int ni = 0; ni < 8; ++ni)
#pragma unroll
            for (int q = 0; q < 4; ++q) acc[mi][ni][q] = 0.f;

#pragma unroll
    for (int kc = 0; kc < 4; ++kc) {
        if (kc < 3) {        // prefetch next B chunk into the other stage
#pragma unroll
            for (int it = 0; it < 4; ++it) {
                int u = it * 256 + tid;
                int hl = u >> 9;
                int rem = u & 511;
                int row = rem >> 4;
                int seg = rem & 15;
                const __half* src = (hl ? Wlk : Whk) +
                                    (size_t)((kc + 1) * 32 + row) * CCH + seg * 8;
                unsigned dst = sb + SM_BB + ((kc + 1) & 1) * 17408 + hl * 8704 +
                               row * 272 + seg * 16;
                cp16(dst, src, 16);
            }
            CP_COMMIT();
            CP_WAIT1();
        } else {
            CP_WAIT0();
        }
        __syncthreads();

        unsigned bb_h = sb + SM_BB + (kc & 1) * 17408;
        unsigned bb_l = bb_h + 8704;
#pragma unroll
        for (int kk = 0; kk < 2; ++kk) {
            unsigned ahf[2][4], alf[2][4];
#pragma unroll
            for (int mi = 0; mi < 2; ++mi) {
                unsigned off = (unsigned)(((arow + mi * 16) * 136 + kc * 32 +
                                           kk * 16 + acol) * 2);
                LDSM_X4(ahf[mi], sb + SM_AH + off);
                LDSM_X4(alf[mi], sb + SM_AL + off);
            }
#pragma unroll
            for (int n2 = 0; n2 < 4; ++n2) {
                unsigned boff = (unsigned)(((kk * 16 + brow) * 136 + bcol +
                                            n2 * 16) * 2);
                unsigned bhf[4], blf[4];
                LDSM_X4T(bhf, bb_h + boff);
                LDSM_X4T(blf, bb_l + boff);
#pragma unroll
                for (int mi = 0; mi < 2; ++mi) {
                    mma16816(acc[mi][n2 * 2],     ahf[mi], bhf);
                    mma16816(acc[mi][n2 * 2],     ahf[mi], blf);
                    mma16816(acc[mi][n2 * 2],     alf[mi], bhf);
                    mma16816(acc[mi][n2 * 2 + 1], ahf[mi], bhf + 2);
                    mma16816(acc[mi][n2 * 2 + 1], ahf[mi], blf + 2);
                    mma16816(acc[mi][n2 * 2 + 1], alf[mi], bhf + 2);
                }
            }
        }
        __syncthreads();
    }

    // ---- epilogue ----
    int gr = lane >> 2, gc = (lane & 3) * 2;
#pragma unroll
    for (int mi = 0; mi < 2; ++mi)
#pragma unroll
        for (int ni = 0; ni < 8; ++ni) {
            int c = wn * 64 + ni * 8 + gc;
            int r0 = wm * 32 + mi * 16 + gr;
            if (r0 < rows)
                *(float2*)(OUT + (size_t)(obase + r0) * CCH + c) =
                    make_float2(acc[mi][ni][0], acc[mi][ni][1]);
            int r1 = r0 + 8;
            if (r1 < rows)
                *(float2*)(OUT + (size_t)(obase + r1) * CCH + c) =
                    make_float2(acc[mi][ni][2], acc[mi][ni][3]);
        }
}

// ---------------- combine staged rows into g_y (+ zero stats) --------------------
__global__ void k_combine(float* __restrict__ Y) {
    if (blockIdx.x == 0 && threadIdx.x < CCH) {
        g_sum[threadIdx.x] = 0.f;
        g_sumsq[threadIdx.x] = 0.f;
    }
    int gt = blockIdx.x * blockDim.x + threadIdx.x;
    int w = gt >> 5;
    int lane = gt & 31;
    if (w >= N_VOX) return;
    int myp = -1;
    if (lane < NK) myp = g_pos[w * NK + lane];
    float4 acc = *(const float4*)(Y + (size_t)w * CCH + lane * 4);
#pragma unroll
    for (int k = 0; k < NK; ++k) {
        int s = __shfl_sync(0xffffffffu, myp, k);
        if (s >= 0) {
            float4 v = *(const float4*)(g_stage + (size_t)s * CCH + lane * 4);
            acc.x += v.x; acc.y += v.y; acc.z += v.z; acc.w += v.w;
        }
    }
    *(float4*)(Y + (size_t)w * CCH + lane * 4) = acc;
}

// ---------------- batchnorm --------------------------------------------------------
__global__ void k_stats(const float* __restrict__ Y) {
    int c = threadIdx.x;
    float s = 0.f, s2 = 0.f;
    for (int i = blockIdx.x; i < N_VOX; i += gridDim.x) {
        float v = Y[(size_t)i * CCH + c];
        s += v; s2 += v * v;
    }
    atomicAdd(&g_sum[c], s);
    atomicAdd(&g_sumsq[c], s2);
}

__global__ void k_finalize(const float* __restrict__ gma, const float* __restrict__ bta) {
    int c = threadIdx.x;
    float mu = g_sum[c] * (1.0f / N_VOX);
    float var = g_sumsq[c] * (1.0f / N_VOX) - mu * mu;
    float rs = rsqrtf(var + EPSF);
    float sc = gma[c] * rs;
    g_scale[c] = sc;
    g_shift[c] = bta[c] - mu * sc;
}

// ---------------- activations --------------------------------------------------------
__global__ void k_act_inner(const float* __restrict__ Y, float* __restrict__ R, int write_res) {
    int idx = blockIdx.x * blockDim.x + threadIdx.x;
    int c4 = (idx & 31) << 2;
    float4 y = *(const float4*)(Y + (size_t)idx * 4);
    float4 sc = *(const float4*)(g_scale + c4);
    float4 sh = *(const float4*)(g_shift + c4);
    float4 v;
    v.x = fmaf(y.x, sc.x, sh.x);
    v.y = fmaf(y.y, sc.y, sh.y);
    v.z = fmaf(y.z, sc.z, sh.z);
    v.w = fmaf(y.w, sc.w, sh.w);
    v.x = v.x >= 0.f ? v.x : SLOPE_IN * v.x;
    v.y = v.y >= 0.f ? v.y : SLOPE_IN * v.y;
    v.z = v.z >= 0.f ? v.z : SLOPE_IN * v.z;
    v.w = v.w >= 0.f ? v.w : SLOPE_IN * v.w;
    split_store4(idx, v);
    if (write_res) *(float4*)(R + (size_t)idx * 4) = v;
}

__global__ void k_act_out(const float* __restrict__ Y, const float* __restrict__ R,
                          float* __restrict__ O) {
    int idx = blockIdx.x * blockDim.x + threadIdx.x;
    int c4 = (idx & 31) << 2;
    float4 y = *(const float4*)(Y + (size_t)idx * 4);
    float4 r = *(const float4*)(R + (size_t)idx * 4);
    float4 sc = *(const float4*)(g_scale + c4);
    float4 sh = *(const float4*)(g_shift + c4);
    float4 v;
    v.x = fmaf(y.x, sc.x, sh.x) + r.x;
    v.y = fmaf(y.y, sc.y, sh.y) + r.y;
    v.z = fmaf(y.z, sc.z, sh.z) + r.z;
    v.w = fmaf(y.w, sc.w, sh.w) + r.w;
    v.x = v.x >= 0.f ? v.x : SLOPE_OUT * v.x;
    v.y = v.y >= 0.f ? v.y : SLOPE_OUT * v.y;
    v.z = v.z >= 0.f ? v.z : SLOPE_OUT * v.z;
    v.w = v.w >= 0.f ? v.w : SLOPE_OUT * v.w;
    *(float4*)(O + (size_t)idx * 4) = v;
}

// ---------------- launch ----------------------------------------------------------------
extern "C" void kernel_launch(void* const* d_in, const int* in_sizes, int n_in,
                              void* d_out, int out_size) {
    const float* feat = (const float*)d_in[0];
    const int*   nbr  = (const int*)d_in[1];
    const float* w1   = (const float*)d_in[2];
    const float* w2   = (const float*)d_in[3];
    const float* w3   = (const float*)d_in[4];
    const float* g1   = (const float*)d_in[5];
    const float* b1   = (const float*)d_in[6];
    const float* g2   = (const float*)d_in[7];
    const float* b2   = (const float*)d_in[8];
    const float* g3   = (const float*)d_in[9];
    const float* b3   = (const float*)d_in[10];
    float* out = (float*)d_out;

    float *p_y, *p_res, *p_stage;
    __half *p_xh, *p_xl, *p_wh, *p_wl;
    cudaGetSymbolAddress((void**)&p_y, g_y);
    cudaGetSymbolAddress((void**)&p_res, g_res);
    cudaGetSymbolAddress((void**)&p_stage, g_stage);
    cudaGetSymbolAddress((void**)&p_xh, g_xh);
    cudaGetSymbolAddress((void**)&p_xl, g_xl);
    cudaGetSymbolAddress((void**)&p_wh, g_wh);
    cudaGetSymbolAddress((void**)&p_wl, g_wl);

    cudaFuncSetAttribute(conv_mma, cudaFuncAttributeMaxDynamicSharedMemorySize,
                         SMEM_BYTES);

    const int nelem4 = (N_VOX * CCH) / 4;
    const int act_grid = nelem4 / 256;
    const int comb_grid = (N_VOX * 32) / 256;
    const int conv_grid = NK * TPK;            // 27648

    // rulebook + operand prep
    k_zero_cnt<<<1, 32>>>();
    k_count<<<(NK * N_VOX) / 256, 256>>>(nbr);
    k_scan<<<1, 1>>>();
    k_fill<<<(NK * N_VOX) / 256, 256>>>(nbr);
    {
        dim3 wg(WSZ / 256, 3);
        k_wsplit<<<wg, 256>>>(w1, w2, w3);
    }
    k_xsplit<<<act_grid, 256>>>(feat);

    // ---- layer 1 ----
    conv_mma<<<conv_grid, 256, SMEM_BYTES>>>(p_xh, p_xl, p_wh, p_wl, p_stage, p_y);
    k_combine<<<comb_grid, 256>>>(p_y);
    k_stats<<<1024, 128>>>(p_y);
    k_finalize<<<1, 128>>>(g1, b1);
    k_act_inner<<<act_grid, 256>>>(p_y, p_res, 1);

    // ---- layer 2 ----
    conv_mma<<<conv_grid, 256, SMEM_BYTES>>>(p_xh, p_xl, p_wh + WSZ, p_wl + WSZ, p_stage, p_y);
    k_combine<<<comb_grid, 256>>>(p_y);
    k_stats<<<1024, 128>>>(p_y);
    k_finalize<<<1, 128>>>(g2, b2);
    k_act_inner<<<act_grid, 256>>>(p_y, p_res, 0);

    // ---- layer 3 ----
    conv_mma<<<conv_grid, 256, SMEM_BYTES>>>(p_xh, p_xl, p_wh + 2 * WSZ, p_wl + 2 * WSZ, p_stage, p_y);
    k_combine<<<comb_grid, 256>>>(p_y);
    k_stats<<<1024, 128>>>(p_y);
    k_finalize<<<1, 128>>>(g3, b3);
    k_act_out<<<act_grid, 256>>>(p_y, p_res, out);
}

// round 6
// speedup vs baseline: 2.7701x; 1.1033x over previous
#include <cuda_runtime.h>
#include <cuda_fp16.h>
#include <cstdint>

#define N_VOX 131072
#define CCH 128
#define NK 27
#define TMROWS 128
#define TPK (N_VOX / TMROWS)       // 1024 tiles per offset
#define STAGE_ROWS (8 * N_VOX)
#define WSZ (NK * CCH * CCH)       // 442368
#define EPSF 1e-4f
#define SLOPE_IN 0.05f
#define SLOPE_OUT (1.0f / 3.0f)

// ---------------- scratch (device globals) ----------------------------------
__device__ float g_y[(size_t)N_VOX * CCH];
__device__ float g_res[(size_t)N_VOX * CCH];
__device__ float g_stage[(size_t)STAGE_ROWS * CCH];
__device__ __half g_xh[(size_t)N_VOX * CCH];
__device__ __half g_xl[(size_t)N_VOX * CCH];
__device__ __half g_wh[3 * WSZ];
__device__ __half g_wl[3 * WSZ];
__device__ int   g_pairs_j[STAGE_ROWS];
__device__ int   g_pos[N_VOX * NK];
__device__ int   g_cnt[NK];
__device__ int   g_off[NK];
__device__ int   g_cursor[NK];
__device__ float g_sum[CCH], g_sumsq[CCH];
__device__ float g_scale[CCH], g_shift[CCH];

// ---------------- rulebook ----------------------------------------------------
__global__ void k_zero_cnt() {
    if (threadIdx.x < NK) { g_cnt[threadIdx.x] = 0; g_cursor[threadIdx.x] = 0; }
}

__global__ void k_count(const int* __restrict__ nbr) {
    __shared__ int scnt;
    if (threadIdx.x == 0) scnt = 0;
    __syncthreads();
    int idx = blockIdx.x * 256 + threadIdx.x;
    int k = idx >> 17;
    int i = idx & (N_VOX - 1);
    int j = (k == 13) ? -1 : nbr[i * NK + k];
    unsigned m = __ballot_sync(0xffffffffu, j >= 0);
    if ((threadIdx.x & 31) == 0 && m) atomicAdd(&scnt, __popc(m));
    __syncthreads();
    if (threadIdx.x == 0 && scnt) atomicAdd(&g_cnt[k], scnt);
}

__global__ void k_scan() {
    int o = 0;
    for (int k = 0; k < NK; ++k) { g_off[k] = o; o += g_cnt[k]; }
}

__global__ void k_fill(const int* __restrict__ nbr) {
    __shared__ int woff[8];
    __shared__ int sbase;
    int idx = blockIdx.x * 256 + threadIdx.x;
    int k = idx >> 17;
    int i = idx & (N_VOX - 1);
    if (k == 13) { g_pos[i * NK + 13] = -1; return; }
    int j = nbr[i * NK + k];
    bool valid = (j >= 0);
    unsigned m = __ballot_sync(0xffffffffu, valid);
    int w = threadIdx.x >> 5, lane = threadIdx.x & 31;
    if (lane == 0) woff[w] = __popc(m);
    __syncthreads();
    if (threadIdx.x == 0) {
        int o = 0;
        for (int q = 0; q < 8; ++q) { int c = woff[q]; woff[q] = o; o += c; }
        sbase = o ? atomicAdd(&g_cursor[k], o) : 0;
    }
    __syncthreads();
    int pos = -1;
    if (valid) {
        pos = g_off[k] + sbase + woff[w] + __popc(m & ((1u << lane) - 1u));
        g_pairs_j[pos] = j;
    }
    g_pos[i * NK + k] = pos;
}

// ---------------- fp16 hi/lo splits --------------------------------------------
__global__ void k_wsplit(const float* __restrict__ w1, const float* __restrict__ w2,
                         const float* __restrict__ w3) {
    int i = blockIdx.x * blockDim.x + threadIdx.x;
    const float* src = (blockIdx.y == 0) ? w1 : (blockIdx.y == 1 ? w2 : w3);
    float v = src[i];
    __half h = __float2half(v);
    g_wh[blockIdx.y * WSZ + i] = h;
    g_wl[blockIdx.y * WSZ + i] = __float2half(v - __half2float(h));
}

__device__ __forceinline__ void split_store4(int idx, float4 v) {
    __half h0 = __float2half(v.x), h1 = __float2half(v.y);
    __half h2 = __float2half(v.z), h3 = __float2half(v.w);
    __half l0 = __float2half(v.x - __half2float(h0));
    __half l1 = __float2half(v.y - __half2float(h1));
    __half l2 = __float2half(v.z - __half2float(h2));
    __half l3 = __float2half(v.w - __half2float(h3));
    __half2* xh = (__half2*)g_xh;
    __half2* xl = (__half2*)g_xl;
    xh[idx * 2]     = __halves2half2(h0, h1);
    xh[idx * 2 + 1] = __halves2half2(h2, h3);
    xl[idx * 2]     = __halves2half2(l0, l1);
    xl[idx * 2 + 1] = __halves2half2(l2, l3);
}

__global__ void k_xsplit(const float* __restrict__ F) {
    int idx = blockIdx.x * blockDim.x + threadIdx.x;
    float4 v = *(const float4*)(F + (size_t)idx * 4);
    split_store4(idx, v);
}

// ---------------- mma.sync helpers ----------------------------------------------
__device__ __forceinline__ void mma16816(float* d, const unsigned* a, const unsigned* b) {
    asm volatile(
        "mma.sync.aligned.m16n8k16.row.col.f32.f16.f16.f32 "
        "{%0,%1,%2,%3}, {%4,%5,%6,%7}, {%8,%9}, {%0,%1,%2,%3};"
        : "+f"(d[0]), "+f"(d[1]), "+f"(d[2]), "+f"(d[3])
        : "r"(a[0]), "r"(a[1]), "r"(a[2]), "r"(a[3]), "r"(b[0]), "r"(b[1]));
}

#define LDSM_X4(R, addr) asm volatile( \
    "ldmatrix.sync.aligned.m8n8.x4.shared.b16 {%0,%1,%2,%3}, [%4];" \
    : "=r"((R)[0]), "=r"((R)[1]), "=r"((R)[2]), "=r"((R)[3]) : "r"(addr))
#define LDSM_X4T(R, addr) asm volatile( \
    "ldmatrix.sync.aligned.m8n8.x4.trans.shared.b16 {%0,%1,%2,%3}, [%4];" \
    : "=r"((R)[0]), "=r"((R)[1]), "=r"((R)[2]), "=r"((R)[3]) : "r"(addr))

__device__ __forceinline__ void cp16(unsigned dst, const void* src, int srcsize) {
    asm volatile("cp.async.cg.shared.global [%0], [%1], 16, %2;"
                 :: "r"(dst), "l"(src), "r"(srcsize) : "memory");
}
#define CP_COMMIT() asm volatile("cp.async.commit_group;" ::: "memory")
#define CP_WAIT1() asm volatile("cp.async.wait_group 1;" ::: "memory")
#define CP_WAIT0() asm volatile("cp.async.wait_group 0;" ::: "memory")

// ---------------- SMEM layout (dynamic, bytes; 256B rows, XOR-swizzled) ----------
// A: 128 rows x 128 halves, hi + lo.  B: 3 stages x (hi,lo) x 32 rows x 128 halves.
#define SM_AH 0
#define SM_AL 32768
#define SM_BB 65536            // + stage*16384 + hl*8192
#define SM_SJ 114688
#define SMEM_BYTES 115200

// granule swizzle: 16B granule g within a 256B row -> g ^ (row & 7)
__device__ __forceinline__ unsigned swz(int row, int g) {
    return (unsigned)(row * 256 + ((g ^ (row & 7)) << 4));
}

// One launch covers all 27 offsets: blockIdx.x = k*1024 + tile.
__global__ void __launch_bounds__(256, 2) conv_mma(
    const __half* __restrict__ Xh, const __half* __restrict__ Xl,
    const __half* __restrict__ Wh, const __half* __restrict__ Wl,
    float* __restrict__ Ystage, float* __restrict__ Yself)
{
    extern __shared__ char dsm[];
    unsigned sb = (unsigned)__cvta_generic_to_shared(dsm);
    int tid = threadIdx.x;
    int k = blockIdx.x >> 10;
    int t = blockIdx.x & (TPK - 1);
    int m0 = t * TMROWS;

    // zero BN accumulators for the following combine pass (one block does it)
    if (blockIdx.x == 13 * 1024 && tid < CCH) {
        g_sum[tid] = 0.f;
        g_sumsq[tid] = 0.f;
    }

    int cnt, obase;
    float* OUT;
    if (k == 13) {
        cnt = N_VOX; obase = m0; OUT = Yself;
    } else {
        cnt = g_cnt[k];
        if (m0 >= cnt) return;
        obase = g_off[k] + m0;
        OUT = Ystage;
    }
    int rows = min(TMROWS, cnt - m0);
    const __half* Whk = Wh + k * CCH * CCH;
    const __half* Wlk = Wl + k * CCH * CCH;

    // ---- issue B chunks 0 and 1 (stages 0,1) ----
#pragma unroll
    for (int c = 0; c < 2; ++c) {
#pragma unroll
        for (int it = 0; it < 4; ++it) {
            int u = it * 256 + tid;
            int hl = u >> 9;
            int rem = u & 511;
            int row = rem >> 4;
            int seg = rem & 15;
            const __half* src = (hl ? Wlk : Whk) + (size_t)(c * 32 + row) * CCH + seg * 8;
            cp16(sb + SM_BB + c * 16384 + hl * 8192 + swz(row, seg), src, 16);
        }
        CP_COMMIT();
    }

    int* sj = (int*)(dsm + SM_SJ);
    if (tid < TMROWS) {
        int j = -1;
        if (tid < rows) j = (k == 13) ? (m0 + tid) : g_pairs_j[obase + tid];
        sj[tid] = j;
    }
    __syncthreads();

    // ---- issue full A (hi+lo), zero-fill invalid rows ----
    {
#pragma unroll
        for (int it = 0; it < 16; ++it) {
            int u = it * 256 + tid;
            int hl = u >> 11;
            int rem = u & 2047;
            int row = rem >> 4;
            int seg = rem & 15;
            int j = sj[row];
            const __half* src = (hl ? Xl : Xh) + (size_t)max(j, 0) * CCH + seg * 8;
            cp16(sb + (hl ? SM_AL : SM_AH) + swz(row, seg), src, j >= 0 ? 16 : 0);
        }
        CP_COMMIT();
    }

    int lane = tid & 31, warp = tid >> 5;
    int wm = warp & 3, wn = warp >> 2;
    int arow = wm * 32 + (lane & 15);
    int brow = lane & 15;
    int gsel = lane >> 4;          // granule half-select

    float acc[2][8][4];
#pragma unroll
    for (int mi = 0; mi < 2; ++mi)
#pragma unroll
        for (int ni = 0; ni < 8; ++ni)
#pragma unroll
            for (int q = 0; q < 4; ++q) acc[mi][ni][q] = 0.f;

#pragma unroll
    for (int kc = 0; kc < 4; ++kc) {
        // 1. wait for the data this iteration reads
        if (kc == 0) {
            CP_WAIT0();        // B0, B1, A all complete
        } else if (kc == 2) {
            CP_WAIT1();        // B2 complete (B3 group may remain pending)
        } else if (kc == 3) {
            CP_WAIT0();        // B3 complete
        }
        // 2. barrier: everyone done with previous compute AND sees waited data
        __syncthreads();
        // 3. prefetch: kc=0 -> chunk2 (stage 2), kc=1 -> chunk3 (stage 0, now free)
        if (kc < 2) {
            int c = kc + 2;
            int s = c % 3;
#pragma unroll
            for (int it = 0; it < 4; ++it) {
                int u = it * 256 + tid;
                int hl = u >> 9;
                int rem = u & 511;
                int row = rem >> 4;
                int seg = rem & 15;
                const __half* src = (hl ? Wlk : Whk) + (size_t)(c * 32 + row) * CCH + seg * 8;
                cp16(sb + SM_BB + s * 16384 + hl * 8192 + swz(row, seg), src, 16);
            }
            CP_COMMIT();
        }
        // 4. compute on stage kc%3
        unsigned bb = sb + SM_BB + (kc % 3) * 16384;
#pragma unroll
        for (int kk = 0; kk < 2; ++kk) {
            unsigned ahf[2][4], alf[2][4];
            int gA = kc * 4 + kk * 2 + gsel;
#pragma unroll
            for (int mi = 0; mi < 2; ++mi) {
                int R = arow + mi * 16;
                unsigned off = swz(R, gA);
                LDSM_X4(ahf[mi], sb + SM_AH + off);
                LDSM_X4(alf[mi], sb + SM_AL + off);
            }
            int rB = kk * 16 + brow;
#pragma unroll
            for (int n2 = 0; n2 < 4; ++n2) {
                int gB = wn * 8 + n2 * 2 + gsel;
                unsigned boff = swz(rB, gB);
                unsigned bhf[4], blf[4];
                LDSM_X4T(bhf, bb + boff);
                LDSM_X4T(blf, bb + 8192 + boff);
#pragma unroll
                for (int mi = 0; mi < 2; ++mi) {
                    mma16816(acc[mi][n2 * 2],     ahf[mi], bhf);
                    mma16816(acc[mi][n2 * 2],     ahf[mi], blf);
                    mma16816(acc[mi][n2 * 2],     alf[mi], bhf);
                    mma16816(acc[mi][n2 * 2 + 1], ahf[mi], bhf + 2);
                    mma16816(acc[mi][n2 * 2 + 1], ahf[mi], blf + 2);
                    mma16816(acc[mi][n2 * 2 + 1], alf[mi], bhf + 2);
                }
            }
        }
    }

    // ---- epilogue ----
    int gr = lane >> 2, gc = (lane & 3) * 2;
#pragma unroll
    for (int mi = 0; mi < 2; ++mi)
#pragma unroll
        for (int ni = 0; ni < 8; ++ni) {
            int c = wn * 64 + ni * 8 + gc;
            int r0 = wm * 32 + mi * 16 + gr;
            if (r0 < rows)
                *(float2*)(OUT + (size_t)(obase + r0) * CCH + c) =
                    make_float2(acc[mi][ni][0], acc[mi][ni][1]);
            int r1 = r0 + 8;
            if (r1 < rows)
                *(float2*)(OUT + (size_t)(obase + r1) * CCH + c) =
                    make_float2(acc[mi][ni][2], acc[mi][ni][3]);
        }
}

// ---------------- combine staged rows into g_y + BN stats -----------------------
__global__ void __launch_bounds__(256) k_combine(float* __restrict__ Y) {
    __shared__ float red[8][CCH];
    int warp = threadIdx.x >> 5, lane = threadIdx.x & 31;
    float s[4] = {0.f, 0.f, 0.f, 0.f}, s2[4] = {0.f, 0.f, 0.f, 0.f};
    int vbase = blockIdx.x * 128 + warp * 16;
#pragma unroll 4
    for (int tt = 0; tt < 16; ++tt) {
        int v = vbase + tt;
        int myp = (lane < NK) ? g_pos[v * NK + lane] : -1;
        float4 acc = *(const float4*)(Y + (size_t)v * CCH + lane * 4);
#pragma unroll
        for (int k = 0; k < NK; ++k) {
            int sl = __shfl_sync(0xffffffffu, myp, k);
            if (sl >= 0) {
                float4 q = *(const float4*)(g_stage + (size_t)sl * CCH + lane * 4);
                acc.x += q.x; acc.y += q.y; acc.z += q.z; acc.w += q.w;
            }
        }
        *(float4*)(Y + (size_t)v * CCH + lane * 4) = acc;
        s[0] += acc.x; s[1] += acc.y; s[2] += acc.z; s[3] += acc.w;
        s2[0] += acc.x * acc.x; s2[1] += acc.y * acc.y;
        s2[2] += acc.z * acc.z; s2[3] += acc.w * acc.w;
    }
#pragma unroll
    for (int q = 0; q < 4; ++q) red[warp][lane * 4 + q] = s[q];
    __syncthreads();
    if (threadIdx.x < CCH) {
        float tot = 0.f;
#pragma unroll
        for (int w = 0; w < 8; ++w) tot += red[w][threadIdx.x];
        atomicAdd(&g_sum[threadIdx.x], tot);
    }
    __syncthreads();
#pragma unroll
    for (int q = 0; q < 4; ++q) red[warp][lane * 4 + q] = s2[q];
    __syncthreads();
    if (threadIdx.x < CCH) {
        float tot = 0.f;
#pragma unroll
        for (int w = 0; w < 8; ++w) tot += red[w][threadIdx.x];
        atomicAdd(&g_sumsq[threadIdx.x], tot);
    }
}

// ---------------- batchnorm finalize ----------------------------------------------
__global__ void k_finalize(const float* __restrict__ gma, const float* __restrict__ bta) {
    int c = threadIdx.x;
    float mu = g_sum[c] * (1.0f / N_VOX);
    float var = g_sumsq[c] * (1.0f / N_VOX) - mu * mu;
    float rs = rsqrtf(var + EPSF);
    float sc = gma[c] * rs;
    g_scale[c] = sc;
    g_shift[c] = bta[c] - mu * sc;
}

// ---------------- activations --------------------------------------------------------
__global__ void k_act_inner(const float* __restrict__ Y, float* __restrict__ R, int write_res) {
    int idx = blockIdx.x * blockDim.x + threadIdx.x;
    int c4 = (idx & 31) << 2;
    float4 y = *(const float4*)(Y + (size_t)idx * 4);
    float4 sc = *(const float4*)(g_scale + c4);
    float4 sh = *(const float4*)(g_shift + c4);
    float4 v;
    v.x = fmaf(y.x, sc.x, sh.x);
    v.y = fmaf(y.y, sc.y, sh.y);
    v.z = fmaf(y.z, sc.z, sh.z);
    v.w = fmaf(y.w, sc.w, sh.w);
    v.x = v.x >= 0.f ? v.x : SLOPE_IN * v.x;
    v.y = v.y >= 0.f ? v.y : SLOPE_IN * v.y;
    v.z = v.z >= 0.f ? v.z : SLOPE_IN * v.z;
    v.w = v.w >= 0.f ? v.w : SLOPE_IN * v.w;
    split_store4(idx, v);
    if (write_res) *(float4*)(R + (size_t)idx * 4) = v;
}

__global__ void k_act_out(const float* __restrict__ Y, const float* __restrict__ R,
                          float* __restrict__ O) {
    int idx = blockIdx.x * blockDim.x + threadIdx.x;
    int c4 = (idx & 31) << 2;
    float4 y = *(const float4*)(Y + (size_t)idx * 4);
    float4 r = *(const float4*)(R + (size_t)idx * 4);
    float4 sc = *(const float4*)(g_scale + c4);
    float4 sh = *(const float4*)(g_shift + c4);
    float4 v;
    v.x = fmaf(y.x, sc.x, sh.x) + r.x;
    v.y = fmaf(y.y, sc.y, sh.y) + r.y;
    v.z = fmaf(y.z, sc.z, sh.z) + r.z;
    v.w = fmaf(y.w, sc.w, sh.w) + r.w;
    v.x = v.x >= 0.f ? v.x : SLOPE_OUT * v.x;
    v.y = v.y >= 0.f ? v.y : SLOPE_OUT * v.y;
    v.z = v.z >= 0.f ? v.z : SLOPE_OUT * v.z;
    v.w = v.w >= 0.f ? v.w : SLOPE_OUT * v.w;
    *(float4*)(O + (size_t)idx * 4) = v;
}

// ---------------- launch ----------------------------------------------------------------
extern "C" void kernel_launch(void* const* d_in, const int* in_sizes, int n_in,
                              void* d_out, int out_size) {
    const float* feat = (const float*)d_in[0];
    const int*   nbr  = (const int*)d_in[1];
    const float* w1   = (const float*)d_in[2];
    const float* w2   = (const float*)d_in[3];
    const float* w3   = (const float*)d_in[4];
    const float* g1   = (const float*)d_in[5];
    const float* b1   = (const float*)d_in[6];
    const float* g2   = (const float*)d_in[7];
    const float* b2   = (const float*)d_in[8];
    const float* g3   = (const float*)d_in[9];
    const float* b3   = (const float*)d_in[10];
    float* out = (float*)d_out;

    float *p_y, *p_res, *p_stage;
    __half *p_xh, *p_xl, *p_wh, *p_wl;
    cudaGetSymbolAddress((void**)&p_y, g_y);
    cudaGetSymbolAddress((void**)&p_res, g_res);
    cudaGetSymbolAddress((void**)&p_stage, g_stage);
    cudaGetSymbolAddress((void**)&p_xh, g_xh);
    cudaGetSymbolAddress((void**)&p_xl, g_xl);
    cudaGetSymbolAddress((void**)&p_wh, g_wh);
    cudaGetSymbolAddress((void**)&p_wl, g_wl);

    cudaFuncSetAttribute(conv_mma, cudaFuncAttributeMaxDynamicSharedMemorySize,
                         SMEM_BYTES);

    const int nelem4 = (N_VOX * CCH) / 4;
    const int act_grid = nelem4 / 256;
    const int comb_grid = N_VOX / 128;         // 1024
    const int conv_grid = NK * TPK;            // 27648

    // rulebook + operand prep
    k_zero_cnt<<<1, 32>>>();
    k_count<<<(NK * N_VOX) / 256, 256>>>(nbr);
    k_scan<<<1, 1>>>();
    k_fill<<<(NK * N_VOX) / 256, 256>>>(nbr);
    {
        dim3 wg(WSZ / 256, 3);
        k_wsplit<<<wg, 256>>>(w1, w2, w3);
    }
    k_xsplit<<<act_grid, 256>>>(feat);

    // ---- layer 1 ----
    conv_mma<<<conv_grid, 256, SMEM_BYTES>>>(p_xh, p_xl, p_wh, p_wl, p_stage, p_y);
    k_combine<<<comb_grid, 256>>>(p_y);
    k_finalize<<<1, 128>>>(g1, b1);
    k_act_inner<<<act_grid, 256>>>(p_y, p_res, 1);

    // ---- layer 2 ----
    conv_mma<<<conv_grid, 256, SMEM_BYTES>>>(p_xh, p_xl, p_wh + WSZ, p_wl + WSZ, p_stage, p_y);
    k_combine<<<comb_grid, 256>>>(p_y);
    k_finalize<<<1, 128>>>(g2, b2);
    k_act_inner<<<act_grid, 256>>>(p_y, p_res, 0);

    // ---- layer 3 ----
    conv_mma<<<conv_grid, 256, SMEM_BYTES>>>(p_xh, p_xl, p_wh + 2 * WSZ, p_wl + 2 * WSZ, p_stage, p_y);
    k_combine<<<comb_grid, 256>>>(p_y);
    k_finalize<<<1, 128>>>(g3, b3);
    k_act_out<<<act_grid, 256>>>(p_y, p_res, out);
}

// round 7
// speedup vs baseline: 2.8607x; 1.0327x over previous
#include <cuda_runtime.h>
#include <cuda_fp16.h>
#include <cstdint>

#define N_VOX 131072
#define CCH 128
#define NK 27
#define TMROWS 128
#define TPK (N_VOX / TMROWS)       // 1024 tiles per offset
#define STAGE_ROWS (8 * N_VOX)
#define WSZ (NK * CCH * CCH)       // 442368
#define EPSF 1e-4f
#define SLOPE_IN 0.05f
#define SLOPE_OUT (1.0f / 3.0f)

// ---------------- scratch (device globals) ----------------------------------
__device__ float g_y[(size_t)N_VOX * CCH];
__device__ __half g_stage[(size_t)STAGE_ROWS * CCH];   // fp16 partial rows
__device__ __half g_xh0[(size_t)N_VOX * CCH];
__device__ __half g_xl0[(size_t)N_VOX * CCH];
__device__ __half g_xh1[(size_t)N_VOX * CCH];
__device__ __half g_xl1[(size_t)N_VOX * CCH];
__device__ __half g_wh[3 * WSZ];
__device__ __half g_wl[3 * WSZ];
__device__ int   g_pairs_j[STAGE_ROWS];
__device__ int   g_pos[N_VOX * NK];
__device__ int   g_cnt[NK];
__device__ int   g_off[NK];
__device__ int   g_cursor[NK];
__device__ float g_sum[CCH], g_sumsq[CCH];
__device__ float g_scale[CCH], g_shift[CCH];

// ---------------- rulebook ----------------------------------------------------
__global__ void k_zero_cnt() {
    if (threadIdx.x < NK) { g_cnt[threadIdx.x] = 0; g_cursor[threadIdx.x] = 0; }
}

__global__ void k_count(const int* __restrict__ nbr) {
    __shared__ int scnt;
    if (threadIdx.x == 0) scnt = 0;
    __syncthreads();
    int idx = blockIdx.x * 256 + threadIdx.x;
    int k = idx >> 17;
    int i = idx & (N_VOX - 1);
    int j = (k == 13) ? -1 : nbr[i * NK + k];
    unsigned m = __ballot_sync(0xffffffffu, j >= 0);
    if ((threadIdx.x & 31) == 0 && m) atomicAdd(&scnt, __popc(m));
    __syncthreads();
    if (threadIdx.x == 0 && scnt) atomicAdd(&g_cnt[k], scnt);
}

__global__ void k_scan() {
    int o = 0;
    for (int k = 0; k < NK; ++k) { g_off[k] = o; o += g_cnt[k]; }
}

__global__ void k_fill(const int* __restrict__ nbr) {
    __shared__ int woff[8];
    __shared__ int sbase;
    int idx = blockIdx.x * 256 + threadIdx.x;
    int k = idx >> 17;
    int i = idx & (N_VOX - 1);
    if (k == 13) { g_pos[i * NK + 13] = -1; return; }
    int j = nbr[i * NK + k];
    bool valid = (j >= 0);
    unsigned m = __ballot_sync(0xffffffffu, valid);
    int w = threadIdx.x >> 5, lane = threadIdx.x & 31;
    if (lane == 0) woff[w] = __popc(m);
    __syncthreads();
    if (threadIdx.x == 0) {
        int o = 0;
        for (int q = 0; q < 8; ++q) { int c = woff[q]; woff[q] = o; o += c; }
        sbase = o ? atomicAdd(&g_cursor[k], o) : 0;
    }
    __syncthreads();
    int pos = -1;
    if (valid) {
        pos = g_off[k] + sbase + woff[w] + __popc(m & ((1u << lane) - 1u));
        g_pairs_j[pos] = j;
    }
    g_pos[i * NK + k] = pos;
}

// ---------------- fp16 hi/lo splits --------------------------------------------
__global__ void k_wsplit(const float* __restrict__ w1, const float* __restrict__ w2,
                         const float* __restrict__ w3) {
    int i = blockIdx.x * blockDim.x + threadIdx.x;
    const float* src = (blockIdx.y == 0) ? w1 : (blockIdx.y == 1 ? w2 : w3);
    float v = src[i];
    __half h = __float2half(v);
    g_wh[blockIdx.y * WSZ + i] = h;
    g_wl[blockIdx.y * WSZ + i] = __float2half(v - __half2float(h));
}

__device__ __forceinline__ void split_store4(__half2* xh, __half2* xl, int idx, float4 v) {
    __half h0 = __float2half(v.x), h1 = __float2half(v.y);
    __half h2 = __float2half(v.z), h3 = __float2half(v.w);
    __half l0 = __float2half(v.x - __half2float(h0));
    __half l1 = __float2half(v.y - __half2float(h1));
    __half l2 = __float2half(v.z - __half2float(h2));
    __half l3 = __float2half(v.w - __half2float(h3));
    xh[idx * 2]     = __halves2half2(h0, h1);
    xh[idx * 2 + 1] = __halves2half2(h2, h3);
    xl[idx * 2]     = __halves2half2(l0, l1);
    xl[idx * 2 + 1] = __halves2half2(l2, l3);
}

__global__ void k_xsplit(const float* __restrict__ F, __half* XH, __half* XL) {
    int idx = blockIdx.x * blockDim.x + threadIdx.x;
    float4 v = *(const float4*)(F + (size_t)idx * 4);
    split_store4((__half2*)XH, (__half2*)XL, idx, v);
}

// ---------------- mma.sync helpers ----------------------------------------------
__device__ __forceinline__ void mma16816(float* d, const unsigned* a, const unsigned* b) {
    asm volatile(
        "mma.sync.aligned.m16n8k16.row.col.f32.f16.f16.f32 "
        "{%0,%1,%2,%3}, {%4,%5,%6,%7}, {%8,%9}, {%0,%1,%2,%3};"
        : "+f"(d[0]), "+f"(d[1]), "+f"(d[2]), "+f"(d[3])
        : "r"(a[0]), "r"(a[1]), "r"(a[2]), "r"(a[3]), "r"(b[0]), "r"(b[1]));
}

#define LDSM_X4(R, addr) asm volatile( \
    "ldmatrix.sync.aligned.m8n8.x4.shared.b16 {%0,%1,%2,%3}, [%4];" \
    : "=r"((R)[0]), "=r"((R)[1]), "=r"((R)[2]), "=r"((R)[3]) : "r"(addr))
#define LDSM_X4T(R, addr) asm volatile( \
    "ldmatrix.sync.aligned.m8n8.x4.trans.shared.b16 {%0,%1,%2,%3}, [%4];" \
    : "=r"((R)[0]), "=r"((R)[1]), "=r"((R)[2]), "=r"((R)[3]) : "r"(addr))

__device__ __forceinline__ void cp16(unsigned dst, const void* src, int srcsize) {
    asm volatile("cp.async.cg.shared.global [%0], [%1], 16, %2;"
                 :: "r"(dst), "l"(src), "r"(srcsize) : "memory");
}
#define CP_COMMIT() asm volatile("cp.async.commit_group;" ::: "memory")
#define CP_WAIT1() asm volatile("cp.async.wait_group 1;" ::: "memory")
#define CP_WAIT0() asm volatile("cp.async.wait_group 0;" ::: "memory")

// ---------------- SMEM layout (dynamic, bytes; 256B rows, XOR-swizzled) ----------
#define SM_AH 0
#define SM_AL 32768
#define SM_BB 65536            // + stage*16384 + hl*8192
#define SM_SJ 114688
#define SMEM_BYTES 115200

__device__ __forceinline__ unsigned swz(int row, int g) {
    return (unsigned)(row * 256 + ((g ^ (row & 7)) << 4));
}

// One launch covers all 27 offsets: blockIdx.x = k*1024 + tile.
__global__ void __launch_bounds__(256, 2) conv_mma(
    const __half* __restrict__ Xh, const __half* __restrict__ Xl,
    const __half* __restrict__ Wh, const __half* __restrict__ Wl,
    __half* __restrict__ Ystage, float* __restrict__ Yself)
{
    extern __shared__ char dsm[];
    unsigned sb = (unsigned)__cvta_generic_to_shared(dsm);
    int tid = threadIdx.x;
    int k = blockIdx.x >> 10;
    int t = blockIdx.x & (TPK - 1);
    int m0 = t * TMROWS;

    // zero BN accumulators for the following combine pass (one block does it)
    if (blockIdx.x == 13 * 1024 && tid < CCH) {
        g_sum[tid] = 0.f;
        g_sumsq[tid] = 0.f;
    }

    int cnt, obase;
    if (k == 13) {
        cnt = N_VOX; obase = m0;
    } else {
        cnt = g_cnt[k];
        if (m0 >= cnt) return;
        obase = g_off[k] + m0;
    }
    int rows = min(TMROWS, cnt - m0);
    const __half* Whk = Wh + k * CCH * CCH;
    const __half* Wlk = Wl + k * CCH * CCH;

    // ---- issue B chunks 0 and 1 (stages 0,1) ----
#pragma unroll
    for (int c = 0; c < 2; ++c) {
#pragma unroll
        for (int it = 0; it < 4; ++it) {
            int u = it * 256 + tid;
            int hl = u >> 9;
            int rem = u & 511;
            int row = rem >> 4;
            int seg = rem & 15;
            const __half* src = (hl ? Wlk : Whk) + (size_t)(c * 32 + row) * CCH + seg * 8;
            cp16(sb + SM_BB + c * 16384 + hl * 8192 + swz(row, seg), src, 16);
        }
        CP_COMMIT();
    }

    int* sj = (int*)(dsm + SM_SJ);
    if (tid < TMROWS) {
        int j = -1;
        if (tid < rows) j = (k == 13) ? (m0 + tid) : g_pairs_j[obase + tid];
        sj[tid] = j;
    }
    __syncthreads();

    // ---- issue full A (hi+lo), zero-fill invalid rows ----
    {
#pragma unroll
        for (int it = 0; it < 16; ++it) {
            int u = it * 256 + tid;
            int hl = u >> 11;
            int rem = u & 2047;
            int row = rem >> 4;
            int seg = rem & 15;
            int j = sj[row];
            const __half* src = (hl ? Xl : Xh) + (size_t)max(j, 0) * CCH + seg * 8;
            cp16(sb + (hl ? SM_AL : SM_AH) + swz(row, seg), src, j >= 0 ? 16 : 0);
        }
        CP_COMMIT();
    }

    int lane = tid & 31, warp = tid >> 5;
    int wm = warp & 3, wn = warp >> 2;
    int arow = wm * 32 + (lane & 15);
    int brow = lane & 15;
    int gsel = lane >> 4;

    float acc[2][8][4];
#pragma unroll
    for (int mi = 0; mi < 2; ++mi)
#pragma unroll
        for (int ni = 0; ni < 8; ++ni)
#pragma unroll
            for (int q = 0; q < 4; ++q) acc[mi][ni][q] = 0.f;

#pragma unroll
    for (int kc = 0; kc < 4; ++kc) {
        if (kc == 0) {
            CP_WAIT0();        // B0, B1, A all complete
        } else if (kc == 2) {
            CP_WAIT1();        // B2 complete
        } else if (kc == 3) {
            CP_WAIT0();        // B3 complete
        }
        __syncthreads();
        if (kc < 2) {          // prefetch chunk kc+2 into stage (kc+2)%3
            int c = kc + 2;
            int s = c % 3;
#pragma unroll
            for (int it = 0; it < 4; ++it) {
                int u = it * 256 + tid;
                int hl = u >> 9;
                int rem = u & 511;
                int row = rem >> 4;
                int seg = rem & 15;
                const __half* src = (hl ? Wlk : Whk) + (size_t)(c * 32 + row) * CCH + seg * 8;
                cp16(sb + SM_BB + s * 16384 + hl * 8192 + swz(row, seg), src, 16);
            }
            CP_COMMIT();
        }
        unsigned bb = sb + SM_BB + (kc % 3) * 16384;
#pragma unroll
        for (int kk = 0; kk < 2; ++kk) {
            unsigned ahf[2][4], alf[2][4];
            int gA = kc * 4 + kk * 2 + gsel;
#pragma unroll
            for (int mi = 0; mi < 2; ++mi) {
                int R = arow + mi * 16;
                unsigned off = swz(R, gA);
                LDSM_X4(ahf[mi], sb + SM_AH + off);
                LDSM_X4(alf[mi], sb + SM_AL + off);
            }
            int rB = kk * 16 + brow;
#pragma unroll
            for (int n2 = 0; n2 < 4; ++n2) {
                int gB = wn * 8 + n2 * 2 + gsel;
                unsigned boff = swz(rB, gB);
                unsigned bhf[4], blf[4];
                LDSM_X4T(bhf, bb + boff);
                LDSM_X4T(blf, bb + 8192 + boff);
#pragma unroll
                for (int mi = 0; mi < 2; ++mi) {
                    mma16816(acc[mi][n2 * 2],     ahf[mi], bhf);
                    mma16816(acc[mi][n2 * 2],     ahf[mi], blf);
                    mma16816(acc[mi][n2 * 2],     alf[mi], bhf);
                    mma16816(acc[mi][n2 * 2 + 1], ahf[mi], bhf + 2);
                    mma16816(acc[mi][n2 * 2 + 1], ahf[mi], blf + 2);
                    mma16816(acc[mi][n2 * 2 + 1], alf[mi], bhf + 2);
                }
            }
        }
    }

    // ---- epilogue: self -> fp32 g_y, pairs -> fp16 stage ----
    int gr = lane >> 2, gc = (lane & 3) * 2;
    if (k == 13) {
#pragma unroll
        for (int mi = 0; mi < 2; ++mi)
#pragma unroll
            for (int ni = 0; ni < 8; ++ni) {
                int c = wn * 64 + ni * 8 + gc;
                int r0 = wm * 32 + mi * 16 + gr;
                *(float2*)(Yself + (size_t)(obase + r0) * CCH + c) =
                    make_float2(acc[mi][ni][0], acc[mi][ni][1]);
                int r1 = r0 + 8;
                *(float2*)(Yself + (size_t)(obase + r1) * CCH + c) =
                    make_float2(acc[mi][ni][2], acc[mi][ni][3]);
            }
    } else {
#pragma unroll
        for (int mi = 0; mi < 2; ++mi)
#pragma unroll
            for (int ni = 0; ni < 8; ++ni) {
                int c = wn * 64 + ni * 8 + gc;
                int r0 = wm * 32 + mi * 16 + gr;
                if (r0 < rows)
                    *(__half2*)(Ystage + (size_t)(obase + r0) * CCH + c) =
                        __floats2half2_rn(acc[mi][ni][0], acc[mi][ni][1]);
                int r1 = r0 + 8;
                if (r1 < rows)
                    *(__half2*)(Ystage + (size_t)(obase + r1) * CCH + c) =
                        __floats2half2_rn(acc[mi][ni][2], acc[mi][ni][3]);
            }
    }
}

// ---------------- combine staged rows into g_y + BN stats -----------------------
__global__ void __launch_bounds__(256) k_combine(float* __restrict__ Y) {
    __shared__ float red[8][CCH];
    int warp = threadIdx.x >> 5, lane = threadIdx.x & 31;
    float s[4] = {0.f, 0.f, 0.f, 0.f}, s2[4] = {0.f, 0.f, 0.f, 0.f};
    int vbase = blockIdx.x * 128 + warp * 16;
#pragma unroll 4
    for (int tt = 0; tt < 16; ++tt) {
        int v = vbase + tt;
        int myp = (lane < NK) ? g_pos[v * NK + lane] : -1;
        float4 acc = *(const float4*)(Y + (size_t)v * CCH + lane * 4);
#pragma unroll
        for (int k = 0; k < NK; ++k) {
            int sl = __shfl_sync(0xffffffffu, myp, k);
            if (sl >= 0) {
                const __half2* q = (const __half2*)(g_stage + (size_t)sl * CCH + lane * 4);
                float2 a = __half22float2(q[0]);
                float2 b = __half22float2(q[1]);
                acc.x += a.x; acc.y += a.y; acc.z += b.x; acc.w += b.y;
            }
        }
        *(float4*)(Y + (size_t)v * CCH + lane * 4) = acc;
        s[0] += acc.x; s[1] += acc.y; s[2] += acc.z; s[3] += acc.w;
        s2[0] += acc.x * acc.x; s2[1] += acc.y * acc.y;
        s2[2] += acc.z * acc.z; s2[3] += acc.w * acc.w;
    }
#pragma unroll
    for (int q = 0; q < 4; ++q) red[warp][lane * 4 + q] = s[q];
    __syncthreads();
    if (threadIdx.x < CCH) {
        float tot = 0.f;
#pragma unroll
        for (int w = 0; w < 8; ++w) tot += red[w][threadIdx.x];
        atomicAdd(&g_sum[threadIdx.x], tot);
    }
    __syncthreads();
#pragma unroll
    for (int q = 0; q < 4; ++q) red[warp][lane * 4 + q] = s2[q];
    __syncthreads();
    if (threadIdx.x < CCH) {
        float tot = 0.f;
#pragma unroll
        for (int w = 0; w < 8; ++w) tot += red[w][threadIdx.x];
        atomicAdd(&g_sumsq[threadIdx.x], tot);
    }
}

// ---------------- batchnorm finalize ----------------------------------------------
__global__ void k_finalize(const float* __restrict__ gma, const float* __restrict__ bta) {
    int c = threadIdx.x;
    float mu = g_sum[c] * (1.0f / N_VOX);
    float var = g_sumsq[c] * (1.0f / N_VOX) - mu * mu;
    float rs = rsqrtf(var + EPSF);
    float sc = gma[c] * rs;
    g_scale[c] = sc;
    g_shift[c] = bta[c] - mu * sc;
}

// ---------------- activations --------------------------------------------------------
__global__ void k_act_inner(const float* __restrict__ Y, __half* __restrict__ XH,
                            __half* __restrict__ XL) {
    int idx = blockIdx.x * blockDim.x + threadIdx.x;
    int c4 = (idx & 31) << 2;
    float4 y = *(const float4*)(Y + (size_t)idx * 4);
    float4 sc = *(const float4*)(g_scale + c4);
    float4 sh = *(const float4*)(g_shift + c4);
    float4 v;
    v.x = fmaf(y.x, sc.x, sh.x);
    v.y = fmaf(y.y, sc.y, sh.y);
    v.z = fmaf(y.z, sc.z, sh.z);
    v.w = fmaf(y.w, sc.w, sh.w);
    v.x = v.x >= 0.f ? v.x : SLOPE_IN * v.x;
    v.y = v.y >= 0.f ? v.y : SLOPE_IN * v.y;
    v.z = v.z >= 0.f ? v.z : SLOPE_IN * v.z;
    v.w = v.w >= 0.f ? v.w : SLOPE_IN * v.w;
    split_store4((__half2*)XH, (__half2*)XL, idx, v);
}

__global__ void k_act_out(const float* __restrict__ Y, const __half* __restrict__ RH,
                          const __half* __restrict__ RL, float* __restrict__ O) {
    int idx = blockIdx.x * blockDim.x + threadIdx.x;
    int c4 = (idx & 31) << 2;
    float4 y = *(const float4*)(Y + (size_t)idx * 4);
    const __half2* rh = (const __half2*)(RH + (size_t)idx * 4);
    const __half2* rl = (const __half2*)(RL + (size_t)idx * 4);
    float2 rh0 = __half22float2(rh[0]), rh1 = __half22float2(rh[1]);
    float2 rl0 = __half22float2(rl[0]), rl1 = __half22float2(rl[1]);
    float4 sc = *(const float4*)(g_scale + c4);
    float4 sh = *(const float4*)(g_shift + c4);
    float4 v;
    v.x = fmaf(y.x, sc.x, sh.x) + (rh0.x + rl0.x);
    v.y = fmaf(y.y, sc.y, sh.y) + (rh0.y + rl0.y);
    v.z = fmaf(y.z, sc.z, sh.z) + (rh1.x + rl1.x);
    v.w = fmaf(y.w, sc.w, sh.w) + (rh1.y + rl1.y);
    v.x = v.x >= 0.f ? v.x : SLOPE_OUT * v.x;
    v.y = v.y >= 0.f ? v.y : SLOPE_OUT * v.y;
    v.z = v.z >= 0.f ? v.z : SLOPE_OUT * v.z;
    v.w = v.w >= 0.f ? v.w : SLOPE_OUT * v.w;
    *(float4*)(O + (size_t)idx * 4) = v;
}

// ---------------- launch ----------------------------------------------------------------
extern "C" void kernel_launch(void* const* d_in, const int* in_sizes, int n_in,
                              void* d_out, int out_size) {
    const float* feat = (const float*)d_in[0];
    const int*   nbr  = (const int*)d_in[1];
    const float* w1   = (const float*)d_in[2];
    const float* w2   = (const float*)d_in[3];
    const float* w3   = (const float*)d_in[4];
    const float* g1   = (const float*)d_in[5];
    const float* b1   = (const float*)d_in[6];
    const float* g2   = (const float*)d_in[7];
    const float* b2   = (const float*)d_in[8];
    const float* g3   = (const float*)d_in[9];
    const float* b3   = (const float*)d_in[10];
    float* out = (float*)d_out;

    float *p_y;
    __half *p_stage, *p_xh0, *p_xl0, *p_xh1, *p_xl1, *p_wh, *p_wl;
    cudaGetSymbolAddress((void**)&p_y, g_y);
    cudaGetSymbolAddress((void**)&p_stage, g_stage);
    cudaGetSymbolAddress((void**)&p_xh0, g_xh0);
    cudaGetSymbolAddress((void**)&p_xl0, g_xl0);
    cudaGetSymbolAddress((void**)&p_xh1, g_xh1);
    cudaGetSymbolAddress((void**)&p_xl1, g_xl1);
    cudaGetSymbolAddress((void**)&p_wh, g_wh);
    cudaGetSymbolAddress((void**)&p_wl, g_wl);

    cudaFuncSetAttribute(conv_mma, cudaFuncAttributeMaxDynamicSharedMemorySize,
                         SMEM_BYTES);

    const int nelem4 = (N_VOX * CCH) / 4;
    const int act_grid = nelem4 / 256;
    const int comb_grid = N_VOX / 128;         // 1024
    const int conv_grid = NK * TPK;            // 27648

    // rulebook + operand prep
    k_zero_cnt<<<1, 32>>>();
    k_count<<<(NK * N_VOX) / 256, 256>>>(nbr);
    k_scan<<<1, 1>>>();
    k_fill<<<(NK * N_VOX) / 256, 256>>>(nbr);
    {
        dim3 wg(WSZ / 256, 3);
        k_wsplit<<<wg, 256>>>(w1, w2, w3);
    }
    k_xsplit<<<act_grid, 256>>>(feat, p_xh0, p_xl0);

    // ---- layer 1 ----
    conv_mma<<<conv_grid, 256, SMEM_BYTES>>>(p_xh0, p_xl0, p_wh, p_wl, p_stage, p_y);
    k_combine<<<comb_grid, 256>>>(p_y);
    k_finalize<<<1, 128>>>(g1, b1);
    k_act_inner<<<act_grid, 256>>>(p_y, p_xh1, p_xl1);   // layer1 act = residual

    // ---- layer 2 ----
    conv_mma<<<conv_grid, 256, SMEM_BYTES>>>(p_xh1, p_xl1, p_wh + WSZ, p_wl + WSZ, p_stage, p_y);
    k_combine<<<comb_grid, 256>>>(p_y);
    k_finalize<<<1, 128>>>(g2, b2);
    k_act_inner<<<act_grid, 256>>>(p_y, p_xh0, p_xl0);   // ping-pong

    // ---- layer 3 ----
    conv_mma<<<conv_grid, 256, SMEM_BYTES>>>(p_xh0, p_xl0, p_wh + 2 * WSZ, p_wl + 2 * WSZ, p_stage, p_y);
    k_combine<<<comb_grid, 256>>>(p_y);
    k_finalize<<<1, 128>>>(g3, b3);
    k_act_out<<<act_grid, 256>>>(p_y, p_xh1, p_xl1, out);
}

// round 8
// speedup vs baseline: 3.2555x; 1.1380x over previous
#include <cuda_runtime.h>
#include <cuda_fp16.h>
#include <cstdint>

#define N_VOX 131072
#define CCH 128
#define NK 27
#define TMROWS 128
#define TPK (N_VOX / TMROWS)       // 1024 tiles per offset
#define KCAP 49152                 // fixed region per offset (>= max pair count)
#define WSZ (NK * CCH * CCH)       // 442368
#define EPSF 1e-4f
#define SLOPE_IN 0.05f
#define SLOPE_OUT (1.0f / 3.0f)

// ---------------- scratch (device globals) ----------------------------------
__device__ float g_y[(size_t)N_VOX * CCH];
__device__ __half g_stage[(size_t)NK * KCAP * CCH];    // fp16 partial rows
__device__ __half g_xh0[(size_t)N_VOX * CCH];
__device__ __half g_xl0[(size_t)N_VOX * CCH];
__device__ __half g_xh1[(size_t)N_VOX * CCH];
__device__ __half g_xl1[(size_t)N_VOX * CCH];
__device__ __half g_wh[3 * WSZ];
__device__ __half g_wl[3 * WSZ];
__device__ int   g_pairs_j[NK * KCAP];
__device__ int   g_vlist[(size_t)N_VOX * 26];          // per-voxel slot list
__device__ int   g_deg[N_VOX];
__device__ int   g_cnt[NK];
__device__ float g_sum[CCH], g_sumsq[CCH];

// ---------------- rulebook ----------------------------------------------------
__global__ void k_zero() {
    int i = blockIdx.x * 256 + threadIdx.x;
    if (i < N_VOX) g_deg[i] = 0;
    if (i < NK) g_cnt[i] = 0;
}

// idx = k*N + i ; k uniform per 256-thread block
__global__ void k_fill(const int* __restrict__ nbr) {
    __shared__ int woff[8];
    __shared__ int sbase;
    int idx = blockIdx.x * 256 + threadIdx.x;
    int k = idx >> 17;
    int i = idx & (N_VOX - 1);
    if (k == 13) return;
    int j = nbr[i * NK + k];
    bool valid = (j >= 0);
    unsigned m = __ballot_sync(0xffffffffu, valid);
    int w = threadIdx.x >> 5, lane = threadIdx.x & 31;
    if (lane == 0) woff[w] = __popc(m);
    __syncthreads();
    if (threadIdx.x == 0) {
        int o = 0;
        for (int q = 0; q < 8; ++q) { int c = woff[q]; woff[q] = o; o += c; }
        sbase = o ? atomicAdd(&g_cnt[k], o) : 0;
    }
    __syncthreads();
    if (valid) {
        int pos = k * KCAP + sbase + woff[w] + __popc(m & ((1u << lane) - 1u));
        g_pairs_j[pos] = j;
        int d = atomicAdd(&g_deg[i], 1);
        g_vlist[(size_t)i * 26 + d] = pos;
    }
}

// ---------------- fp16 hi/lo splits --------------------------------------------
__global__ void k_wsplit(const float* __restrict__ w1, const float* __restrict__ w2,
                         const float* __restrict__ w3) {
    int i = blockIdx.x * blockDim.x + threadIdx.x;
    const float* src = (blockIdx.y == 0) ? w1 : (blockIdx.y == 1 ? w2 : w3);
    float v = src[i];
    __half h = __float2half(v);
    g_wh[blockIdx.y * WSZ + i] = h;
    g_wl[blockIdx.y * WSZ + i] = __float2half(v - __half2float(h));
}

__device__ __forceinline__ void split_store4(__half2* xh, __half2* xl, int idx, float4 v) {
    __half h0 = __float2half(v.x), h1 = __float2half(v.y);
    __half h2 = __float2half(v.z), h3 = __float2half(v.w);
    __half l0 = __float2half(v.x - __half2float(h0));
    __half l1 = __float2half(v.y - __half2float(h1));
    __half l2 = __float2half(v.z - __half2float(h2));
    __half l3 = __float2half(v.w - __half2float(h3));
    xh[idx * 2]     = __halves2half2(h0, h1);
    xh[idx * 2 + 1] = __halves2half2(h2, h3);
    xl[idx * 2]     = __halves2half2(l0, l1);
    xl[idx * 2 + 1] = __halves2half2(l2, l3);
}

__global__ void k_xsplit(const float* __restrict__ F, __half* XH, __half* XL) {
    int idx = blockIdx.x * blockDim.x + threadIdx.x;
    float4 v = *(const float4*)(F + (size_t)idx * 4);
    split_store4((__half2*)XH, (__half2*)XL, idx, v);
}

// ---------------- mma.sync helpers ----------------------------------------------
__device__ __forceinline__ void mma16816(float* d, const unsigned* a, const unsigned* b) {
    asm volatile(
        "mma.sync.aligned.m16n8k16.row.col.f32.f16.f16.f32 "
        "{%0,%1,%2,%3}, {%4,%5,%6,%7}, {%8,%9}, {%0,%1,%2,%3};"
        : "+f"(d[0]), "+f"(d[1]), "+f"(d[2]), "+f"(d[3])
        : "r"(a[0]), "r"(a[1]), "r"(a[2]), "r"(a[3]), "r"(b[0]), "r"(b[1]));
}

#define LDSM_X4(R, addr) asm volatile( \
    "ldmatrix.sync.aligned.m8n8.x4.shared.b16 {%0,%1,%2,%3}, [%4];" \
    : "=r"((R)[0]), "=r"((R)[1]), "=r"((R)[2]), "=r"((R)[3]) : "r"(addr))
#define LDSM_X4T(R, addr) asm volatile( \
    "ldmatrix.sync.aligned.m8n8.x4.trans.shared.b16 {%0,%1,%2,%3}, [%4];" \
    : "=r"((R)[0]), "=r"((R)[1]), "=r"((R)[2]), "=r"((R)[3]) : "r"(addr))

__device__ __forceinline__ void cp16(unsigned dst, const void* src, int srcsize) {
    asm volatile("cp.async.cg.shared.global [%0], [%1], 16, %2;"
                 :: "r"(dst), "l"(src), "r"(srcsize) : "memory");
}
#define CP_COMMIT() asm volatile("cp.async.commit_group;" ::: "memory")
#define CP_WAIT1() asm volatile("cp.async.wait_group 1;" ::: "memory")
#define CP_WAIT0() asm volatile("cp.async.wait_group 0;" ::: "memory")

// ---------------- SMEM layout (dynamic, bytes; 256B rows, XOR-swizzled) ----------
#define SM_AH 0
#define SM_AL 32768
#define SM_BB 65536            // + stage*16384 + hl*8192
#define SM_SJ 114688
#define SMEM_BYTES 115200

__device__ __forceinline__ unsigned swz(int row, int g) {
    return (unsigned)(row * 256 + ((g ^ (row & 7)) << 4));
}

// One launch covers all 27 offsets: blockIdx.x = k*1024 + tile.
__global__ void __launch_bounds__(256, 2) conv_mma(
    const __half* __restrict__ Xh, const __half* __restrict__ Xl,
    const __half* __restrict__ Wh, const __half* __restrict__ Wl,
    __half* __restrict__ Ystage, float* __restrict__ Yself)
{
    extern __shared__ char dsm[];
    unsigned sb = (unsigned)__cvta_generic_to_shared(dsm);
    int tid = threadIdx.x;
    int k = blockIdx.x >> 10;
    int t = blockIdx.x & (TPK - 1);
    int m0 = t * TMROWS;

    // zero BN accumulators for the following combine pass (one block does it)
    if (blockIdx.x == 13 * 1024 && tid < CCH) {
        g_sum[tid] = 0.f;
        g_sumsq[tid] = 0.f;
    }

    int cnt, obase;
    if (k == 13) {
        cnt = N_VOX; obase = m0;
    } else {
        cnt = g_cnt[k];
        if (m0 >= cnt) return;
        obase = k * KCAP + m0;
    }
    int rows = min(TMROWS, cnt - m0);
    const __half* Whk = Wh + k * CCH * CCH;
    const __half* Wlk = Wl + k * CCH * CCH;

    // ---- issue B chunks 0 and 1 (stages 0,1) ----
#pragma unroll
    for (int c = 0; c < 2; ++c) {
#pragma unroll
        for (int it = 0; it < 4; ++it) {
            int u = it * 256 + tid;
            int hl = u >> 9;
            int rem = u & 511;
            int row = rem >> 4;
            int seg = rem & 15;
            const __half* src = (hl ? Wlk : Whk) + (size_t)(c * 32 + row) * CCH + seg * 8;
            cp16(sb + SM_BB + c * 16384 + hl * 8192 + swz(row, seg), src, 16);
        }
        CP_COMMIT();
    }

    int* sj = (int*)(dsm + SM_SJ);
    if (tid < TMROWS) {
        int j = -1;
        if (tid < rows) j = (k == 13) ? (m0 + tid) : g_pairs_j[obase + tid];
        sj[tid] = j;
    }
    __syncthreads();

    // ---- issue full A (hi+lo), zero-fill invalid rows ----
    {
#pragma unroll
        for (int it = 0; it < 16; ++it) {
            int u = it * 256 + tid;
            int hl = u >> 11;
            int rem = u & 2047;
            int row = rem >> 4;
            int seg = rem & 15;
            int j = sj[row];
            const __half* src = (hl ? Xl : Xh) + (size_t)max(j, 0) * CCH + seg * 8;
            cp16(sb + (hl ? SM_AL : SM_AH) + swz(row, seg), src, j >= 0 ? 16 : 0);
        }
        CP_COMMIT();
    }

    int lane = tid & 31, warp = tid >> 5;
    int wm = warp & 3, wn = warp >> 2;
    int arow = wm * 32 + (lane & 15);
    int brow = lane & 15;
    int gsel = lane >> 4;

    float acc[2][8][4];
#pragma unroll
    for (int mi = 0; mi < 2; ++mi)
#pragma unroll
        for (int ni = 0; ni < 8; ++ni)
#pragma unroll
            for (int q = 0; q < 4; ++q) acc[mi][ni][q] = 0.f;

#pragma unroll
    for (int kc = 0; kc < 4; ++kc) {
        if (kc == 0) {
            CP_WAIT0();
        } else if (kc == 2) {
            CP_WAIT1();
        } else if (kc == 3) {
            CP_WAIT0();
        }
        __syncthreads();
        if (kc < 2) {          // prefetch chunk kc+2 into stage (kc+2)%3
            int c = kc + 2;
            int s = c % 3;
#pragma unroll
            for (int it = 0; it < 4; ++it) {
                int u = it * 256 + tid;
                int hl = u >> 9;
                int rem = u & 511;
                int row = rem >> 4;
                int seg = rem & 15;
                const __half* src = (hl ? Wlk : Whk) + (size_t)(c * 32 + row) * CCH + seg * 8;
                cp16(sb + SM_BB + s * 16384 + hl * 8192 + swz(row, seg), src, 16);
            }
            CP_COMMIT();
        }
        unsigned bb = sb + SM_BB + (kc % 3) * 16384;
#pragma unroll
        for (int kk = 0; kk < 2; ++kk) {
            unsigned ahf[2][4], alf[2][4];
            int gA = kc * 4 + kk * 2 + gsel;
#pragma unroll
            for (int mi = 0; mi < 2; ++mi) {
                int R = arow + mi * 16;
                unsigned off = swz(R, gA);
                LDSM_X4(ahf[mi], sb + SM_AH + off);
                LDSM_X4(alf[mi], sb + SM_AL + off);
            }
            int rB = kk * 16 + brow;
#pragma unroll
            for (int n2 = 0; n2 < 4; ++n2) {
                int gB = wn * 8 + n2 * 2 + gsel;
                unsigned boff = swz(rB, gB);
                unsigned bhf[4], blf[4];
                LDSM_X4T(bhf, bb + boff);
                LDSM_X4T(blf, bb + 8192 + boff);
#pragma unroll
                for (int mi = 0; mi < 2; ++mi) {
                    mma16816(acc[mi][n2 * 2],     ahf[mi], bhf);
                    mma16816(acc[mi][n2 * 2],     ahf[mi], blf);
                    mma16816(acc[mi][n2 * 2],     alf[mi], bhf);
                    mma16816(acc[mi][n2 * 2 + 1], ahf[mi], bhf + 2);
                    mma16816(acc[mi][n2 * 2 + 1], ahf[mi], blf + 2);
                    mma16816(acc[mi][n2 * 2 + 1], alf[mi], bhf + 2);
                }
            }
        }
    }

    // ---- epilogue: self -> fp32 g_y, pairs -> fp16 stage ----
    int gr = lane >> 2, gc = (lane & 3) * 2;
    if (k == 13) {
#pragma unroll
        for (int mi = 0; mi < 2; ++mi)
#pragma unroll
            for (int ni = 0; ni < 8; ++ni) {
                int c = wn * 64 + ni * 8 + gc;
                int r0 = wm * 32 + mi * 16 + gr;
                *(float2*)(Yself + (size_t)(obase + r0) * CCH + c) =
                    make_float2(acc[mi][ni][0], acc[mi][ni][1]);
                int r1 = r0 + 8;
                *(float2*)(Yself + (size_t)(obase + r1) * CCH + c) =
                    make_float2(acc[mi][ni][2], acc[mi][ni][3]);
            }
    } else {
#pragma unroll
        for (int mi = 0; mi < 2; ++mi)
#pragma unroll
            for (int ni = 0; ni < 8; ++ni) {
                int c = wn * 64 + ni * 8 + gc;
                int r0 = wm * 32 + mi * 16 + gr;
                if (r0 < rows)
                    *(__half2*)(Ystage + (size_t)(obase + r0) * CCH + c) =
                        __floats2half2_rn(acc[mi][ni][0], acc[mi][ni][1]);
                int r1 = r0 + 8;
                if (r1 < rows)
                    *(__half2*)(Ystage + (size_t)(obase + r1) * CCH + c) =
                        __floats2half2_rn(acc[mi][ni][2], acc[mi][ni][3]);
            }
    }
}

// ---------------- combine staged rows into g_y + BN stats -----------------------
__global__ void __launch_bounds__(256) k_combine(float* __restrict__ Y) {
    __shared__ float red[8][CCH];
    int warp = threadIdx.x >> 5, lane = threadIdx.x & 31;
    float s[4] = {0.f, 0.f, 0.f, 0.f}, s2[4] = {0.f, 0.f, 0.f, 0.f};
    int vbase = blockIdx.x * 128 + warp * 16;
    for (int tt = 0; tt < 16; ++tt) {
        int v = vbase + tt;
        int deg = g_deg[v];
        int myp = (lane < deg) ? g_vlist[(size_t)v * 26 + lane] : -1;
        float4 acc = *(const float4*)(Y + (size_t)v * CCH + lane * 4);
        for (int q = 0; q < deg; ++q) {
            int sl = __shfl_sync(0xffffffffu, myp, q);
            const __half2* p = (const __half2*)(g_stage + (size_t)sl * CCH + lane * 4);
            float2 a = __half22float2(p[0]);
            float2 b = __half22float2(p[1]);
            acc.x += a.x; acc.y += a.y; acc.z += b.x; acc.w += b.y;
        }
        *(float4*)(Y + (size_t)v * CCH + lane * 4) = acc;
        s[0] += acc.x; s[1] += acc.y; s[2] += acc.z; s[3] += acc.w;
        s2[0] += acc.x * acc.x; s2[1] += acc.y * acc.y;
        s2[2] += acc.z * acc.z; s2[3] += acc.w * acc.w;
    }
#pragma unroll
    for (int q = 0; q < 4; ++q) red[warp][lane * 4 + q] = s[q];
    __syncthreads();
    if (threadIdx.x < CCH) {
        float tot = 0.f;
#pragma unroll
        for (int w = 0; w < 8; ++w) tot += red[w][threadIdx.x];
        atomicAdd(&g_sum[threadIdx.x], tot);
    }
    __syncthreads();
#pragma unroll
    for (int q = 0; q < 4; ++q) red[warp][lane * 4 + q] = s2[q];
    __syncthreads();
    if (threadIdx.x < CCH) {
        float tot = 0.f;
#pragma unroll
        for (int w = 0; w < 8; ++w) tot += red[w][threadIdx.x];
        atomicAdd(&g_sumsq[threadIdx.x], tot);
    }
}

// ---------------- activations (BN finalize fused in-block) --------------------------
__global__ void k_act_inner(const float* __restrict__ Y,
                            const float* __restrict__ gma, const float* __restrict__ bta,
                            __half* __restrict__ XH, __half* __restrict__ XL) {
    __shared__ float ssc[CCH], ssh[CCH];
    if (threadIdx.x < CCH) {
        float mu = g_sum[threadIdx.x] * (1.0f / N_VOX);
        float var = g_sumsq[threadIdx.x] * (1.0f / N_VOX) - mu * mu;
        float rs = rsqrtf(var + EPSF);
        float sc = gma[threadIdx.x] * rs;
        ssc[threadIdx.x] = sc;
        ssh[threadIdx.x] = bta[threadIdx.x] - mu * sc;
    }
    __syncthreads();
    int idx = blockIdx.x * blockDim.x + threadIdx.x;
    int c4 = (idx & 31) << 2;
    float4 y = *(const float4*)(Y + (size_t)idx * 4);
    float4 sc = *(const float4*)(ssc + c4);
    float4 sh = *(const float4*)(ssh + c4);
    float4 v;
    v.x = fmaf(y.x, sc.x, sh.x);
    v.y = fmaf(y.y, sc.y, sh.y);
    v.z = fmaf(y.z, sc.z, sh.z);
    v.w = fmaf(y.w, sc.w, sh.w);
    v.x = v.x >= 0.f ? v.x : SLOPE_IN * v.x;
    v.y = v.y >= 0.f ? v.y : SLOPE_IN * v.y;
    v.z = v.z >= 0.f ? v.z : SLOPE_IN * v.z;
    v.w = v.w >= 0.f ? v.w : SLOPE_IN * v.w;
    split_store4((__half2*)XH, (__half2*)XL, idx, v);
}

__global__ void k_act_out(const float* __restrict__ Y,
                          const float* __restrict__ gma, const float* __restrict__ bta,
                          const __half* __restrict__ RH, const __half* __restrict__ RL,
                          float* __restrict__ O) {
    __shared__ float ssc[CCH], ssh[CCH];
    if (threadIdx.x < CCH) {
        float mu = g_sum[threadIdx.x] * (1.0f / N_VOX);
        float var = g_sumsq[threadIdx.x] * (1.0f / N_VOX) - mu * mu;
        float rs = rsqrtf(var + EPSF);
        float sc = gma[threadIdx.x] * rs;
        ssc[threadIdx.x] = sc;
        ssh[threadIdx.x] = bta[threadIdx.x] - mu * sc;
    }
    __syncthreads();
    int idx = blockIdx.x * blockDim.x + threadIdx.x;
    int c4 = (idx & 31) << 2;
    float4 y = *(const float4*)(Y + (size_t)idx * 4);
    const __half2* rh = (const __half2*)(RH + (size_t)idx * 4);
    const __half2* rl = (const __half2*)(RL + (size_t)idx * 4);
    float2 rh0 = __half22float2(rh[0]), rh1 = __half22float2(rh[1]);
    float2 rl0 = __half22float2(rl[0]), rl1 = __half22float2(rl[1]);
    float4 sc = *(const float4*)(ssc + c4);
    float4 sh = *(const float4*)(ssh + c4);
    float4 v;
    v.x = fmaf(y.x, sc.x, sh.x) + (rh0.x + rl0.x);
    v.y = fmaf(y.y, sc.y, sh.y) + (rh0.y + rl0.y);
    v.z = fmaf(y.z, sc.z, sh.z) + (rh1.x + rl1.x);
    v.w = fmaf(y.w, sc.w, sh.w) + (rh1.y + rl1.y);
    v.x = v.x >= 0.f ? v.x : SLOPE_OUT * v.x;
    v.y = v.y >= 0.f ? v.y : SLOPE_OUT * v.y;
    v.z = v.z >= 0.f ? v.z : SLOPE_OUT * v.z;
    v.w = v.w >= 0.f ? v.w : SLOPE_OUT * v.w;
    *(float4*)(O + (size_t)idx * 4) = v;
}

// ---------------- launch ----------------------------------------------------------------
extern "C" void kernel_launch(void* const* d_in, const int* in_sizes, int n_in,
                              void* d_out, int out_size) {
    const float* feat = (const float*)d_in[0];
    const int*   nbr  = (const int*)d_in[1];
    const float* w1   = (const float*)d_in[2];
    const float* w2   = (const float*)d_in[3];
    const float* w3   = (const float*)d_in[4];
    const float* g1   = (const float*)d_in[5];
    const float* b1   = (const float*)d_in[6];
    const float* g2   = (const float*)d_in[7];
    const float* b2   = (const float*)d_in[8];
    const float* g3   = (const float*)d_in[9];
    const float* b3   = (const float*)d_in[10];
    float* out = (float*)d_out;

    float *p_y;
    __half *p_stage, *p_xh0, *p_xl0, *p_xh1, *p_xl1, *p_wh, *p_wl;
    cudaGetSymbolAddress((void**)&p_y, g_y);
    cudaGetSymbolAddress((void**)&p_stage, g_stage);
    cudaGetSymbolAddress((void**)&p_xh0, g_xh0);
    cudaGetSymbolAddress((void**)&p_xl0, g_xl0);
    cudaGetSymbolAddress((void**)&p_xh1, g_xh1);
    cudaGetSymbolAddress((void**)&p_xl1, g_xl1);
    cudaGetSymbolAddress((void**)&p_wh, g_wh);
    cudaGetSymbolAddress((void**)&p_wl, g_wl);

    cudaFuncSetAttribute(conv_mma, cudaFuncAttributeMaxDynamicSharedMemorySize,
                         SMEM_BYTES);

    const int nelem4 = (N_VOX * CCH) / 4;
    const int act_grid = nelem4 / 256;
    const int comb_grid = N_VOX / 128;         // 1024
    const int conv_grid = NK * TPK;            // 27648

    // rulebook + operand prep
    k_zero<<<N_VOX / 256, 256>>>();
    k_fill<<<(NK * N_VOX) / 256, 256>>>(nbr);
    {
        dim3 wg(WSZ / 256, 3);
        k_wsplit<<<wg, 256>>>(w1, w2, w3);
    }
    k_xsplit<<<act_grid, 256>>>(feat, p_xh0, p_xl0);

    // ---- layer 1 ----
    conv_mma<<<conv_grid, 256, SMEM_BYTES>>>(p_xh0, p_xl0, p_wh, p_wl, p_stage, p_y);
    k_combine<<<comb_grid, 256>>>(p_y);
    k_act_inner<<<act_grid, 256>>>(p_y, g1, b1, p_xh1, p_xl1);   // layer1 act = residual

    // ---- layer 2 ----
    conv_mma<<<conv_grid, 256, SMEM_BYTES>>>(p_xh1, p_xl1, p_wh + WSZ, p_wl + WSZ, p_stage, p_y);
    k_combine<<<comb_grid, 256>>>(p_y);
    k_act_inner<<<act_grid, 256>>>(p_y, g2, b2, p_xh0, p_xl0);   // ping-pong

    // ---- layer 3 ----
    conv_mma<<<conv_grid, 256, SMEM_BYTES>>>(p_xh0, p_xl0, p_wh + 2 * WSZ, p_wl + 2 * WSZ, p_stage, p_y);
    k_combine<<<comb_grid, 256>>>(p_y);
    k_act_out<<<act_grid, 256>>>(p_y, g3, b3, p_xh1, p_xl1, out);
}

// round 9
// speedup vs baseline: 3.5025x; 1.0759x over previous
#include <cuda_runtime.h>
#include <cuda_fp16.h>
#include <cstdint>

#define N_VOX 131072
#define CCH 128
#define NK 27
#define TMROWS 128
#define TPK (N_VOX / TMROWS)       // 1024 tiles per offset
#define KCAP 49152                 // fixed region per offset (>= max pair count)
#define WSZ (NK * CCH * CCH)       // 442368
#define EPSF 1e-4f
#define SLOPE_IN 0.05f
#define SLOPE_OUT (1.0f / 3.0f)

// ---------------- scratch (device globals) ----------------------------------
__device__ float g_y[(size_t)N_VOX * CCH];
__device__ __half g_stage[(size_t)NK * KCAP * CCH];    // fp16 partial rows
__device__ __half g_xh0[(size_t)N_VOX * CCH];
__device__ __half g_xl0[(size_t)N_VOX * CCH];
__device__ __half g_xh1[(size_t)N_VOX * CCH];
__device__ __half g_xl1[(size_t)N_VOX * CCH];
__device__ __half g_wh[3 * WSZ];                       // fp16 weights (hi only)
__device__ int   g_pairs_j[NK * KCAP];
__device__ int   g_vlist[(size_t)N_VOX * 26];          // per-voxel slot list
__device__ int   g_deg[N_VOX];
__device__ int   g_cnt[NK];
__device__ float g_sum[CCH], g_sumsq[CCH];

// ---------------- rulebook ----------------------------------------------------
__global__ void k_zero() {
    int i = blockIdx.x * 256 + threadIdx.x;
    if (i < N_VOX) g_deg[i] = 0;
    if (i < NK) g_cnt[i] = 0;
}

// idx = k*N + i ; k uniform per 256-thread block
__global__ void k_fill(const int* __restrict__ nbr) {
    __shared__ int woff[8];
    __shared__ int sbase;
    int idx = blockIdx.x * 256 + threadIdx.x;
    int k = idx >> 17;
    int i = idx & (N_VOX - 1);
    if (k == 13) return;
    int j = nbr[i * NK + k];
    bool valid = (j >= 0);
    unsigned m = __ballot_sync(0xffffffffu, valid);
    int w = threadIdx.x >> 5, lane = threadIdx.x & 31;
    if (lane == 0) woff[w] = __popc(m);
    __syncthreads();
    if (threadIdx.x == 0) {
        int o = 0;
        for (int q = 0; q < 8; ++q) { int c = woff[q]; woff[q] = o; o += c; }
        sbase = o ? atomicAdd(&g_cnt[k], o) : 0;
    }
    __syncthreads();
    if (valid) {
        int pos = k * KCAP + sbase + woff[w] + __popc(m & ((1u << lane) - 1u));
        g_pairs_j[pos] = j;
        int d = atomicAdd(&g_deg[i], 1);
        g_vlist[(size_t)i * 26 + d] = pos;
    }
}

// ---------------- fp16 splits --------------------------------------------------
__global__ void k_wsplit(const float* __restrict__ w1, const float* __restrict__ w2,
                         const float* __restrict__ w3) {
    int i = blockIdx.x * blockDim.x + threadIdx.x;
    const float* src = (blockIdx.y == 0) ? w1 : (blockIdx.y == 1 ? w2 : w3);
    g_wh[blockIdx.y * WSZ + i] = __float2half(src[i]);
}

__device__ __forceinline__ void split_store4(__half2* xh, __half2* xl, int idx, float4 v) {
    __half h0 = __float2half(v.x), h1 = __float2half(v.y);
    __half h2 = __float2half(v.z), h3 = __float2half(v.w);
    __half l0 = __float2half(v.x - __half2float(h0));
    __half l1 = __float2half(v.y - __half2float(h1));
    __half l2 = __float2half(v.z - __half2float(h2));
    __half l3 = __float2half(v.w - __half2float(h3));
    xh[idx * 2]     = __halves2half2(h0, h1);
    xh[idx * 2 + 1] = __halves2half2(h2, h3);
    xl[idx * 2]     = __halves2half2(l0, l1);
    xl[idx * 2 + 1] = __halves2half2(l2, l3);
}

__global__ void k_xsplit(const float* __restrict__ F, __half* XH, __half* XL) {
    int idx = blockIdx.x * blockDim.x + threadIdx.x;
    float4 v = *(const float4*)(F + (size_t)idx * 4);
    split_store4((__half2*)XH, (__half2*)XL, idx, v);
}

// ---------------- mma.sync helpers ----------------------------------------------
__device__ __forceinline__ void mma16816(float* d, const unsigned* a, const unsigned* b) {
    asm volatile(
        "mma.sync.aligned.m16n8k16.row.col.f32.f16.f16.f32 "
        "{%0,%1,%2,%3}, {%4,%5,%6,%7}, {%8,%9}, {%0,%1,%2,%3};"
        : "+f"(d[0]), "+f"(d[1]), "+f"(d[2]), "+f"(d[3])
        : "r"(a[0]), "r"(a[1]), "r"(a[2]), "r"(a[3]), "r"(b[0]), "r"(b[1]));
}

#define LDSM_X4(R, addr) asm volatile( \
    "ldmatrix.sync.aligned.m8n8.x4.shared.b16 {%0,%1,%2,%3}, [%4];" \
    : "=r"((R)[0]), "=r"((R)[1]), "=r"((R)[2]), "=r"((R)[3]) : "r"(addr))
#define LDSM_X4T(R, addr) asm volatile( \
    "ldmatrix.sync.aligned.m8n8.x4.trans.shared.b16 {%0,%1,%2,%3}, [%4];" \
    : "=r"((R)[0]), "=r"((R)[1]), "=r"((R)[2]), "=r"((R)[3]) : "r"(addr))

__device__ __forceinline__ void cp16(unsigned dst, const void* src, int srcsize) {
    asm volatile("cp.async.cg.shared.global [%0], [%1], 16, %2;"
                 :: "r"(dst), "l"(src), "r"(srcsize) : "memory");
}
#define CP_COMMIT() asm volatile("cp.async.commit_group;" ::: "memory")
#define CP_WAIT1() asm volatile("cp.async.wait_group 1;" ::: "memory")
#define CP_WAIT0() asm volatile("cp.async.wait_group 0;" ::: "memory")

// ---------------- SMEM layout (dynamic, bytes; 256B rows, XOR-swizzled) ----------
// A: 128 rows x 128 halves, hi + lo.  B: 3 stages x 32 rows x 128 halves (hi only).
#define SM_AH 0
#define SM_AL 32768
#define SM_BB 65536            // + stage*8192
#define SM_SJ 90112
#define SMEM_BYTES 90624

__device__ __forceinline__ unsigned swz(int row, int g) {
    return (unsigned)(row * 256 + ((g ^ (row & 7)) << 4));
}

// One launch covers all 27 offsets: blockIdx.x = k*1024 + tile.
__global__ void __launch_bounds__(256, 2) conv_mma(
    const __half* __restrict__ Xh, const __half* __restrict__ Xl,
    const __half* __restrict__ Wh,
    __half* __restrict__ Ystage, float* __restrict__ Yself)
{
    extern __shared__ char dsm[];
    unsigned sb = (unsigned)__cvta_generic_to_shared(dsm);
    int tid = threadIdx.x;
    int k = blockIdx.x >> 10;
    int t = blockIdx.x & (TPK - 1);
    int m0 = t * TMROWS;

    // zero BN accumulators for the following combine pass (one block does it)
    if (blockIdx.x == 13 * 1024 && tid < CCH) {
        g_sum[tid] = 0.f;
        g_sumsq[tid] = 0.f;
    }

    int cnt, obase;
    if (k == 13) {
        cnt = N_VOX; obase = m0;
    } else {
        cnt = g_cnt[k];
        if (m0 >= cnt) return;
        obase = k * KCAP + m0;
    }
    int rows = min(TMROWS, cnt - m0);
    const __half* Whk = Wh + k * CCH * CCH;

    // ---- issue B chunks 0 and 1 (stages 0,1): 8 KB each = 2 iters of 256x16B ----
#pragma unroll
    for (int c = 0; c < 2; ++c) {
#pragma unroll
        for (int it = 0; it < 2; ++it) {
            int u = it * 256 + tid;
            int row = u >> 4;
            int seg = u & 15;
            const __half* src = Whk + (size_t)(c * 32 + row) * CCH + seg * 8;
            cp16(sb + SM_BB + c * 8192 + swz(row, seg), src, 16);
        }
        CP_COMMIT();
    }

    int* sj = (int*)(dsm + SM_SJ);
    if (tid < TMROWS) {
        int j = -1;
        if (tid < rows) j = (k == 13) ? (m0 + tid) : g_pairs_j[obase + tid];
        sj[tid] = j;
    }
    __syncthreads();

    // ---- issue full A (hi+lo), zero-fill invalid rows ----
    {
#pragma unroll
        for (int it = 0; it < 16; ++it) {
            int u = it * 256 + tid;
            int hl = u >> 11;
            int rem = u & 2047;
            int row = rem >> 4;
            int seg = rem & 15;
            int j = sj[row];
            const __half* src = (hl ? Xl : Xh) + (size_t)max(j, 0) * CCH + seg * 8;
            cp16(sb + (hl ? SM_AL : SM_AH) + swz(row, seg), src, j >= 0 ? 16 : 0);
        }
        CP_COMMIT();
    }

    int lane = tid & 31, warp = tid >> 5;
    int wm = warp & 3, wn = warp >> 2;
    int arow = wm * 32 + (lane & 15);
    int brow = lane & 15;
    int gsel = lane >> 4;

    float acc[2][8][4];
#pragma unroll
    for (int mi = 0; mi < 2; ++mi)
#pragma unroll
        for (int ni = 0; ni < 8; ++ni)
#pragma unroll
            for (int q = 0; q < 4; ++q) acc[mi][ni][q] = 0.f;

#pragma unroll
    for (int kc = 0; kc < 4; ++kc) {
        if (kc == 0) {
            CP_WAIT0();
        } else if (kc == 2) {
            CP_WAIT1();
        } else if (kc == 3) {
            CP_WAIT0();
        }
        __syncthreads();
        if (kc < 2) {          // prefetch chunk kc+2 into stage (kc+2)%3
            int c = kc + 2;
            int s = c % 3;
#pragma unroll
            for (int it = 0; it < 2; ++it) {
                int u = it * 256 + tid;
                int row = u >> 4;
                int seg = u & 15;
                const __half* src = Whk + (size_t)(c * 32 + row) * CCH + seg * 8;
                cp16(sb + SM_BB + s * 8192 + swz(row, seg), src, 16);
            }
            CP_COMMIT();
        }
        unsigned bb = sb + SM_BB + (kc % 3) * 8192;
#pragma unroll
        for (int kk = 0; kk < 2; ++kk) {
            unsigned ahf[2][4], alf[2][4];
            int gA = kc * 4 + kk * 2 + gsel;
#pragma unroll
            for (int mi = 0; mi < 2; ++mi) {
                int R = arow + mi * 16;
                unsigned off = swz(R, gA);
                LDSM_X4(ahf[mi], sb + SM_AH + off);
                LDSM_X4(alf[mi], sb + SM_AL + off);
            }
            int rB = kk * 16 + brow;
#pragma unroll
            for (int n2 = 0; n2 < 4; ++n2) {
                int gB = wn * 8 + n2 * 2 + gsel;
                unsigned boff = swz(rB, gB);
                unsigned bhf[4];
                LDSM_X4T(bhf, bb + boff);
#pragma unroll
                for (int mi = 0; mi < 2; ++mi) {
                    mma16816(acc[mi][n2 * 2],     ahf[mi], bhf);
                    mma16816(acc[mi][n2 * 2],     alf[mi], bhf);
                    mma16816(acc[mi][n2 * 2 + 1], ahf[mi], bhf + 2);
                    mma16816(acc[mi][n2 * 2 + 1], alf[mi], bhf + 2);
                }
            }
        }
    }

    // ---- epilogue: self -> fp32 g_y, pairs -> fp16 stage ----
    int gr = lane >> 2, gc = (lane & 3) * 2;
    if (k == 13) {
#pragma unroll
        for (int mi = 0; mi < 2; ++mi)
#pragma unroll
            for (int ni = 0; ni < 8; ++ni) {
                int c = wn * 64 + ni * 8 + gc;
                int r0 = wm * 32 + mi * 16 + gr;
                *(float2*)(Yself + (size_t)(obase + r0) * CCH + c) =
                    make_float2(acc[mi][ni][0], acc[mi][ni][1]);
                int r1 = r0 + 8;
                *(float2*)(Yself + (size_t)(obase + r1) * CCH + c) =
                    make_float2(acc[mi][ni][2], acc[mi][ni][3]);
            }
    } else {
#pragma unroll
        for (int mi = 0; mi < 2; ++mi)
#pragma unroll
            for (int ni = 0; ni < 8; ++ni) {
                int c = wn * 64 + ni * 8 + gc;
                int r0 = wm * 32 + mi * 16 + gr;
                if (r0 < rows)
                    *(__half2*)(Ystage + (size_t)(obase + r0) * CCH + c) =
                        __floats2half2_rn(acc[mi][ni][0], acc[mi][ni][1]);
                int r1 = r0 + 8;
                if (r1 < rows)
                    *(__half2*)(Ystage + (size_t)(obase + r1) * CCH + c) =
                        __floats2half2_rn(acc[mi][ni][2], acc[mi][ni][3]);
            }
    }
}

// ---------------- combine staged rows into g_y + BN stats -----------------------
__global__ void __launch_bounds__(256) k_combine(float* __restrict__ Y) {
    __shared__ float red[8][CCH];
    int warp = threadIdx.x >> 5, lane = threadIdx.x & 31;
    float s[4] = {0.f, 0.f, 0.f, 0.f}, s2[4] = {0.f, 0.f, 0.f, 0.f};
    int vbase = blockIdx.x * 128 + warp * 16;
    for (int tt = 0; tt < 16; ++tt) {
        int v = vbase + tt;
        int deg = g_deg[v];
        int myp = (lane < deg) ? g_vlist[(size_t)v * 26 + lane] : -1;
        float4 acc = *(const float4*)(Y + (size_t)v * CCH + lane * 4);
        for (int q = 0; q < deg; ++q) {
            int sl = __shfl_sync(0xffffffffu, myp, q);
            const __half2* p = (const __half2*)(g_stage + (size_t)sl * CCH + lane * 4);
            float2 a = __half22float2(p[0]);
            float2 b = __half22float2(p[1]);
            acc.x += a.x; acc.y += a.y; acc.z += b.x; acc.w += b.y;
        }
        *(float4*)(Y + (size_t)v * CCH + lane * 4) = acc;
        s[0] += acc.x; s[1] += acc.y; s[2] += acc.z; s[3] += acc.w;
        s2[0] += acc.x * acc.x; s2[1] += acc.y * acc.y;
        s2[2] += acc.z * acc.z; s2[3] += acc.w * acc.w;
    }
#pragma unroll
    for (int q = 0; q < 4; ++q) red[warp][lane * 4 + q] = s[q];
    __syncthreads();
    if (threadIdx.x < CCH) {
        float tot = 0.f;
#pragma unroll
        for (int w = 0; w < 8; ++w) tot += red[w][threadIdx.x];
        atomicAdd(&g_sum[threadIdx.x], tot);
    }
    __syncthreads();
#pragma unroll
    for (int q = 0; q < 4; ++q) red[warp][lane * 4 + q] = s2[q];
    __syncthreads();
    if (threadIdx.x < CCH) {
        float tot = 0.f;
#pragma unroll
        for (int w = 0; w < 8; ++w) tot += red[w][threadIdx.x];
        atomicAdd(&g_sumsq[threadIdx.x], tot);
    }
}

// ---------------- activations (BN finalize fused in-block) --------------------------
__global__ void k_act_inner(const float* __restrict__ Y,
                            const float* __restrict__ gma, const float* __restrict__ bta,
                            __half* __restrict__ XH, __half* __restrict__ XL) {
    __shared__ float ssc[CCH], ssh[CCH];
    if (threadIdx.x < CCH) {
        float mu = g_sum[threadIdx.x] * (1.0f / N_VOX);
        float var = g_sumsq[threadIdx.x] * (1.0f / N_VOX) - mu * mu;
        float rs = rsqrtf(var + EPSF);
        float sc = gma[threadIdx.x] * rs;
        ssc[threadIdx.x] = sc;
        ssh[threadIdx.x] = bta[threadIdx.x] - mu * sc;
    }
    __syncthreads();
    int idx = blockIdx.x * blockDim.x + threadIdx.x;
    int c4 = (idx & 31) << 2;
    float4 y = *(const float4*)(Y + (size_t)idx * 4);
    float4 sc = *(const float4*)(ssc + c4);
    float4 sh = *(const float4*)(ssh + c4);
    float4 v;
    v.x = fmaf(y.x, sc.x, sh.x);
    v.y = fmaf(y.y, sc.y, sh.y);
    v.z = fmaf(y.z, sc.z, sh.z);
    v.w = fmaf(y.w, sc.w, sh.w);
    v.x = v.x >= 0.f ? v.x : SLOPE_IN * v.x;
    v.y = v.y >= 0.f ? v.y : SLOPE_IN * v.y;
    v.z = v.z >= 0.f ? v.z : SLOPE_IN * v.z;
    v.w = v.w >= 0.f ? v.w : SLOPE_IN * v.w;
    split_store4((__half2*)XH, (__half2*)XL, idx, v);
}

__global__ void k_act_out(const float* __restrict__ Y,
                          const float* __restrict__ gma, const float* __restrict__ bta,
                          const __half* __restrict__ RH, const __half* __restrict__ RL,
                          float* __restrict__ O) {
    __shared__ float ssc[CCH], ssh[CCH];
    if (threadIdx.x < CCH) {
        float mu = g_sum[threadIdx.x] * (1.0f / N_VOX);
        float var = g_sumsq[threadIdx.x] * (1.0f / N_VOX) - mu * mu;
        float rs = rsqrtf(var + EPSF);
        float sc = gma[threadIdx.x] * rs;
        ssc[threadIdx.x] = sc;
        ssh[threadIdx.x] = bta[threadIdx.x] - mu * sc;
    }
    __syncthreads();
    int idx = blockIdx.x * blockDim.x + threadIdx.x;
    int c4 = (idx & 31) << 2;
    float4 y = *(const float4*)(Y + (size_t)idx * 4);
    const __half2* rh = (const __half2*)(RH + (size_t)idx * 4);
    const __half2* rl = (const __half2*)(RL + (size_t)idx * 4);
    float2 rh0 = __half22float2(rh[0]), rh1 = __half22float2(rh[1]);
    float2 rl0 = __half22float2(rl[0]), rl1 = __half22float2(rl[1]);
    float4 sc = *(const float4*)(ssc + c4);
    float4 sh = *(const float4*)(ssh + c4);
    float4 v;
    v.x = fmaf(y.x, sc.x, sh.x) + (rh0.x + rl0.x);
    v.y = fmaf(y.y, sc.y, sh.y) + (rh0.y + rl0.y);
    v.z = fmaf(y.z, sc.z, sh.z) + (rh1.x + rl1.x);
    v.w = fmaf(y.w, sc.w, sh.w) + (rh1.y + rl1.y);
    v.x = v.x >= 0.f ? v.x : SLOPE_OUT * v.x;
    v.y = v.y >= 0.f ? v.y : SLOPE_OUT * v.y;
    v.z = v.z >= 0.f ? v.z : SLOPE_OUT * v.z;
    v.w = v.w >= 0.f ? v.w : SLOPE_OUT * v.w;
    *(float4*)(O + (size_t)idx * 4) = v;
}

// ---------------- launch ----------------------------------------------------------------
extern "C" void kernel_launch(void* const* d_in, const int* in_sizes, int n_in,
                              void* d_out, int out_size) {
    const float* feat = (const float*)d_in[0];
    const int*   nbr  = (const int*)d_in[1];
    const float* w1   = (const float*)d_in[2];
    const float* w2   = (const float*)d_in[3];
    const float* w3   = (const float*)d_in[4];
    const float* g1   = (const float*)d_in[5];
    const float* b1   = (const float*)d_in[6];
    const float* g2   = (const float*)d_in[7];
    const float* b2   = (const float*)d_in[8];
    const float* g3   = (const float*)d_in[9];
    const float* b3   = (const float*)d_in[10];
    float* out = (float*)d_out;

    float *p_y;
    __half *p_stage, *p_xh0, *p_xl0, *p_xh1, *p_xl1, *p_wh;
    cudaGetSymbolAddress((void**)&p_y, g_y);
    cudaGetSymbolAddress((void**)&p_stage, g_stage);
    cudaGetSymbolAddress((void**)&p_xh0, g_xh0);
    cudaGetSymbolAddress((void**)&p_xl0, g_xl0);
    cudaGetSymbolAddress((void**)&p_xh1, g_xh1);
    cudaGetSymbolAddress((void**)&p_xl1, g_xl1);
    cudaGetSymbolAddress((void**)&p_wh, g_wh);

    cudaFuncSetAttribute(conv_mma, cudaFuncAttributeMaxDynamicSharedMemorySize,
                         SMEM_BYTES);

    const int nelem4 = (N_VOX * CCH) / 4;
    const int act_grid = nelem4 / 256;
    const int comb_grid = N_VOX / 128;         // 1024
    const int conv_grid = NK * TPK;            // 27648

    // rulebook + operand prep
    k_zero<<<N_VOX / 256, 256>>>();
    k_fill<<<(NK * N_VOX) / 256, 256>>>(nbr);
    {
        dim3 wg(WSZ / 256, 3);
        k_wsplit<<<wg, 256>>>(w1, w2, w3);
    }
    k_xsplit<<<act_grid, 256>>>(feat, p_xh0, p_xl0);

    // ---- layer 1 ----
    conv_mma<<<conv_grid, 256, SMEM_BYTES>>>(p_xh0, p_xl0, p_wh, p_stage, p_y);
    k_combine<<<comb_grid, 256>>>(p_y);
    k_act_inner<<<act_grid, 256>>>(p_y, g1, b1, p_xh1, p_xl1);   // layer1 act = residual

    // ---- layer 2 ----
    conv_mma<<<conv_grid, 256, SMEM_BYTES>>>(p_xh1, p_xl1, p_wh + WSZ, p_stage, p_y);
    k_combine<<<comb_grid, 256>>>(p_y);
    k_act_inner<<<act_grid, 256>>>(p_y, g2, b2, p_xh0, p_xl0);   // ping-pong

    // ---- layer 3 ----
    conv_mma<<<conv_grid, 256, SMEM_BYTES>>>(p_xh0, p_xl0, p_wh + 2 * WSZ, p_stage, p_y);
    k_combine<<<comb_grid, 256>>>(p_y);
    k_act_out<<<act_grid, 256>>>(p_y, g3, b3, p_xh1, p_xl1, out);
}

// round 10
// speedup vs baseline: 3.6897x; 1.0534x over previous
#include <cuda_runtime.h>
#include <cuda_fp16.h>
#include <cstdint>

#define N_VOX 131072
#define CCH 128
#define NK 27
#define TMROWS 128
#define TPK (N_VOX / TMROWS)       // 1024 tiles for the dense self offset
#define KCAP 49152                 // fixed region per offset (>= max pair count)
#define WSZ (NK * CCH * CCH)       // 442368
#define MAXTILES (NK * TPK)
#define CONV_GRID 296
#define EPSF 1e-4f
#define SLOPE_IN 0.05f
#define SLOPE_OUT (1.0f / 3.0f)

// ---------------- scratch (device globals) ----------------------------------
__device__ float g_y[(size_t)N_VOX * CCH];
__device__ __half g_stage[(size_t)NK * KCAP * CCH];    // fp16 partial rows
__device__ __half g_xh0[(size_t)N_VOX * CCH];
__device__ __half g_xl0[(size_t)N_VOX * CCH];
__device__ __half g_xh1[(size_t)N_VOX * CCH];
__device__ __half g_xl1[(size_t)N_VOX * CCH];
__device__ __half g_wh[3 * WSZ];                       // fp16 weights (hi only)
__device__ int   g_pairs_j[NK * KCAP];
__device__ int   g_vlist[(size_t)N_VOX * 26];          // per-voxel slot list
__device__ int   g_deg[N_VOX];
__device__ int   g_cnt[NK];
__device__ int   g_work[MAXTILES];                     // (k<<16)|tile
__device__ int   g_ntiles;
__device__ float g_sum[CCH], g_sumsq[CCH];

// ---------------- rulebook ----------------------------------------------------
__global__ void k_zero() {
    int i = blockIdx.x * 256 + threadIdx.x;
    if (i < N_VOX) g_deg[i] = 0;
    if (i < NK) g_cnt[i] = 0;
}

// idx = k*N + i ; k uniform per 256-thread block
__global__ void k_fill(const int* __restrict__ nbr) {
    __shared__ int woff[8];
    __shared__ int sbase;
    int idx = blockIdx.x * 256 + threadIdx.x;
    int k = idx >> 17;
    int i = idx & (N_VOX - 1);
    if (k == 13) return;
    int j = nbr[i * NK + k];
    bool valid = (j >= 0);
    unsigned m = __ballot_sync(0xffffffffu, valid);
    int w = threadIdx.x >> 5, lane = threadIdx.x & 31;
    if (lane == 0) woff[w] = __popc(m);
    __syncthreads();
    if (threadIdx.x == 0) {
        int o = 0;
        for (int q = 0; q < 8; ++q) { int c = woff[q]; woff[q] = o; o += c; }
        sbase = o ? atomicAdd(&g_cnt[k], o) : 0;
    }
    __syncthreads();
    if (valid) {
        int pos = k * KCAP + sbase + woff[w] + __popc(m & ((1u << lane) - 1u));
        g_pairs_j[pos] = j;
        int d = atomicAdd(&g_deg[i], 1);
        g_vlist[(size_t)i * 26 + d] = pos;
    }
}

// build exact, k-sorted tile work list
__global__ void k_worklist() {
    __shared__ int tk[NK], base[NK];
    int tid = threadIdx.x;
    if (tid < NK)
        tk[tid] = (tid == 13) ? TPK : ((g_cnt[tid] + TMROWS - 1) >> 7);
    __syncthreads();
    if (tid == 0) {
        int o = 0;
        for (int k = 0; k < NK; ++k) { base[k] = o; o += tk[k]; }
        g_ntiles = o;
    }
    __syncthreads();
    for (int k = 0; k < NK; ++k)
        for (int t = tid; t < tk[k]; t += 256)
            g_work[base[k] + t] = (k << 16) | t;
}

// ---------------- fp16 splits --------------------------------------------------
__global__ void k_wsplit(const float* __restrict__ w1, const float* __restrict__ w2,
                         const float* __restrict__ w3) {
    int i = blockIdx.x * blockDim.x + threadIdx.x;
    const float* src = (blockIdx.y == 0) ? w1 : (blockIdx.y == 1 ? w2 : w3);
    g_wh[blockIdx.y * WSZ + i] = __float2half(src[i]);
}

__device__ __forceinline__ void split_store4(__half2* xh, __half2* xl, int idx, float4 v) {
    __half h0 = __float2half(v.x), h1 = __float2half(v.y);
    __half h2 = __float2half(v.z), h3 = __float2half(v.w);
    __half l0 = __float2half(v.x - __half2float(h0));
    __half l1 = __float2half(v.y - __half2float(h1));
    __half l2 = __float2half(v.z - __half2float(h2));
    __half l3 = __float2half(v.w - __half2float(h3));
    xh[idx * 2]     = __halves2half2(h0, h1);
    xh[idx * 2 + 1] = __halves2half2(h2, h3);
    xl[idx * 2]     = __halves2half2(l0, l1);
    xl[idx * 2 + 1] = __halves2half2(l2, l3);
}

__global__ void k_xsplit(const float* __restrict__ F, __half* XH, __half* XL) {
    int idx = blockIdx.x * blockDim.x + threadIdx.x;
    float4 v = *(const float4*)(F + (size_t)idx * 4);
    split_store4((__half2*)XH, (__half2*)XL, idx, v);
}

// ---------------- mma.sync helpers ----------------------------------------------
__device__ __forceinline__ void mma16816(float* d, const unsigned* a, const unsigned* b) {
    asm volatile(
        "mma.sync.aligned.m16n8k16.row.col.f32.f16.f16.f32 "
        "{%0,%1,%2,%3}, {%4,%5,%6,%7}, {%8,%9}, {%0,%1,%2,%3};"
        : "+f"(d[0]), "+f"(d[1]), "+f"(d[2]), "+f"(d[3])
        : "r"(a[0]), "r"(a[1]), "r"(a[2]), "r"(a[3]), "r"(b[0]), "r"(b[1]));
}

#define LDSM_X4(R, addr) asm volatile( \
    "ldmatrix.sync.aligned.m8n8.x4.shared.b16 {%0,%1,%2,%3}, [%4];" \
    : "=r"((R)[0]), "=r"((R)[1]), "=r"((R)[2]), "=r"((R)[3]) : "r"(addr))
#define LDSM_X4T(R, addr) asm volatile( \
    "ldmatrix.sync.aligned.m8n8.x4.trans.shared.b16 {%0,%1,%2,%3}, [%4];" \
    : "=r"((R)[0]), "=r"((R)[1]), "=r"((R)[2]), "=r"((R)[3]) : "r"(addr))

__device__ __forceinline__ void cp16(unsigned dst, const void* src, int srcsize) {
    asm volatile("cp.async.cg.shared.global [%0], [%1], 16, %2;"
                 :: "r"(dst), "l"(src), "r"(srcsize) : "memory");
}
#define CP_COMMIT() asm volatile("cp.async.commit_group;" ::: "memory")
#define CP_WAIT1() asm volatile("cp.async.wait_group 1;" ::: "memory")
#define CP_WAIT0() asm volatile("cp.async.wait_group 0;" ::: "memory")

// ---------------- SMEM layout (dynamic, bytes) -----------------------------------
// A: 3 stages x (hi 8KB + lo 8KB) = 49152.  B: 4 chunks x 8KB = 32768 (per-k).
#define SM_A 0
#define SM_B 49152
#define SM_SJ 81920
#define SMEM_BYTES 82432

// B rows: 256B, granule swizzle g ^ (row & 7)
__device__ __forceinline__ unsigned swz(int row, int g) {
    return (unsigned)(row * 256 + ((g ^ (row & 7)) << 4));
}
// A chunk rows: 64B (4 granules); slot(row,g) = (4*row + g') mod 8 distinct over
// any 8 consecutive rows with g' = g ^ ((row>>1)&3)  -> conflict-free ldmatrix
__device__ __forceinline__ unsigned swzA(int row, int g) {
    return (unsigned)(row * 64 + ((g ^ ((row >> 1) & 3)) << 4));
}

// Persistent conv: grid = CONV_GRID, contiguous work-list partition per block.
__global__ void __launch_bounds__(256, 2) conv_mma(
    const __half* __restrict__ Xh, const __half* __restrict__ Xl,
    const __half* __restrict__ Wh,
    __half* __restrict__ Ystage, float* __restrict__ Yself)
{
    extern __shared__ char dsm[];
    unsigned sb = (unsigned)__cvta_generic_to_shared(dsm);
    int tid = threadIdx.x;

    // zero BN accumulators for the following combine pass
    if (blockIdx.x == 0 && tid < CCH) {
        g_sum[tid] = 0.f;
        g_sumsq[tid] = 0.f;
    }

    int total = g_ntiles;
    int per = (total + gridDim.x - 1) / gridDim.x;
    int lo = blockIdx.x * per;
    int hi = min(lo + per, total);

    int lane = tid & 31, warp = tid >> 5;
    int wm = warp & 3, wn = warp >> 2;
    int arow = wm * 32 + (lane & 15);
    int brow = lane & 15;
    int gsel = lane >> 4;
    int gr = lane >> 2, gc = (lane & 3) * 2;

    int* sj = (int*)(dsm + SM_SJ);
    int kprev = -1;

    for (int itm = lo; itm < hi; ++itm) {
        int wk = g_work[itm];
        int k = wk >> 16;
        int t = wk & 0xFFFF;
        int m0 = t * TMROWS;
        int cnt = (k == 13) ? N_VOX : g_cnt[k];
        int obase = (k == 13) ? m0 : k * KCAP + m0;
        int rows = min(TMROWS, cnt - m0);
        const __half* Whk = Wh + k * CCH * CCH;

        if (tid < TMROWS) {
            int j = -1;
            if (tid < rows) j = (k == 13) ? (m0 + tid) : g_pairs_j[obase + tid];
            sj[tid] = j;
        }
        // barrier: sj visible AND all warps finished previous tile's smem reads
        __syncthreads();

        if (k != kprev) {   // load full B for this offset (one group, 32 KB)
            kprev = k;
#pragma unroll
            for (int it2 = 0; it2 < 8; ++it2) {
                int u = it2 * 256 + tid;       // 0..2047
                int c = u >> 9;
                int rem = u & 511;
                int row = rem >> 4;
                int seg = rem & 15;
                const __half* src = Whk + (size_t)(c * 32 + row) * CCH + seg * 8;
                cp16(sb + SM_B + c * 8192 + swz(row, seg), src, 16);
            }
            CP_COMMIT();
        }
        // A chunks 0,1 (stages 0,1): each 16 KB hi+lo = 4 iters of 256
#pragma unroll
        for (int c = 0; c < 2; ++c) {
#pragma unroll
            for (int it2 = 0; it2 < 4; ++it2) {
                int u = it2 * 256 + tid;       // 0..1023
                int hl = u >> 9;
                int rem = u & 511;
                int row = rem >> 2;
                int g = rem & 3;
                int j = sj[row];
                const __half* src = (hl ? Xl : Xh) + (size_t)max(j, 0) * CCH +
                                    c * 32 + g * 8;
                cp16(sb + SM_A + c * 16384 + hl * 8192 + swzA(row, g), src,
                     j >= 0 ? 16 : 0);
            }
            CP_COMMIT();
        }

        float acc[2][8][4];
#pragma unroll
        for (int mi = 0; mi < 2; ++mi)
#pragma unroll
            for (int ni = 0; ni < 8; ++ni)
#pragma unroll
                for (int q = 0; q < 4; ++q) acc[mi][ni][q] = 0.f;

#pragma unroll
        for (int kc = 0; kc < 4; ++kc) {
            if (kc < 3) { CP_WAIT1(); } else { CP_WAIT0(); }
            __syncthreads();
            if (kc < 2) {   // prefetch A chunk kc+2 into stage (kc+2)%3
                int c = kc + 2;
                int s = c % 3;
#pragma unroll
                for (int it2 = 0; it2 < 4; ++it2) {
                    int u = it2 * 256 + tid;
                    int hl = u >> 9;
                    int rem = u & 511;
                    int row = rem >> 2;
                    int g = rem & 3;
                    int j = sj[row];
                    const __half* src = (hl ? Xl : Xh) + (size_t)max(j, 0) * CCH +
                                        c * 32 + g * 8;
                    cp16(sb + SM_A + s * 16384 + hl * 8192 + swzA(row, g), src,
                         j >= 0 ? 16 : 0);
                }
                CP_COMMIT();
            }
            unsigned aa = sb + SM_A + (kc % 3) * 16384;
            unsigned bb = sb + SM_B + kc * 8192;
#pragma unroll
            for (int kk = 0; kk < 2; ++kk) {
                unsigned ahf[2][4], alf[2][4];
                int gA = kk * 2 + gsel;
#pragma unroll
                for (int mi = 0; mi < 2; ++mi) {
                    int R = arow + mi * 16;
                    unsigned off = swzA(R, gA);
                    LDSM_X4(ahf[mi], aa + off);
                    LDSM_X4(alf[mi], aa + 8192 + off);
                }
                int rB = kk * 16 + brow;
#pragma unroll
                for (int n2 = 0; n2 < 4; ++n2) {
                    int gB = wn * 8 + n2 * 2 + gsel;
                    unsigned boff = swz(rB, gB);
                    unsigned bhf[4];
                    LDSM_X4T(bhf, bb + boff);
#pragma unroll
                    for (int mi = 0; mi < 2; ++mi) {
                        mma16816(acc[mi][n2 * 2],     ahf[mi], bhf);
                        mma16816(acc[mi][n2 * 2],     alf[mi], bhf);
                        mma16816(acc[mi][n2 * 2 + 1], ahf[mi], bhf + 2);
                        mma16816(acc[mi][n2 * 2 + 1], alf[mi], bhf + 2);
                    }
                }
            }
        }

        // epilogue: self -> fp32 g_y, pairs -> fp16 stage
        if (k == 13) {
#pragma unroll
            for (int mi = 0; mi < 2; ++mi)
#pragma unroll
                for (int ni = 0; ni < 8; ++ni) {
                    int c = wn * 64 + ni * 8 + gc;
                    int r0 = wm * 32 + mi * 16 + gr;
                    *(float2*)(Yself + (size_t)(obase + r0) * CCH + c) =
                        make_float2(acc[mi][ni][0], acc[mi][ni][1]);
                    int r1 = r0 + 8;
                    *(float2*)(Yself + (size_t)(obase + r1) * CCH + c) =
                        make_float2(acc[mi][ni][2], acc[mi][ni][3]);
                }
        } else {
#pragma unroll
            for (int mi = 0; mi < 2; ++mi)
#pragma unroll
                for (int ni = 0; ni < 8; ++ni) {
                    int c = wn * 64 + ni * 8 + gc;
                    int r0 = wm * 32 + mi * 16 + gr;
                    if (r0 < rows)
                        *(__half2*)(Ystage + (size_t)(obase + r0) * CCH + c) =
                            __floats2half2_rn(acc[mi][ni][0], acc[mi][ni][1]);
                    int r1 = r0 + 8;
                    if (r1 < rows)
                        *(__half2*)(Ystage + (size_t)(obase + r1) * CCH + c) =
                            __floats2half2_rn(acc[mi][ni][2], acc[mi][ni][3]);
                }
        }
    }
}

// ---------------- combine staged rows into g_y + BN stats -----------------------
__global__ void __launch_bounds__(256) k_combine(float* __restrict__ Y) {
    __shared__ float red[8][CCH];
    int warp = threadIdx.x >> 5, lane = threadIdx.x & 31;
    float s[4] = {0.f, 0.f, 0.f, 0.f}, s2[4] = {0.f, 0.f, 0.f, 0.f};
    int vbase = blockIdx.x * 128 + warp * 16;
    for (int tt = 0; tt < 16; ++tt) {
        int v = vbase + tt;
        int deg = g_deg[v];
        int myp = (lane < deg) ? g_vlist[(size_t)v * 26 + lane] : -1;
        float4 acc = *(const float4*)(Y + (size_t)v * CCH + lane * 4);
        for (int q = 0; q < deg; ++q) {
            int sl = __shfl_sync(0xffffffffu, myp, q);
            const __half2* p = (const __half2*)(g_stage + (size_t)sl * CCH + lane * 4);
            float2 a = __half22float2(p[0]);
            float2 b = __half22float2(p[1]);
            acc.x += a.x; acc.y += a.y; acc.z += b.x; acc.w += b.y;
        }
        *(float4*)(Y + (size_t)v * CCH + lane * 4) = acc;
        s[0] += acc.x; s[1] += acc.y; s[2] += acc.z; s[3] += acc.w;
        s2[0] += acc.x * acc.x; s2[1] += acc.y * acc.y;
        s2[2] += acc.z * acc.z; s2[3] += acc.w * acc.w;
    }
#pragma unroll
    for (int q = 0; q < 4; ++q) red[warp][lane * 4 + q] = s[q];
    __syncthreads();
    if (threadIdx.x < CCH) {
        float tot = 0.f;
#pragma unroll
        for (int w = 0; w < 8; ++w) tot += red[w][threadIdx.x];
        atomicAdd(&g_sum[threadIdx.x], tot);
    }
    __syncthreads();
#pragma unroll
    for (int q = 0; q < 4; ++q) red[warp][lane * 4 + q] = s2[q];
    __syncthreads();
    if (threadIdx.x < CCH) {
        float tot = 0.f;
#pragma unroll
        for (int w = 0; w < 8; ++w) tot += red[w][threadIdx.x];
        atomicAdd(&g_sumsq[threadIdx.x], tot);
    }
}

// ---------------- activations (BN finalize fused in-block) --------------------------
__global__ void k_act_inner(const float* __restrict__ Y,
                            const float* __restrict__ gma, const float* __restrict__ bta,
                            __half* __restrict__ XH, __half* __restrict__ XL) {
    __shared__ float ssc[CCH], ssh[CCH];
    if (threadIdx.x < CCH) {
        float mu = g_sum[threadIdx.x] * (1.0f / N_VOX);
        float var = g_sumsq[threadIdx.x] * (1.0f / N_VOX) - mu * mu;
        float rs = rsqrtf(var + EPSF);
        float sc = gma[threadIdx.x] * rs;
        ssc[threadIdx.x] = sc;
        ssh[threadIdx.x] = bta[threadIdx.x] - mu * sc;
    }
    __syncthreads();
    int idx = blockIdx.x * blockDim.x + threadIdx.x;
    int c4 = (idx & 31) << 2;
    float4 y = *(const float4*)(Y + (size_t)idx * 4);
    float4 sc = *(const float4*)(ssc + c4);
    float4 sh = *(const float4*)(ssh + c4);
    float4 v;
    v.x = fmaf(y.x, sc.x, sh.x);
    v.y = fmaf(y.y, sc.y, sh.y);
    v.z = fmaf(y.z, sc.z, sh.z);
    v.w = fmaf(y.w, sc.w, sh.w);
    v.x = v.x >= 0.f ? v.x : SLOPE_IN * v.x;
    v.y = v.y >= 0.f ? v.y : SLOPE_IN * v.y;
    v.z = v.z >= 0.f ? v.z : SLOPE_IN * v.z;
    v.w = v.w >= 0.f ? v.w : SLOPE_IN * v.w;
    split_store4((__half2*)XH, (__half2*)XL, idx, v);
}

__global__ void k_act_out(const float* __restrict__ Y,
                          const float* __restrict__ gma, const float* __restrict__ bta,
                          const __half* __restrict__ RH, const __half* __restrict__ RL,
                          float* __restrict__ O) {
    __shared__ float ssc[CCH], ssh[CCH];
    if (threadIdx.x < CCH) {
        float mu = g_sum[threadIdx.x] * (1.0f / N_VOX);
        float var = g_sumsq[threadIdx.x] * (1.0f / N_VOX) - mu * mu;
        float rs = rsqrtf(var + EPSF);
        float sc = gma[threadIdx.x] * rs;
        ssc[threadIdx.x] = sc;
        ssh[threadIdx.x] = bta[threadIdx.x] - mu * sc;
    }
    __syncthreads();
    int idx = blockIdx.x * blockDim.x + threadIdx.x;
    int c4 = (idx & 31) << 2;
    float4 y = *(const float4*)(Y + (size_t)idx * 4);
    const __half2* rh = (const __half2*)(RH + (size_t)idx * 4);
    const __half2* rl = (const __half2*)(RL + (size_t)idx * 4);
    float2 rh0 = __half22float2(rh[0]), rh1 = __half22float2(rh[1]);
    float2 rl0 = __half22float2(rl[0]), rl1 = __half22float2(rl[1]);
    float4 sc = *(const float4*)(ssc + c4);
    float4 sh = *(const float4*)(ssh + c4);
    float4 v;
    v.x = fmaf(y.x, sc.x, sh.x) + (rh0.x + rl0.x);
    v.y = fmaf(y.y, sc.y, sh.y) + (rh0.y + rl0.y);
    v.z = fmaf(y.z, sc.z, sh.z) + (rh1.x + rl1.x);
    v.w = fmaf(y.w, sc.w, sh.w) + (rh1.y + rl1.y);
    v.x = v.x >= 0.f ? v.x : SLOPE_OUT * v.x;
    v.y = v.y >= 0.f ? v.y : SLOPE_OUT * v.y;
    v.z = v.z >= 0.f ? v.z : SLOPE_OUT * v.z;
    v.w = v.w >= 0.f ? v.w : SLOPE_OUT * v.w;
    *(float4*)(O + (size_t)idx * 4) = v;
}

// ---------------- launch ----------------------------------------------------------------
extern "C" void kernel_launch(void* const* d_in, const int* in_sizes, int n_in,
                              void* d_out, int out_size) {
    const float* feat = (const float*)d_in[0];
    const int*   nbr  = (const int*)d_in[1];
    const float* w1   = (const float*)d_in[2];
    const float* w2   = (const float*)d_in[3];
    const float* w3   = (const float*)d_in[4];
    const float* g1   = (const float*)d_in[5];
    const float* b1   = (const float*)d_in[6];
    const float* g2   = (const float*)d_in[7];
    const float* b2   = (const float*)d_in[8];
    const float* g3   = (const float*)d_in[9];
    const float* b3   = (const float*)d_in[10];
    float* out = (float*)d_out;

    float *p_y;
    __half *p_stage, *p_xh0, *p_xl0, *p_xh1, *p_xl1, *p_wh;
    cudaGetSymbolAddress((void**)&p_y, g_y);
    cudaGetSymbolAddress((void**)&p_stage, g_stage);
    cudaGetSymbolAddress((void**)&p_xh0, g_xh0);
    cudaGetSymbolAddress((void**)&p_xl0, g_xl0);
    cudaGetSymbolAddress((void**)&p_xh1, g_xh1);
    cudaGetSymbolAddress((void**)&p_xl1, g_xl1);
    cudaGetSymbolAddress((void**)&p_wh, g_wh);

    cudaFuncSetAttribute(conv_mma, cudaFuncAttributeMaxDynamicSharedMemorySize,
                         SMEM_BYTES);

    const int nelem4 = (N_VOX * CCH) / 4;
    const int act_grid = nelem4 / 256;
    const int comb_grid = N_VOX / 128;         // 1024

    // rulebook + operand prep
    k_zero<<<N_VOX / 256, 256>>>();
    k_fill<<<(NK * N_VOX) / 256, 256>>>(nbr);
    k_worklist<<<1, 256>>>();
    {
        dim3 wg(WSZ / 256, 3);
        k_wsplit<<<wg, 256>>>(w1, w2, w3);
    }
    k_xsplit<<<act_grid, 256>>>(feat, p_xh0, p_xl0);

    // ---- layer 1 ----
    conv_mma<<<CONV_GRID, 256, SMEM_BYTES>>>(p_xh0, p_xl0, p_wh, p_stage, p_y);
    k_combine<<<comb_grid, 256>>>(p_y);
    k_act_inner<<<act_grid, 256>>>(p_y, g1, b1, p_xh1, p_xl1);   // layer1 act = residual

    // ---- layer 2 ----
    conv_mma<<<CONV_GRID, 256, SMEM_BYTES>>>(p_xh1, p_xl1, p_wh + WSZ, p_stage, p_y);
    k_combine<<<comb_grid, 256>>>(p_y);
    k_act_inner<<<act_grid, 256>>>(p_y, g2, b2, p_xh0, p_xl0);   // ping-pong

    // ---- layer 3 ----
    conv_mma<<<CONV_GRID, 256, SMEM_BYTES>>>(p_xh0, p_xl0, p_wh + 2 * WSZ, p_stage, p_y);
    k_combine<<<comb_grid, 256>>>(p_y);
    k_act_out<<<act_grid, 256>>>(p_y, g3, b3, p_xh1, p_xl1, out);
}

// round 11
// speedup vs baseline: 4.2763x; 1.1590x over previous
#include <cuda_runtime.h>
#include <cuda_fp16.h>
#include <cstdint>

#define N_VOX 131072
#define CCH 128
#define NK 27
#define TMROWS 128
#define TPK (N_VOX / TMROWS)       // 1024 tiles for the dense self offset
#define KCAP 49152                 // fixed region per offset (>= max pair count)
#define WSZ (NK * CCH * CCH)       // 442368
#define MAXTILES (NK * TPK)
#define CONV_GRID 296
#define EPSF 1e-4f
#define SLOPE_IN 0.05f
#define SLOPE_OUT (1.0f / 3.0f)

// ---------------- scratch (device globals) ----------------------------------
__device__ float g_y[(size_t)N_VOX * CCH];
__device__ __half g_stage[(size_t)NK * KCAP * CCH];    // fp16 partial rows
__device__ __half g_x0[(size_t)N_VOX * CCH];           // fp16 activations (ping)
__device__ __half g_x1[(size_t)N_VOX * CCH];           // fp16 activations (pong)
__device__ __half g_wh[3 * WSZ];                       // fp16 weights
__device__ int   g_pairs_j[NK * KCAP];
__device__ int   g_vlist[(size_t)N_VOX * 26];          // per-voxel slot list
__device__ int   g_deg[N_VOX];
__device__ int   g_cnt[NK];
__device__ int   g_work[MAXTILES];                     // (k<<16)|tile
__device__ int   g_ntiles;
__device__ float g_sum[CCH], g_sumsq[CCH];

// ---------------- rulebook ----------------------------------------------------
__global__ void k_zero() {
    int i = blockIdx.x * 256 + threadIdx.x;
    if (i < N_VOX) g_deg[i] = 0;
    if (i < NK) g_cnt[i] = 0;
}

// idx = k*N + i ; k uniform per 256-thread block
__global__ void k_fill(const int* __restrict__ nbr) {
    __shared__ int woff[8];
    __shared__ int sbase;
    int idx = blockIdx.x * 256 + threadIdx.x;
    int k = idx >> 17;
    int i = idx & (N_VOX - 1);
    if (k == 13) return;
    int j = nbr[i * NK + k];
    bool valid = (j >= 0);
    unsigned m = __ballot_sync(0xffffffffu, valid);
    int w = threadIdx.x >> 5, lane = threadIdx.x & 31;
    if (lane == 0) woff[w] = __popc(m);
    __syncthreads();
    if (threadIdx.x == 0) {
        int o = 0;
        for (int q = 0; q < 8; ++q) { int c = woff[q]; woff[q] = o; o += c; }
        sbase = o ? atomicAdd(&g_cnt[k], o) : 0;
    }
    __syncthreads();
    if (valid) {
        int pos = k * KCAP + sbase + woff[w] + __popc(m & ((1u << lane) - 1u));
        g_pairs_j[pos] = j;
        int d = atomicAdd(&g_deg[i], 1);
        g_vlist[(size_t)i * 26 + d] = pos;
    }
}

// build exact, k-sorted tile work list
__global__ void k_worklist() {
    __shared__ int tk[NK], base[NK];
    int tid = threadIdx.x;
    if (tid < NK)
        tk[tid] = (tid == 13) ? TPK : ((g_cnt[tid] + TMROWS - 1) >> 7);
    __syncthreads();
    if (tid == 0) {
        int o = 0;
        for (int k = 0; k < NK; ++k) { base[k] = o; o += tk[k]; }
        g_ntiles = o;
    }
    __syncthreads();
    for (int k = 0; k < NK; ++k)
        for (int t = tid; t < tk[k]; t += 256)
            g_work[base[k] + t] = (k << 16) | t;
}

// ---------------- fp16 conversions ----------------------------------------------
__global__ void k_wsplit(const float* __restrict__ w1, const float* __restrict__ w2,
                         const float* __restrict__ w3) {
    int i = blockIdx.x * blockDim.x + threadIdx.x;
    const float* src = (blockIdx.y == 0) ? w1 : (blockIdx.y == 1 ? w2 : w3);
    g_wh[blockIdx.y * WSZ + i] = __float2half(src[i]);
}

__global__ void k_xsplit(const float* __restrict__ F, __half* X) {
    int idx = blockIdx.x * blockDim.x + threadIdx.x;
    float4 v = *(const float4*)(F + (size_t)idx * 4);
    __half2* x = (__half2*)X;
    x[idx * 2]     = __floats2half2_rn(v.x, v.y);
    x[idx * 2 + 1] = __floats2half2_rn(v.z, v.w);
}

// ---------------- mma.sync helpers ----------------------------------------------
__device__ __forceinline__ void mma16816(float* d, const unsigned* a, const unsigned* b) {
    asm volatile(
        "mma.sync.aligned.m16n8k16.row.col.f32.f16.f16.f32 "
        "{%0,%1,%2,%3}, {%4,%5,%6,%7}, {%8,%9}, {%0,%1,%2,%3};"
        : "+f"(d[0]), "+f"(d[1]), "+f"(d[2]), "+f"(d[3])
        : "r"(a[0]), "r"(a[1]), "r"(a[2]), "r"(a[3]), "r"(b[0]), "r"(b[1]));
}

#define LDSM_X4(R, addr) asm volatile( \
    "ldmatrix.sync.aligned.m8n8.x4.shared.b16 {%0,%1,%2,%3}, [%4];" \
    : "=r"((R)[0]), "=r"((R)[1]), "=r"((R)[2]), "=r"((R)[3]) : "r"(addr))
#define LDSM_X4T(R, addr) asm volatile( \
    "ldmatrix.sync.aligned.m8n8.x4.trans.shared.b16 {%0,%1,%2,%3}, [%4];" \
    : "=r"((R)[0]), "=r"((R)[1]), "=r"((R)[2]), "=r"((R)[3]) : "r"(addr))

__device__ __forceinline__ void cp16(unsigned dst, const void* src, int srcsize) {
    asm volatile("cp.async.cg.shared.global [%0], [%1], 16, %2;"
                 :: "r"(dst), "l"(src), "r"(srcsize) : "memory");
}
#define CP_COMMIT() asm volatile("cp.async.commit_group;" ::: "memory")
#define CP_WAIT1() asm volatile("cp.async.wait_group 1;" ::: "memory")
#define CP_WAIT0() asm volatile("cp.async.wait_group 0;" ::: "memory")

// ---------------- SMEM layout (dynamic, bytes) -----------------------------------
// A: 3 stages x 8KB.  B: 4 chunks x 8KB (per-k).  sj: 512B.
#define SM_A 0
#define SM_B 24576
#define SM_SJ 57344
#define SMEM_BYTES 57856

// B rows: 256B, granule swizzle g ^ (row & 7)
__device__ __forceinline__ unsigned swz(int row, int g) {
    return (unsigned)(row * 256 + ((g ^ (row & 7)) << 4));
}
// A chunk rows: 64B (4 granules), conflict-free for ldmatrix
__device__ __forceinline__ unsigned swzA(int row, int g) {
    return (unsigned)(row * 64 + ((g ^ ((row >> 1) & 3)) << 4));
}

// Persistent conv: grid = CONV_GRID, contiguous work-list partition per block.
__global__ void __launch_bounds__(256, 2) conv_mma(
    const __half* __restrict__ X,
    const __half* __restrict__ Wh,
    __half* __restrict__ Ystage, float* __restrict__ Yself)
{
    extern __shared__ char dsm[];
    unsigned sb = (unsigned)__cvta_generic_to_shared(dsm);
    int tid = threadIdx.x;

    // zero BN accumulators for the following combine pass
    if (blockIdx.x == 0 && tid < CCH) {
        g_sum[tid] = 0.f;
        g_sumsq[tid] = 0.f;
    }

    int total = g_ntiles;
    int per = (total + gridDim.x - 1) / gridDim.x;
    int lo = blockIdx.x * per;
    int hi = min(lo + per, total);

    int lane = tid & 31, warp = tid >> 5;
    int wm = warp & 3, wn = warp >> 2;
    int arow = wm * 32 + (lane & 15);
    int brow = lane & 15;
    int gsel = lane >> 4;
    int gr = lane >> 2, gc = (lane & 3) * 2;

    int* sj = (int*)(dsm + SM_SJ);
    int kprev = -1;

    for (int itm = lo; itm < hi; ++itm) {
        int wk = g_work[itm];
        int k = wk >> 16;
        int t = wk & 0xFFFF;
        int m0 = t * TMROWS;
        int cnt = (k == 13) ? N_VOX : g_cnt[k];
        int obase = (k == 13) ? m0 : k * KCAP + m0;
        int rows = min(TMROWS, cnt - m0);
        const __half* Whk = Wh + k * CCH * CCH;

        if (tid < TMROWS) {
            int j = -1;
            if (tid < rows) j = (k == 13) ? (m0 + tid) : g_pairs_j[obase + tid];
            sj[tid] = j;
        }
        // barrier: sj visible AND all warps finished previous tile's smem reads
        __syncthreads();

        if (k != kprev) {   // load full B for this offset (one group, 32 KB)
            kprev = k;
#pragma unroll
            for (int it2 = 0; it2 < 8; ++it2) {
                int u = it2 * 256 + tid;       // 0..2047
                int c = u >> 9;
                int rem = u & 511;
                int row = rem >> 4;
                int seg = rem & 15;
                const __half* src = Whk + (size_t)(c * 32 + row) * CCH + seg * 8;
                cp16(sb + SM_B + c * 8192 + swz(row, seg), src, 16);
            }
            CP_COMMIT();
        }
        // A chunks 0,1 (stages 0,1): each 8 KB = 2 iters of 256
#pragma unroll
        for (int c = 0; c < 2; ++c) {
#pragma unroll
            for (int it2 = 0; it2 < 2; ++it2) {
                int u = it2 * 256 + tid;       // 0..511
                int row = u >> 2;
                int g = u & 3;
                int j = sj[row];
                const __half* src = X + (size_t)max(j, 0) * CCH + c * 32 + g * 8;
                cp16(sb + SM_A + c * 8192 + swzA(row, g), src, j >= 0 ? 16 : 0);
            }
            CP_COMMIT();
        }

        float acc[2][8][4];
#pragma unroll
        for (int mi = 0; mi < 2; ++mi)
#pragma unroll
            for (int ni = 0; ni < 8; ++ni)
#pragma unroll
                for (int q = 0; q < 4; ++q) acc[mi][ni][q] = 0.f;

#pragma unroll
        for (int kc = 0; kc < 4; ++kc) {
            if (kc < 3) { CP_WAIT1(); } else { CP_WAIT0(); }
            __syncthreads();
            if (kc < 2) {   // prefetch A chunk kc+2 into stage (kc+2)%3
                int c = kc + 2;
                int s = c % 3;
#pragma unroll
                for (int it2 = 0; it2 < 2; ++it2) {
                    int u = it2 * 256 + tid;
                    int row = u >> 2;
                    int g = u & 3;
                    int j = sj[row];
                    const __half* src = X + (size_t)max(j, 0) * CCH + c * 32 + g * 8;
                    cp16(sb + SM_A + s * 8192 + swzA(row, g), src, j >= 0 ? 16 : 0);
                }
                CP_COMMIT();
            }
            unsigned aa = sb + SM_A + (kc % 3) * 8192;
            unsigned bb = sb + SM_B + kc * 8192;
#pragma unroll
            for (int kk = 0; kk < 2; ++kk) {
                unsigned ahf[2][4];
                int gA = kk * 2 + gsel;
#pragma unroll
                for (int mi = 0; mi < 2; ++mi) {
                    int R = arow + mi * 16;
                    LDSM_X4(ahf[mi], aa + swzA(R, gA));
                }
                int rB = kk * 16 + brow;
#pragma unroll
                for (int n2 = 0; n2 < 4; ++n2) {
                    int gB = wn * 8 + n2 * 2 + gsel;
                    unsigned boff = swz(rB, gB);
                    unsigned bhf[4];
                    LDSM_X4T(bhf, bb + boff);
#pragma unroll
                    for (int mi = 0; mi < 2; ++mi) {
                        mma16816(acc[mi][n2 * 2],     ahf[mi], bhf);
                        mma16816(acc[mi][n2 * 2 + 1], ahf[mi], bhf + 2);
                    }
                }
            }
        }

        // epilogue: self -> fp32 g_y, pairs -> fp16 stage
        if (k == 13) {
#pragma unroll
            for (int mi = 0; mi < 2; ++mi)
#pragma unroll
                for (int ni = 0; ni < 8; ++ni) {
                    int c = wn * 64 + ni * 8 + gc;
                    int r0 = wm * 32 + mi * 16 + gr;
                    *(float2*)(Yself + (size_t)(obase + r0) * CCH + c) =
                        make_float2(acc[mi][ni][0], acc[mi][ni][1]);
                    int r1 = r0 + 8;
                    *(float2*)(Yself + (size_t)(obase + r1) * CCH + c) =
                        make_float2(acc[mi][ni][2], acc[mi][ni][3]);
                }
        } else {
#pragma unroll
            for (int mi = 0; mi < 2; ++mi)
#pragma unroll
                for (int ni = 0; ni < 8; ++ni) {
                    int c = wn * 64 + ni * 8 + gc;
                    int r0 = wm * 32 + mi * 16 + gr;
                    if (r0 < rows)
                        *(__half2*)(Ystage + (size_t)(obase + r0) * CCH + c) =
                            __floats2half2_rn(acc[mi][ni][0], acc[mi][ni][1]);
                    int r1 = r0 + 8;
                    if (r1 < rows)
                        *(__half2*)(Ystage + (size_t)(obase + r1) * CCH + c) =
                            __floats2half2_rn(acc[mi][ni][2], acc[mi][ni][3]);
                }
        }
    }
}

// ---------------- combine staged rows into g_y + BN stats -----------------------
__global__ void __launch_bounds__(256) k_combine(float* __restrict__ Y) {
    __shared__ float red[8][CCH];
    int warp = threadIdx.x >> 5, lane = threadIdx.x & 31;
    float s[4] = {0.f, 0.f, 0.f, 0.f}, s2[4] = {0.f, 0.f, 0.f, 0.f};
    int vbase = blockIdx.x * 128 + warp * 16;
    for (int tt = 0; tt < 16; ++tt) {
        int v = vbase + tt;
        int deg = g_deg[v];
        int myp = (lane < deg) ? g_vlist[(size_t)v * 26 + lane] : -1;
        float4 acc = *(const float4*)(Y + (size_t)v * CCH + lane * 4);
        for (int q = 0; q < deg; ++q) {
            int sl = __shfl_sync(0xffffffffu, myp, q);
            const __half2* p = (const __half2*)(g_stage + (size_t)sl * CCH + lane * 4);
            float2 a = __half22float2(p[0]);
            float2 b = __half22float2(p[1]);
            acc.x += a.x; acc.y += a.y; acc.z += b.x; acc.w += b.y;
        }
        *(float4*)(Y + (size_t)v * CCH + lane * 4) = acc;
        s[0] += acc.x; s[1] += acc.y; s[2] += acc.z; s[3] += acc.w;
        s2[0] += acc.x * acc.x; s2[1] += acc.y * acc.y;
        s2[2] += acc.z * acc.z; s2[3] += acc.w * acc.w;
    }
#pragma unroll
    for (int q = 0; q < 4; ++q) red[warp][lane * 4 + q] = s[q];
    __syncthreads();
    if (threadIdx.x < CCH) {
        float tot = 0.f;
#pragma unroll
        for (int w = 0; w < 8; ++w) tot += red[w][threadIdx.x];
        atomicAdd(&g_sum[threadIdx.x], tot);
    }
    __syncthreads();
#pragma unroll
    for (int q = 0; q < 4; ++q) red[warp][lane * 4 + q] = s2[q];
    __syncthreads();
    if (threadIdx.x < CCH) {
        float tot = 0.f;
#pragma unroll
        for (int w = 0; w < 8; ++w) tot += red[w][threadIdx.x];
        atomicAdd(&g_sumsq[threadIdx.x], tot);
    }
}

// ---------------- activations (BN finalize fused in-block) --------------------------
__global__ void k_act_inner(const float* __restrict__ Y,
                            const float* __restrict__ gma, const float* __restrict__ bta,
                            __half* __restrict__ X) {
    __shared__ float ssc[CCH], ssh[CCH];
    if (threadIdx.x < CCH) {
        float mu = g_sum[threadIdx.x] * (1.0f / N_VOX);
        float var = g_sumsq[threadIdx.x] * (1.0f / N_VOX) - mu * mu;
        float rs = rsqrtf(var + EPSF);
        float sc = gma[threadIdx.x] * rs;
        ssc[threadIdx.x] = sc;
        ssh[threadIdx.x] = bta[threadIdx.x] - mu * sc;
    }
    __syncthreads();
    int idx = blockIdx.x * blockDim.x + threadIdx.x;
    int c4 = (idx & 31) << 2;
    float4 y = *(const float4*)(Y + (size_t)idx * 4);
    float4 sc = *(const float4*)(ssc + c4);
    float4 sh = *(const float4*)(ssh + c4);
    float4 v;
    v.x = fmaf(y.x, sc.x, sh.x);
    v.y = fmaf(y.y, sc.y, sh.y);
    v.z = fmaf(y.z, sc.z, sh.z);
    v.w = fmaf(y.w, sc.w, sh.w);
    v.x = v.x >= 0.f ? v.x : SLOPE_IN * v.x;
    v.y = v.y >= 0.f ? v.y : SLOPE_IN * v.y;
    v.z = v.z >= 0.f ? v.z : SLOPE_IN * v.z;
    v.w = v.w >= 0.f ? v.w : SLOPE_IN * v.w;
    __half2* x = (__half2*)X;
    x[idx * 2]     = __floats2half2_rn(v.x, v.y);
    x[idx * 2 + 1] = __floats2half2_rn(v.z, v.w);
}

__global__ void k_act_out(const float* __restrict__ Y,
                          const float* __restrict__ gma, const float* __restrict__ bta,
                          const __half* __restrict__ RH, float* __restrict__ O) {
    __shared__ float ssc[CCH], ssh[CCH];
    if (threadIdx.x < CCH) {
        float mu = g_sum[threadIdx.x] * (1.0f / N_VOX);
        float var = g_sumsq[threadIdx.x] * (1.0f / N_VOX) - mu * mu;
        float rs = rsqrtf(var + EPSF);
        float sc = gma[threadIdx.x] * rs;
        ssc[threadIdx.x] = sc;
        ssh[threadIdx.x] = bta[threadIdx.x] - mu * sc;
    }
    __syncthreads();
    int idx = blockIdx.x * blockDim.x + threadIdx.x;
    int c4 = (idx & 31) << 2;
    float4 y = *(const float4*)(Y + (size_t)idx * 4);
    const __half2* rh = (const __half2*)(RH + (size_t)idx * 4);
    float2 r0 = __half22float2(rh[0]), r1 = __half22float2(rh[1]);
    float4 sc = *(const float4*)(ssc + c4);
    float4 sh = *(const float4*)(ssh + c4);
    float4 v;
    v.x = fmaf(y.x, sc.x, sh.x) + r0.x;
    v.y = fmaf(y.y, sc.y, sh.y) + r0.y;
    v.z = fmaf(y.z, sc.z, sh.z) + r1.x;
    v.w = fmaf(y.w, sc.w, sh.w) + r1.y;
    v.x = v.x >= 0.f ? v.x : SLOPE_OUT * v.x;
    v.y = v.y >= 0.f ? v.y : SLOPE_OUT * v.y;
    v.z = v.z >= 0.f ? v.z : SLOPE_OUT * v.z;
    v.w = v.w >= 0.f ? v.w : SLOPE_OUT * v.w;
    *(float4*)(O + (size_t)idx * 4) = v;
}

// ---------------- launch ----------------------------------------------------------------
extern "C" void kernel_launch(void* const* d_in, const int* in_sizes, int n_in,
                              void* d_out, int out_size) {
    const float* feat = (const float*)d_in[0];
    const int*   nbr  = (const int*)d_in[1];
    const float* w1   = (const float*)d_in[2];
    const float* w2   = (const float*)d_in[3];
    const float* w3   = (const float*)d_in[4];
    const float* g1   = (const float*)d_in[5];
    const float* b1   = (const float*)d_in[6];
    const float* g2   = (const float*)d_in[7];
    const float* b2   = (const float*)d_in[8];
    const float* g3   = (const float*)d_in[9];
    const float* b3   = (const float*)d_in[10];
    float* out = (float*)d_out;

    float *p_y;
    __half *p_stage, *p_x0, *p_x1, *p_wh;
    cudaGetSymbolAddress((void**)&p_y, g_y);
    cudaGetSymbolAddress((void**)&p_stage, g_stage);
    cudaGetSymbolAddress((void**)&p_x0, g_x0);
    cudaGetSymbolAddress((void**)&p_x1, g_x1);
    cudaGetSymbolAddress((void**)&p_wh, g_wh);

    cudaFuncSetAttribute(conv_mma, cudaFuncAttributeMaxDynamicSharedMemorySize,
                         SMEM_BYTES);

    const int nelem4 = (N_VOX * CCH) / 4;
    const int act_grid = nelem4 / 256;
    const int comb_grid = N_VOX / 128;         // 1024

    // rulebook + operand prep
    k_zero<<<N_VOX / 256, 256>>>();
    k_fill<<<(NK * N_VOX) / 256, 256>>>(nbr);
    k_worklist<<<1, 256>>>();
    {
        dim3 wg(WSZ / 256, 3);
        k_wsplit<<<wg, 256>>>(w1, w2, w3);
    }
    k_xsplit<<<act_grid, 256>>>(feat, p_x0);

    // ---- layer 1 ----
    conv_mma<<<CONV_GRID, 256, SMEM_BYTES>>>(p_x0, p_wh, p_stage, p_y);
    k_combine<<<comb_grid, 256>>>(p_y);
    k_act_inner<<<act_grid, 256>>>(p_y, g1, b1, p_x1);   // act1 = residual

    // ---- layer 2 ----
    conv_mma<<<CONV_GRID, 256, SMEM_BYTES>>>(p_x1, p_wh + WSZ, p_stage, p_y);
    k_combine<<<comb_grid, 256>>>(p_y);
    k_act_inner<<<act_grid, 256>>>(p_y, g2, b2, p_x0);   // ping-pong

    // ---- layer 3 ----
    conv_mma<<<CONV_GRID, 256, SMEM_BYTES>>>(p_x0, p_wh + 2 * WSZ, p_stage, p_y);
    k_combine<<<comb_grid, 256>>>(p_y);
    k_act_out<<<act_grid, 256>>>(p_y, g3, b3, p_x1, out);
}

// round 13
// speedup vs baseline: 4.6946x; 1.0978x over previous
#include <cuda_runtime.h>
#include <cuda_fp16.h>
#include <cstdint>

#define N_VOX 131072
#define CCH 128
#define NK 27
#define TMROWS 128
#define TPK (N_VOX / TMROWS)       // 1024 tiles for the dense self offset
#define KCAP 49152                 // fixed region per offset (>= max pair count)
#define WSZ (NK * CCH * CCH)       // 442368
#define MAXTILES (NK * TPK)
#define CONV_GRID 296
#define EPSF 1e-4f
#define SLOPE_IN 0.05f
#define SLOPE_OUT (1.0f / 3.0f)

// ---------------- scratch (device globals) ----------------------------------
__device__ float g_y[(size_t)N_VOX * CCH];
__device__ __half g_stage[(size_t)N_VOX * 26 * CCH];   // dst-ordered partial rows
__device__ __half g_x0[(size_t)N_VOX * CCH];           // fp16 activations (ping)
__device__ __half g_x1[(size_t)N_VOX * CCH];           // fp16 activations (pong)
__device__ __half g_wh[3 * WSZ];                       // fp16 weights
__device__ int   g_pairs_j[NK * KCAP];                 // source row per pair slot
__device__ int   g_pairs_dst[NK * KCAP];               // dest stage slot per pair
__device__ int   g_deg[N_VOX];
__device__ int   g_cnt[NK];
__device__ int   g_work[MAXTILES];                     // (k<<16)|tile
__device__ int   g_ntiles;
__device__ float g_sum[CCH], g_sumsq[CCH];

// ---------------- rulebook ----------------------------------------------------
__global__ void k_zero() {
    int i = blockIdx.x * 256 + threadIdx.x;
    if (i < N_VOX) g_deg[i] = 0;
    if (i < NK) g_cnt[i] = 0;
}

// idx = k*N + i ; k uniform per 256-thread block
__global__ void k_fill(const int* __restrict__ nbr) {
    __shared__ int woff[8];
    __shared__ int sbase;
    int idx = blockIdx.x * 256 + threadIdx.x;
    int k = idx >> 17;
    int i = idx & (N_VOX - 1);
    if (k == 13) return;
    int j = nbr[i * NK + k];
    bool valid = (j >= 0);
    unsigned m = __ballot_sync(0xffffffffu, valid);
    int w = threadIdx.x >> 5, lane = threadIdx.x & 31;
    if (lane == 0) woff[w] = __popc(m);
    __syncthreads();
    if (threadIdx.x == 0) {
        int o = 0;
        for (int q = 0; q < 8; ++q) { int c = woff[q]; woff[q] = o; o += c; }
        sbase = o ? atomicAdd(&g_cnt[k], o) : 0;
    }
    __syncthreads();
    if (valid) {
        int pos = k * KCAP + sbase + woff[w] + __popc(m & ((1u << lane) - 1u));
        g_pairs_j[pos] = j;
        int d = atomicAdd(&g_deg[i], 1);
        g_pairs_dst[pos] = i * 26 + d;
    }
}

// build exact, k-sorted tile work list
__global__ void k_worklist() {
    __shared__ int tk[NK], base[NK];
    int tid = threadIdx.x;
    if (tid < NK)
        tk[tid] = (tid == 13) ? TPK : ((g_cnt[tid] + TMROWS - 1) >> 7);
    __syncthreads();
    if (tid == 0) {
        int o = 0;
        for (int k = 0; k < NK; ++k) { base[k] = o; o += tk[k]; }
        g_ntiles = o;
    }
    __syncthreads();
    for (int k = 0; k < NK; ++k)
        for (int t = tid; t < tk[k]; t += 256)
            g_work[base[k] + t] = (k << 16) | t;
}

// ---------------- fp16 conversions ----------------------------------------------
__global__ void k_wsplit(const float* __restrict__ w1, const float* __restrict__ w2,
                         const float* __restrict__ w3) {
    int i = blockIdx.x * blockDim.x + threadIdx.x;
    const float* src = (blockIdx.y == 0) ? w1 : (blockIdx.y == 1 ? w2 : w3);
    g_wh[blockIdx.y * WSZ + i] = __float2half(src[i]);
}

__global__ void k_xsplit(const float* __restrict__ F, __half* X) {
    int idx = blockIdx.x * blockDim.x + threadIdx.x;
    float4 v = *(const float4*)(F + (size_t)idx * 4);
    __half2* x = (__half2*)X;
    x[idx * 2]     = __floats2half2_rn(v.x, v.y);
    x[idx * 2 + 1] = __floats2half2_rn(v.z, v.w);
}

// ---------------- mma.sync helpers ----------------------------------------------
__device__ __forceinline__ void mma16816(float* d, const unsigned* a, const unsigned* b) {
    asm volatile(
        "mma.sync.aligned.m16n8k16.row.col.f32.f16.f16.f32 "
        "{%0,%1,%2,%3}, {%4,%5,%6,%7}, {%8,%9}, {%0,%1,%2,%3};"
        : "+f"(d[0]), "+f"(d[1]), "+f"(d[2]), "+f"(d[3])
        : "r"(a[0]), "r"(a[1]), "r"(a[2]), "r"(a[3]), "r"(b[0]), "r"(b[1]));
}

#define LDSM_X4(R, addr) asm volatile( \
    "ldmatrix.sync.aligned.m8n8.x4.shared.b16 {%0,%1,%2,%3}, [%4];" \
    : "=r"((R)[0]), "=r"((R)[1]), "=r"((R)[2]), "=r"((R)[3]) : "r"(addr))
#define LDSM_X4T(R, addr) asm volatile( \
    "ldmatrix.sync.aligned.m8n8.x4.trans.shared.b16 {%0,%1,%2,%3}, [%4];" \
    : "=r"((R)[0]), "=r"((R)[1]), "=r"((R)[2]), "=r"((R)[3]) : "r"(addr))

__device__ __forceinline__ void cp16(unsigned dst, const void* src, int srcsize) {
    asm volatile("cp.async.cg.shared.global [%0], [%1], 16, %2;"
                 :: "r"(dst), "l"(src), "r"(srcsize) : "memory");
}
#define CP_COMMIT() asm volatile("cp.async.commit_group;" ::: "memory")
#define CP_WAIT1() asm volatile("cp.async.wait_group 1;" ::: "memory")
#define CP_WAIT0() asm volatile("cp.async.wait_group 0;" ::: "memory")

// ---------------- SMEM layout (dynamic, bytes) -----------------------------------
// A: 3 stages x 8KB.  B: 4 chunks x 8KB (per-k).  sj: 512B. sd: 2 x 512B (parity).
#define SM_A 0
#define SM_B 24576
#define SM_SJ 57344
#define SM_SD 57856
#define SMEM_BYTES 58880

// B rows: 256B, granule swizzle g ^ (row & 7)
__device__ __forceinline__ unsigned swz(int row, int g) {
    return (unsigned)(row * 256 + ((g ^ (row & 7)) << 4));
}
// A chunk rows: 64B (4 granules), conflict-free for ldmatrix
__device__ __forceinline__ unsigned swzA(int row, int g) {
    return (unsigned)(row * 64 + ((g ^ ((row >> 1) & 3)) << 4));
}

// Persistent conv: grid = CONV_GRID, contiguous work-list partition per block.
__global__ void __launch_bounds__(256, 2) conv_mma(
    const __half* __restrict__ X,
    const __half* __restrict__ Wh,
    __half* __restrict__ Ystage, float* __restrict__ Yself)
{
    extern __shared__ char dsm[];
    unsigned sb = (unsigned)__cvta_generic_to_shared(dsm);
    int tid = threadIdx.x;

    // zero BN accumulators for the following combine pass
    if (blockIdx.x == 0 && tid < CCH) {
        g_sum[tid] = 0.f;
        g_sumsq[tid] = 0.f;
    }

    int total = g_ntiles;
    int per = (total + gridDim.x - 1) / gridDim.x;
    int lo = blockIdx.x * per;
    int hi = min(lo + per, total);

    int lane = tid & 31, warp = tid >> 5;
    int wm = warp & 3, wn = warp >> 2;
    int arow = wm * 32 + (lane & 15);
    int brow = lane & 15;
    int gsel = lane >> 4;
    int gr = lane >> 2, gc = (lane & 3) * 2;

    int* sj = (int*)(dsm + SM_SJ);
    int kprev = -1;

    for (int itm = lo; itm < hi; ++itm) {
        int wk = g_work[itm];
        int k = wk >> 16;
        int t = wk & 0xFFFF;
        int m0 = t * TMROWS;
        int cnt = (k == 13) ? N_VOX : g_cnt[k];
        int obase = (k == 13) ? m0 : k * KCAP + m0;
        int rows = min(TMROWS, cnt - m0);
        const __half* Whk = Wh + k * CCH * CCH;

        // sd double-buffered on tile parity: the epilogue reads sd AFTER the
        // last kc barrier, so the next tile must write a DIFFERENT buffer.
        int* sd = (int*)(dsm + SM_SD + (itm & 1) * 512);

        if (tid < TMROWS) {
            int j = -1, d = 0;
            if (tid < rows) {
                if (k == 13) { j = m0 + tid; }
                else { j = g_pairs_j[obase + tid]; d = g_pairs_dst[obase + tid]; }
            }
            sj[tid] = j;
            sd[tid] = d;
        }
        // barrier: sj/sd visible AND all warps finished previous tile's sj reads
        __syncthreads();

        if (k != kprev) {   // load full B for this offset (one group, 32 KB)
            kprev = k;
#pragma unroll
            for (int it2 = 0; it2 < 8; ++it2) {
                int u = it2 * 256 + tid;       // 0..2047
                int c = u >> 9;
                int rem = u & 511;
                int row = rem >> 4;
                int seg = rem & 15;
                const __half* src = Whk + (size_t)(c * 32 + row) * CCH + seg * 8;
                cp16(sb + SM_B + c * 8192 + swz(row, seg), src, 16);
            }
            CP_COMMIT();
        }
        // A chunks 0,1 (stages 0,1): each 8 KB = 2 iters of 256
#pragma unroll
        for (int c = 0; c < 2; ++c) {
#pragma unroll
            for (int it2 = 0; it2 < 2; ++it2) {
                int u = it2 * 256 + tid;       // 0..511
                int row = u >> 2;
                int g = u & 3;
                int j = sj[row];
                const __half* src = X + (size_t)max(j, 0) * CCH + c * 32 + g * 8;
                cp16(sb + SM_A + c * 8192 + swzA(row, g), src, j >= 0 ? 16 : 0);
            }
            CP_COMMIT();
        }

        float acc[2][8][4];
#pragma unroll
        for (int mi = 0; mi < 2; ++mi)
#pragma unroll
            for (int ni = 0; ni < 8; ++ni)
#pragma unroll
                for (int q = 0; q < 4; ++q) acc[mi][ni][q] = 0.f;

#pragma unroll
        for (int kc = 0; kc < 4; ++kc) {
            if (kc < 3) { CP_WAIT1(); } else { CP_WAIT0(); }
            __syncthreads();
            if (kc < 2) {   // prefetch A chunk kc+2 into stage (kc+2)%3
                int c = kc + 2;
                int s = c % 3;
#pragma unroll
                for (int it2 = 0; it2 < 2; ++it2) {
                    int u = it2 * 256 + tid;
                    int row = u >> 2;
                    int g = u & 3;
                    int j = sj[row];
                    const __half* src = X + (size_t)max(j, 0) * CCH + c * 32 + g * 8;
                    cp16(sb + SM_A + s * 8192 + swzA(row, g), src, j >= 0 ? 16 : 0);
                }
                CP_COMMIT();
            }
            unsigned aa = sb + SM_A + (kc % 3) * 8192;
            unsigned bb = sb + SM_B + kc * 8192;
#pragma unroll
            for (int kk = 0; kk < 2; ++kk) {
                unsigned ahf[2][4];
                int gA = kk * 2 + gsel;
#pragma unroll
                for (int mi = 0; mi < 2; ++mi) {
                    int R = arow + mi * 16;
                    LDSM_X4(ahf[mi], aa + swzA(R, gA));
                }
                int rB = kk * 16 + brow;
#pragma unroll
                for (int n2 = 0; n2 < 4; ++n2) {
                    int gB = wn * 8 + n2 * 2 + gsel;
                    unsigned boff = swz(rB, gB);
                    unsigned bhf[4];
                    LDSM_X4T(bhf, bb + boff);
#pragma unroll
                    for (int mi = 0; mi < 2; ++mi) {
                        mma16816(acc[mi][n2 * 2],     ahf[mi], bhf);
                        mma16816(acc[mi][n2 * 2 + 1], ahf[mi], bhf + 2);
                    }
                }
            }
        }

        // epilogue: self -> fp32 g_y, pairs -> fp16 stage at dst slot
        if (k == 13) {
#pragma unroll
            for (int mi = 0; mi < 2; ++mi)
#pragma unroll
                for (int ni = 0; ni < 8; ++ni) {
                    int c = wn * 64 + ni * 8 + gc;
                    int r0 = wm * 32 + mi * 16 + gr;
                    *(float2*)(Yself + (size_t)(obase + r0) * CCH + c) =
                        make_float2(acc[mi][ni][0], acc[mi][ni][1]);
                    int r1 = r0 + 8;
                    *(float2*)(Yself + (size_t)(obase + r1) * CCH + c) =
                        make_float2(acc[mi][ni][2], acc[mi][ni][3]);
                }
        } else {
#pragma unroll
            for (int mi = 0; mi < 2; ++mi)
#pragma unroll
                for (int ni = 0; ni < 8; ++ni) {
                    int c = wn * 64 + ni * 8 + gc;
                    int r0 = wm * 32 + mi * 16 + gr;
                    if (r0 < rows)
                        *(__half2*)(Ystage + (size_t)sd[r0] * CCH + c) =
                            __floats2half2_rn(acc[mi][ni][0], acc[mi][ni][1]);
                    int r1 = r0 + 8;
                    if (r1 < rows)
                        *(__half2*)(Ystage + (size_t)sd[r1] * CCH + c) =
                            __floats2half2_rn(acc[mi][ni][2], acc[mi][ni][3]);
                }
        }
    }
}

// ---------------- combine staged rows into g_y + BN stats -----------------------
// 8 voxels per warp; stage rows for voxel v are CONTIGUOUS at v*26..v*26+deg-1.
__global__ void __launch_bounds__(256) k_combine(float* __restrict__ Y) {
    __shared__ float red[8][CCH];
    int warp = threadIdx.x >> 5, lane = threadIdx.x & 31;
    float s[4] = {0.f, 0.f, 0.f, 0.f}, s2[4] = {0.f, 0.f, 0.f, 0.f};
    int vbase = blockIdx.x * 64 + warp * 8;
    for (int tt = 0; tt < 8; ++tt) {
        int v = vbase + tt;
        int deg = g_deg[v];
        float4 acc = *(const float4*)(Y + (size_t)v * CCH + lane * 4);
        const __half2* base = (const __half2*)(g_stage + (size_t)v * 26 * CCH + lane * 4);
        for (int q = 0; q < deg; ++q) {
            const __half2* p = base + q * (CCH / 2);
            float2 a = __half22float2(p[0]);
            float2 b = __half22float2(p[1]);
            acc.x += a.x; acc.y += a.y; acc.z += b.x; acc.w += b.y;
        }
        *(float4*)(Y + (size_t)v * CCH + lane * 4) = acc;
        s[0] += acc.x; s[1] += acc.y; s[2] += acc.z; s[3] += acc.w;
        s2[0] += acc.x * acc.x; s2[1] += acc.y * acc.y;
        s2[2] += acc.z * acc.z; s2[3] += acc.w * acc.w;
    }
#pragma unroll
    for (int q = 0; q < 4; ++q) red[warp][lane * 4 + q] = s[q];
    __syncthreads();
    if (threadIdx.x < CCH) {
        float tot = 0.f;
#pragma unroll
        for (int w = 0; w < 8; ++w) tot += red[w][threadIdx.x];
        atomicAdd(&g_sum[threadIdx.x], tot);
    }
    __syncthreads();
#pragma unroll
    for (int q = 0; q < 4; ++q) red[warp][lane * 4 + q] = s2[q];
    __syncthreads();
    if (threadIdx.x < CCH) {
        float tot = 0.f;
#pragma unroll
        for (int w = 0; w < 8; ++w) tot += red[w][threadIdx.x];
        atomicAdd(&g_sumsq[threadIdx.x], tot);
    }
}

// ---------------- activations (BN finalize fused in-block) --------------------------
__global__ void k_act_inner(const float* __restrict__ Y,
                            const float* __restrict__ gma, const float* __restrict__ bta,
                            __half* __restrict__ X) {
    __shared__ float ssc[CCH], ssh[CCH];
    if (threadIdx.x < CCH) {
        float mu = g_sum[threadIdx.x] * (1.0f / N_VOX);
        float var = g_sumsq[threadIdx.x] * (1.0f / N_VOX) - mu * mu;
        float rs = rsqrtf(var + EPSF);
        float sc = gma[threadIdx.x] * rs;
        ssc[threadIdx.x] = sc;
        ssh[threadIdx.x] = bta[threadIdx.x] - mu * sc;
    }
    __syncthreads();
    int idx = blockIdx.x * blockDim.x + threadIdx.x;
    int c4 = (idx & 31) << 2;
    float4 y = *(const float4*)(Y + (size_t)idx * 4);
    float4 sc = *(const float4*)(ssc + c4);
    float4 sh = *(const float4*)(ssh + c4);
    float4 v;
    v.x = fmaf(y.x, sc.x, sh.x);
    v.y = fmaf(y.y, sc.y, sh.y);
    v.z = fmaf(y.z, sc.z, sh.z);
    v.w = fmaf(y.w, sc.w, sh.w);
    v.x = v.x >= 0.f ? v.x : SLOPE_IN * v.x;
    v.y = v.y >= 0.f ? v.y : SLOPE_IN * v.y;
    v.z = v.z >= 0.f ? v.z : SLOPE_IN * v.z;
    v.w = v.w >= 0.f ? v.w : SLOPE_IN * v.w;
    __half2* x = (__half2*)X;
    x[idx * 2]     = __floats2half2_rn(v.x, v.y);
    x[idx * 2 + 1] = __floats2half2_rn(v.z, v.w);
}

__global__ void k_act_out(const float* __restrict__ Y,
                          const float* __restrict__ gma, const float* __restrict__ bta,
                          const __half* __restrict__ RH, float* __restrict__ O) {
    __shared__ float ssc[CCH], ssh[CCH];
    if (threadIdx.x < CCH) {
        float mu = g_sum[threadIdx.x] * (1.0f / N_VOX);
        float var = g_sumsq[threadIdx.x] * (1.0f / N_VOX) - mu * mu;
        float rs = rsqrtf(var + EPSF);
        float sc = gma[threadIdx.x] * rs;
        ssc[threadIdx.x] = sc;
        ssh[threadIdx.x] = bta[threadIdx.x] - mu * sc;
    }
    __syncthreads();
    int idx = blockIdx.x * blockDim.x + threadIdx.x;
    int c4 = (idx & 31) << 2;
    float4 y = *(const float4*)(Y + (size_t)idx * 4);
    const __half2* rh = (const __half2*)(RH + (size_t)idx * 4);
    float2 r0 = __half22float2(rh[0]), r1 = __half22float2(rh[1]);
    float4 sc = *(const float4*)(ssc + c4);
    float4 sh = *(const float4*)(ssh + c4);
    float4 v;
    v.x = fmaf(y.x, sc.x, sh.x) + r0.x;
    v.y = fmaf(y.y, sc.y, sh.y) + r0.y;
    v.z = fmaf(y.z, sc.z, sh.z) + r1.x;
    v.w = fmaf(y.w, sc.w, sh.w) + r1.y;
    v.x = v.x >= 0.f ? v.x : SLOPE_OUT * v.x;
    v.y = v.y >= 0.f ? v.y : SLOPE_OUT * v.y;
    v.z = v.z >= 0.f ? v.z : SLOPE_OUT * v.z;
    v.w = v.w >= 0.f ? v.w : SLOPE_OUT * v.w;
    *(float4*)(O + (size_t)idx * 4) = v;
}

// ---------------- launch ----------------------------------------------------------------
extern "C" void kernel_launch(void* const* d_in, const int* in_sizes, int n_in,
                              void* d_out, int out_size) {
    const float* feat = (const float*)d_in[0];
    const int*   nbr  = (const int*)d_in[1];
    const float* w1   = (const float*)d_in[2];
    const float* w2   = (const float*)d_in[3];
    const float* w3   = (const float*)d_in[4];
    const float* g1   = (const float*)d_in[5];
    const float* b1   = (const float*)d_in[6];
    const float* g2   = (const float*)d_in[7];
    const float* b2   = (const float*)d_in[8];
    const float* g3   = (const float*)d_in[9];
    const float* b3   = (const float*)d_in[10];
    float* out = (float*)d_out;

    float *p_y;
    __half *p_stage, *p_x0, *p_x1, *p_wh;
    cudaGetSymbolAddress((void**)&p_y, g_y);
    cudaGetSymbolAddress((void**)&p_stage, g_stage);
    cudaGetSymbolAddress((void**)&p_x0, g_x0);
    cudaGetSymbolAddress((void**)&p_x1, g_x1);
    cudaGetSymbolAddress((void**)&p_wh, g_wh);

    cudaFuncSetAttribute(conv_mma, cudaFuncAttributeMaxDynamicSharedMemorySize,
                         SMEM_BYTES);

    const int nelem4 = (N_VOX * CCH) / 4;
    const int act_grid = nelem4 / 256;
    const int comb_grid = N_VOX / 64;          // 2048

    // rulebook + operand prep
    k_zero<<<N_VOX / 256, 256>>>();
    k_fill<<<(NK * N_VOX) / 256, 256>>>(nbr);
    k_worklist<<<1, 256>>>();
    {
        dim3 wg(WSZ / 256, 3);
        k_wsplit<<<wg, 256>>>(w1, w2, w3);
    }
    k_xsplit<<<act_grid, 256>>>(feat, p_x0);

    // ---- layer 1 ----
    conv_mma<<<CONV_GRID, 256, SMEM_BYTES>>>(p_x0, p_wh, p_stage, p_y);
    k_combine<<<comb_grid, 256>>>(p_y);
    k_act_inner<<<act_grid, 256>>>(p_y, g1, b1, p_x1);   // act1 = residual

    // ---- layer 2 ----
    conv_mma<<<CONV_GRID, 256, SMEM_BYTES>>>(p_x1, p_wh + WSZ, p_stage, p_y);
    k_combine<<<comb_grid, 256>>>(p_y);
    k_act_inner<<<act_grid, 256>>>(p_y, g2, b2, p_x0);   // ping-pong

    // ---- layer 3 ----
    conv_mma<<<CONV_GRID, 256, SMEM_BYTES>>>(p_x0, p_wh + 2 * WSZ, p_stage, p_y);
    k_combine<<<comb_grid, 256>>>(p_y);
    k_act_out<<<act_grid, 256>>>(p_y, g3, b3, p_x1, out);
}

// round 14
// speedup vs baseline: 4.8864x; 1.0408x over previous
#include <cuda_runtime.h>
#include <cuda_fp16.h>
#include <cstdint>

#define N_VOX 131072
#define CCH 128
#define NK 27
#define TMROWS 128
#define TPK (N_VOX / TMROWS)       // 1024 tiles for the dense self offset
#define KCAP 49152                 // fixed region per offset (>= max pair count)
#define WSZ (NK * CCH * CCH)       // 442368
#define MAXTILES (NK * TPK)
#define CONV_GRID 296
#define EPSF 1e-4f
#define SLOPE_IN 0.05f
#define SLOPE_OUT (1.0f / 3.0f)

// ---------------- scratch (device globals) ----------------------------------
__device__ __half g_y[(size_t)N_VOX * CCH];            // fp16 conv output
__device__ __half g_stage[(size_t)N_VOX * 27 * CCH];   // dst-ordered partials (+self)
__device__ __half g_x0[(size_t)N_VOX * CCH];           // fp16 activations (ping)
__device__ __half g_x1[(size_t)N_VOX * CCH];           // fp16 activations (pong)
__device__ __half g_wh[3 * WSZ];                       // fp16 weights
__device__ int   g_pairs_j[NK * KCAP];                 // source row per pair slot
__device__ int   g_pairs_dst[NK * KCAP];               // dest stage slot per pair
__device__ int   g_deg[N_VOX];
__device__ int   g_cnt[NK];
__device__ int   g_work[MAXTILES];                     // (k<<16)|tile
__device__ int   g_ntiles;
__device__ float g_sum[CCH], g_sumsq[CCH];

// ---------------- rulebook ----------------------------------------------------
__global__ void k_zero() {
    int i = blockIdx.x * 256 + threadIdx.x;
    if (i < N_VOX) g_deg[i] = 0;
    if (i < NK) g_cnt[i] = 0;
}

// idx = k*N + i ; k uniform per 256-thread block
__global__ void k_fill(const int* __restrict__ nbr) {
    __shared__ int woff[8];
    __shared__ int sbase;
    int idx = blockIdx.x * 256 + threadIdx.x;
    int k = idx >> 17;
    int i = idx & (N_VOX - 1);
    if (k == 13) return;
    int j = nbr[i * NK + k];
    bool valid = (j >= 0);
    unsigned m = __ballot_sync(0xffffffffu, valid);
    int w = threadIdx.x >> 5, lane = threadIdx.x & 31;
    if (lane == 0) woff[w] = __popc(m);
    __syncthreads();
    if (threadIdx.x == 0) {
        int o = 0;
        for (int q = 0; q < 8; ++q) { int c = woff[q]; woff[q] = o; o += c; }
        sbase = o ? atomicAdd(&g_cnt[k], o) : 0;
    }
    __syncthreads();
    if (valid) {
        int pos = k * KCAP + sbase + woff[w] + __popc(m & ((1u << lane) - 1u));
        g_pairs_j[pos] = j;
        int d = atomicAdd(&g_deg[i], 1);
        g_pairs_dst[pos] = i * 27 + d;
    }
}

// build exact, k-sorted tile work list
__global__ void k_worklist() {
    __shared__ int tk[NK], base[NK];
    int tid = threadIdx.x;
    if (tid < NK)
        tk[tid] = (tid == 13) ? TPK : ((g_cnt[tid] + TMROWS - 1) >> 7);
    __syncthreads();
    if (tid == 0) {
        int o = 0;
        for (int k = 0; k < NK; ++k) { base[k] = o; o += tk[k]; }
        g_ntiles = o;
    }
    __syncthreads();
    for (int k = 0; k < NK; ++k)
        for (int t = tid; t < tk[k]; t += 256)
            g_work[base[k] + t] = (k << 16) | t;
}

// ---------------- fp16 conversions ----------------------------------------------
__global__ void k_wsplit(const float* __restrict__ w1, const float* __restrict__ w2,
                         const float* __restrict__ w3) {
    int i = blockIdx.x * blockDim.x + threadIdx.x;
    const float* src = (blockIdx.y == 0) ? w1 : (blockIdx.y == 1 ? w2 : w3);
    g_wh[blockIdx.y * WSZ + i] = __float2half(src[i]);
}

__global__ void k_xsplit(const float* __restrict__ F, __half* X) {
    int idx = blockIdx.x * blockDim.x + threadIdx.x;
    float4 v = *(const float4*)(F + (size_t)idx * 4);
    __half2* x = (__half2*)X;
    x[idx * 2]     = __floats2half2_rn(v.x, v.y);
    x[idx * 2 + 1] = __floats2half2_rn(v.z, v.w);
}

// ---------------- mma.sync helpers ----------------------------------------------
__device__ __forceinline__ void mma16816(float* d, const unsigned* a, const unsigned* b) {
    asm volatile(
        "mma.sync.aligned.m16n8k16.row.col.f32.f16.f16.f32 "
        "{%0,%1,%2,%3}, {%4,%5,%6,%7}, {%8,%9}, {%0,%1,%2,%3};"
        : "+f"(d[0]), "+f"(d[1]), "+f"(d[2]), "+f"(d[3])
        : "r"(a[0]), "r"(a[1]), "r"(a[2]), "r"(a[3]), "r"(b[0]), "r"(b[1]));
}

#define LDSM_X4(R, addr) asm volatile( \
    "ldmatrix.sync.aligned.m8n8.x4.shared.b16 {%0,%1,%2,%3}, [%4];" \
    : "=r"((R)[0]), "=r"((R)[1]), "=r"((R)[2]), "=r"((R)[3]) : "r"(addr))
#define LDSM_X4T(R, addr) asm volatile( \
    "ldmatrix.sync.aligned.m8n8.x4.trans.shared.b16 {%0,%1,%2,%3}, [%4];" \
    : "=r"((R)[0]), "=r"((R)[1]), "=r"((R)[2]), "=r"((R)[3]) : "r"(addr))

__device__ __forceinline__ void cp16(unsigned dst, const void* src, int srcsize) {
    asm volatile("cp.async.cg.shared.global [%0], [%1], 16, %2;"
                 :: "r"(dst), "l"(src), "r"(srcsize) : "memory");
}
#define CP_COMMIT() asm volatile("cp.async.commit_group;" ::: "memory")
#define CP_WAIT1() asm volatile("cp.async.wait_group 1;" ::: "memory")
#define CP_WAIT0() asm volatile("cp.async.wait_group 0;" ::: "memory")

// ---------------- SMEM layout (dynamic, bytes) -----------------------------------
// A: 3 stages x 8KB.  B: 4 chunks x 8KB (per-k).  sj: 512B. sd: 2 x 512B (parity).
#define SM_A 0
#define SM_B 24576
#define SM_SJ 57344
#define SM_SD 57856
#define SMEM_BYTES 58880

// B rows: 256B, granule swizzle g ^ (row & 7)
__device__ __forceinline__ unsigned swz(int row, int g) {
    return (unsigned)(row * 256 + ((g ^ (row & 7)) << 4));
}
// A chunk rows: 64B (4 granules), conflict-free for ldmatrix
__device__ __forceinline__ unsigned swzA(int row, int g) {
    return (unsigned)(row * 64 + ((g ^ ((row >> 1) & 3)) << 4));
}

// Persistent conv: grid = CONV_GRID, contiguous work-list partition per block.
__global__ void __launch_bounds__(256, 2) conv_mma(
    const __half* __restrict__ X,
    const __half* __restrict__ Wh,
    __half* __restrict__ Ystage)
{
    extern __shared__ char dsm[];
    unsigned sb = (unsigned)__cvta_generic_to_shared(dsm);
    int tid = threadIdx.x;

    // zero BN accumulators for the following combine pass
    if (blockIdx.x == 0 && tid < CCH) {
        g_sum[tid] = 0.f;
        g_sumsq[tid] = 0.f;
    }

    int total = g_ntiles;
    int per = (total + gridDim.x - 1) / gridDim.x;
    int lo = blockIdx.x * per;
    int hi = min(lo + per, total);

    int lane = tid & 31, warp = tid >> 5;
    int wm = warp & 3, wn = warp >> 2;
    int arow = wm * 32 + (lane & 15);
    int brow = lane & 15;
    int gsel = lane >> 4;
    int gr = lane >> 2, gc = (lane & 3) * 2;

    int* sj = (int*)(dsm + SM_SJ);
    int kprev = -1;

    for (int itm = lo; itm < hi; ++itm) {
        int wk = g_work[itm];
        int k = wk >> 16;
        int t = wk & 0xFFFF;
        int m0 = t * TMROWS;
        int cnt = (k == 13) ? N_VOX : g_cnt[k];
        int obase = k * KCAP + m0;
        int rows = min(TMROWS, cnt - m0);
        const __half* Whk = Wh + k * CCH * CCH;

        // sd double-buffered on tile parity (epilogue reads sd after last barrier)
        int* sd = (int*)(dsm + SM_SD + (itm & 1) * 512);

        if (tid < TMROWS) {
            int j = -1, d = 0;
            if (tid < rows) {
                if (k == 13) {
                    j = m0 + tid;
                    d = j * 27 + g_deg[j];      // self tap -> slot deg (contiguous)
                } else {
                    j = g_pairs_j[obase + tid];
                    d = g_pairs_dst[obase + tid];
                }
            }
            sj[tid] = j;
            sd[tid] = d;
        }
        // barrier: sj/sd visible AND all warps finished previous tile's sj reads
        __syncthreads();

        if (k != kprev) {   // load full B for this offset (one group, 32 KB)
            kprev = k;
#pragma unroll
            for (int it2 = 0; it2 < 8; ++it2) {
                int u = it2 * 256 + tid;       // 0..2047
                int c = u >> 9;
                int rem = u & 511;
                int row = rem >> 4;
                int seg = rem & 15;
                const __half* src = Whk + (size_t)(c * 32 + row) * CCH + seg * 8;
                cp16(sb + SM_B + c * 8192 + swz(row, seg), src, 16);
            }
            CP_COMMIT();
        }
        // A chunks 0,1 (stages 0,1): each 8 KB = 2 iters of 256
#pragma unroll
        for (int c = 0; c < 2; ++c) {
#pragma unroll
            for (int it2 = 0; it2 < 2; ++it2) {
                int u = it2 * 256 + tid;       // 0..511
                int row = u >> 2;
                int g = u & 3;
                int j = sj[row];
                const __half* src = X + (size_t)max(j, 0) * CCH + c * 32 + g * 8;
                cp16(sb + SM_A + c * 8192 + swzA(row, g), src, j >= 0 ? 16 : 0);
            }
            CP_COMMIT();
        }

        float acc[2][8][4];
#pragma unroll
        for (int mi = 0; mi < 2; ++mi)
#pragma unroll
            for (int ni = 0; ni < 8; ++ni)
#pragma unroll
                for (int q = 0; q < 4; ++q) acc[mi][ni][q] = 0.f;

#pragma unroll
        for (int kc = 0; kc < 4; ++kc) {
            if (kc < 3) { CP_WAIT1(); } else { CP_WAIT0(); }
            __syncthreads();
            if (kc < 2) {   // prefetch A chunk kc+2 into stage (kc+2)%3
                int c = kc + 2;
                int s = c % 3;
#pragma unroll
                for (int it2 = 0; it2 < 2; ++it2) {
                    int u = it2 * 256 + tid;
                    int row = u >> 2;
                    int g = u & 3;
                    int j = sj[row];
                    const __half* src = X + (size_t)max(j, 0) * CCH + c * 32 + g * 8;
                    cp16(sb + SM_A + s * 8192 + swzA(row, g), src, j >= 0 ? 16 : 0);
                }
                CP_COMMIT();
            }
            unsigned aa = sb + SM_A + (kc % 3) * 8192;
            unsigned bb = sb + SM_B + kc * 8192;
#pragma unroll
            for (int kk = 0; kk < 2; ++kk) {
                unsigned ahf[2][4];
                int gA = kk * 2 + gsel;
#pragma unroll
                for (int mi = 0; mi < 2; ++mi) {
                    int R = arow + mi * 16;
                    LDSM_X4(ahf[mi], aa + swzA(R, gA));
                }
                int rB = kk * 16 + brow;
#pragma unroll
                for (int n2 = 0; n2 < 4; ++n2) {
                    int gB = wn * 8 + n2 * 2 + gsel;
                    unsigned boff = swz(rB, gB);
                    unsigned bhf[4];
                    LDSM_X4T(bhf, bb + boff);
#pragma unroll
                    for (int mi = 0; mi < 2; ++mi) {
                        mma16816(acc[mi][n2 * 2],     ahf[mi], bhf);
                        mma16816(acc[mi][n2 * 2 + 1], ahf[mi], bhf + 2);
                    }
                }
            }
        }

        // epilogue: unified fp16 scatter to stage dst slots
#pragma unroll
        for (int mi = 0; mi < 2; ++mi)
#pragma unroll
            for (int ni = 0; ni < 8; ++ni) {
                int c = wn * 64 + ni * 8 + gc;
                int r0 = wm * 32 + mi * 16 + gr;
                if (r0 < rows)
                    *(__half2*)(Ystage + (size_t)sd[r0] * CCH + c) =
                        __floats2half2_rn(acc[mi][ni][0], acc[mi][ni][1]);
                int r1 = r0 + 8;
                if (r1 < rows)
                    *(__half2*)(Ystage + (size_t)sd[r1] * CCH + c) =
                        __floats2half2_rn(acc[mi][ni][2], acc[mi][ni][3]);
            }
    }
}

// ---------------- combine staged rows -> fp16 y + BN stats -----------------------
// 8 voxels per warp; rows for voxel v are CONTIGUOUS at v*27..v*27+deg (incl self).
__global__ void __launch_bounds__(256) k_combine(__half* __restrict__ Y) {
    __shared__ float red[8][CCH];
    int warp = threadIdx.x >> 5, lane = threadIdx.x & 31;
    float s[4] = {0.f, 0.f, 0.f, 0.f}, s2[4] = {0.f, 0.f, 0.f, 0.f};
    int vbase = blockIdx.x * 64 + warp * 8;
    for (int tt = 0; tt < 8; ++tt) {
        int v = vbase + tt;
        int degp = g_deg[v] + 1;
        float4 acc = make_float4(0.f, 0.f, 0.f, 0.f);
        const __half2* base = (const __half2*)(g_stage + (size_t)v * 27 * CCH + lane * 4);
        for (int q = 0; q < degp; ++q) {
            const __half2* p = base + q * (CCH / 2);
            float2 a = __half22float2(p[0]);
            float2 b = __half22float2(p[1]);
            acc.x += a.x; acc.y += a.y; acc.z += b.x; acc.w += b.y;
        }
        __half2* yv = (__half2*)(Y + (size_t)v * CCH);
        yv[lane * 2]     = __floats2half2_rn(acc.x, acc.y);
        yv[lane * 2 + 1] = __floats2half2_rn(acc.z, acc.w);
        s[0] += acc.x; s[1] += acc.y; s[2] += acc.z; s[3] += acc.w;
        s2[0] += acc.x * acc.x; s2[1] += acc.y * acc.y;
        s2[2] += acc.z * acc.z; s2[3] += acc.w * acc.w;
    }
#pragma unroll
    for (int q = 0; q < 4; ++q) red[warp][lane * 4 + q] = s[q];
    __syncthreads();
    if (threadIdx.x < CCH) {
        float tot = 0.f;
#pragma unroll
        for (int w = 0; w < 8; ++w) tot += red[w][threadIdx.x];
        atomicAdd(&g_sum[threadIdx.x], tot);
    }
    __syncthreads();
#pragma unroll
    for (int q = 0; q < 4; ++q) red[warp][lane * 4 + q] = s2[q];
    __syncthreads();
    if (threadIdx.x < CCH) {
        float tot = 0.f;
#pragma unroll
        for (int w = 0; w < 8; ++w) tot += red[w][threadIdx.x];
        atomicAdd(&g_sumsq[threadIdx.x], tot);
    }
}

// ---------------- activations (BN finalize fused in-block) --------------------------
__global__ void k_act_inner(const __half* __restrict__ Y,
                            const float* __restrict__ gma, const float* __restrict__ bta,
                            __half* __restrict__ X) {
    __shared__ float ssc[CCH], ssh[CCH];
    if (threadIdx.x < CCH) {
        float mu = g_sum[threadIdx.x] * (1.0f / N_VOX);
        float var = g_sumsq[threadIdx.x] * (1.0f / N_VOX) - mu * mu;
        float rs = rsqrtf(var + EPSF);
        float sc = gma[threadIdx.x] * rs;
        ssc[threadIdx.x] = sc;
        ssh[threadIdx.x] = bta[threadIdx.x] - mu * sc;
    }
    __syncthreads();
    int idx = blockIdx.x * blockDim.x + threadIdx.x;
    int c4 = (idx & 31) << 2;
    const __half2* yv = (const __half2*)(Y + (size_t)idx * 4);
    float2 y0 = __half22float2(yv[0]), y1 = __half22float2(yv[1]);
    float4 sc = *(const float4*)(ssc + c4);
    float4 sh = *(const float4*)(ssh + c4);
    float4 v;
    v.x = fmaf(y0.x, sc.x, sh.x);
    v.y = fmaf(y0.y, sc.y, sh.y);
    v.z = fmaf(y1.x, sc.z, sh.z);
    v.w = fmaf(y1.y, sc.w, sh.w);
    v.x = v.x >= 0.f ? v.x : SLOPE_IN * v.x;
    v.y = v.y >= 0.f ? v.y : SLOPE_IN * v.y;
    v.z = v.z >= 0.f ? v.z : SLOPE_IN * v.z;
    v.w = v.w >= 0.f ? v.w : SLOPE_IN * v.w;
    __half2* x = (__half2*)X;
    x[idx * 2]     = __floats2half2_rn(v.x, v.y);
    x[idx * 2 + 1] = __floats2half2_rn(v.z, v.w);
}

__global__ void k_act_out(const __half* __restrict__ Y,
                          const float* __restrict__ gma, const float* __restrict__ bta,
                          const __half* __restrict__ RH, float* __restrict__ O) {
    __shared__ float ssc[CCH], ssh[CCH];
    if (threadIdx.x < CCH) {
        float mu = g_sum[threadIdx.x] * (1.0f / N_VOX);
        float var = g_sumsq[threadIdx.x] * (1.0f / N_VOX) - mu * mu;
        float rs = rsqrtf(var + EPSF);
        float sc = gma[threadIdx.x] * rs;
        ssc[threadIdx.x] = sc;
        ssh[threadIdx.x] = bta[threadIdx.x] - mu * sc;
    }
    __syncthreads();
    int idx = blockIdx.x * blockDim.x + threadIdx.x;
    int c4 = (idx & 31) << 2;
    const __half2* yv = (const __half2*)(Y + (size_t)idx * 4);
    float2 y0 = __half22float2(yv[0]), y1 = __half22float2(yv[1]);
    const __half2* rh = (const __half2*)(RH + (size_t)idx * 4);
    float2 r0 = __half22float2(rh[0]), r1 = __half22float2(rh[1]);
    float4 sc = *(const float4*)(ssc + c4);
    float4 sh = *(const float4*)(ssh + c4);
    float4 v;
    v.x = fmaf(y0.x, sc.x, sh.x) + r0.x;
    v.y = fmaf(y0.y, sc.y, sh.y) + r0.y;
    v.z = fmaf(y1.x, sc.z, sh.z) + r1.x;
    v.w = fmaf(y1.y, sc.w, sh.w) + r1.y;
    v.x = v.x >= 0.f ? v.x : SLOPE_OUT * v.x;
    v.y = v.y >= 0.f ? v.y : SLOPE_OUT * v.y;
    v.z = v.z >= 0.f ? v.z : SLOPE_OUT * v.z;
    v.w = v.w >= 0.f ? v.w : SLOPE_OUT * v.w;
    *(float4*)(O + (size_t)idx * 4) = v;
}

// ---------------- launch ----------------------------------------------------------------
extern "C" void kernel_launch(void* const* d_in, const int* in_sizes, int n_in,
                              void* d_out, int out_size) {
    const float* feat = (const float*)d_in[0];
    const int*   nbr  = (const int*)d_in[1];
    const float* w1   = (const float*)d_in[2];
    const float* w2   = (const float*)d_in[3];
    const float* w3   = (const float*)d_in[4];
    const float* g1   = (const float*)d_in[5];
    const float* b1   = (const float*)d_in[6];
    const float* g2   = (const float*)d_in[7];
    const float* b2   = (const float*)d_in[8];
    const float* g3   = (const float*)d_in[9];
    const float* b3   = (const float*)d_in[10];
    float* out = (float*)d_out;

    __half *p_y, *p_stage, *p_x0, *p_x1, *p_wh;
    cudaGetSymbolAddress((void**)&p_y, g_y);
    cudaGetSymbolAddress((void**)&p_stage, g_stage);
    cudaGetSymbolAddress((void**)&p_x0, g_x0);
    cudaGetSymbolAddress((void**)&p_x1, g_x1);
    cudaGetSymbolAddress((void**)&p_wh, g_wh);

    cudaFuncSetAttribute(conv_mma, cudaFuncAttributeMaxDynamicSharedMemorySize,
                         SMEM_BYTES);

    const int nelem4 = (N_VOX * CCH) / 4;
    const int act_grid = nelem4 / 256;
    const int comb_grid = N_VOX / 64;          // 2048

    // rulebook + operand prep
    k_zero<<<N_VOX / 256, 256>>>();
    k_fill<<<(NK * N_VOX) / 256, 256>>>(nbr);
    k_worklist<<<1, 256>>>();
    {
        dim3 wg(WSZ / 256, 3);
        k_wsplit<<<wg, 256>>>(w1, w2, w3);
    }
    k_xsplit<<<act_grid, 256>>>(feat, p_x0);

    // ---- layer 1 ----
    conv_mma<<<CONV_GRID, 256, SMEM_BYTES>>>(p_x0, p_wh, p_stage);
    k_combine<<<comb_grid, 256>>>(p_y);
    k_act_inner<<<act_grid, 256>>>(p_y, g1, b1, p_x1);   // act1 = residual

    // ---- layer 2 ----
    conv_mma<<<CONV_GRID, 256, SMEM_BYTES>>>(p_x1, p_wh + WSZ, p_stage);
    k_combine<<<comb_grid, 256>>>(p_y);
    k_act_inner<<<act_grid, 256>>>(p_y, g2, b2, p_x0);   // ping-pong

    // ---- layer 3 ----
    conv_mma<<<CONV_GRID, 256, SMEM_BYTES>>>(p_x0, p_wh + 2 * WSZ, p_stage);
    k_combine<<<comb_grid, 256>>>(p_y);
    k_act_out<<<act_grid, 256>>>(p_y, g3, b3, p_x1, out);
}